// round 9
// baseline (speedup 1.0000x reference)
#include <cuda_runtime.h>
#include <cuda_bf16.h>
#include <math.h>
#include <stdint.h>

#define NN 100000
#define EE 400000
#define BB 512

// ---------------- scratch (no allocations allowed) ----------------
__device__ float g_dinv[NN];
__device__ int   g_cnt[NN];
__device__ int   g_rowptr[NN + 1];
__device__ int   g_cursor[NN];
__device__ int   g_esrc[EE];
__device__ int   g_bsums[128];
__device__ __nv_bfloat16 g_aggHi[(size_t)NN * 256];  // aggregated A, high bf16
__device__ __nv_bfloat16 g_aggLo[(size_t)NN * 256];  // aggregated A, low  bf16
__device__ float g_bufB[(size_t)NN * 256];           // post-GEMM features (fp32)
__device__ float g_x2[BB * 256];                     // pooled max
__device__ float g_hidden[BB * 1024];                // fc1 output
// per-layer W^T split buffers (hi/lo planes), exact sizes, offsets below
#define WT_TOTAL (8192 + 24576 + 49152 + 65536 + 65536)
__device__ __nv_bfloat16 g_wt_hi[WT_TOTAL];
__device__ __nv_bfloat16 g_wt_lo[WT_TOTAL];
#define WOFF_L1 0
#define WOFF_L2 8192
#define WOFF_L3 32768
#define WOFF_MU 81920
#define WOFF_LV 147456

// ---------------- CSR construction ----------------
__global__ void zero_int_kernel(int* p, int n) {
    int i = blockIdx.x * blockDim.x + threadIdx.x;
    if (i < n) p[i] = 0;
}

__global__ void count_kernel(const int* __restrict__ col, int* cnt, int e) {
    int i = blockIdx.x * blockDim.x + threadIdx.x;
    if (i < e) atomicAdd(&cnt[col[i]], 1);
}

__global__ void dinv_kernel(const int* __restrict__ cnt, float* dinv, int n) {
    int i = blockIdx.x * blockDim.x + threadIdx.x;
    if (i < n) dinv[i] = rsqrtf(1.0f + (float)cnt[i]);   // +1 self-loop
}

__global__ void block_reduce_kernel(const int* __restrict__ cnt, int* bsums, int n) {
    __shared__ int wsum[32];
    int idx = blockIdx.x * 1024 + threadIdx.x;
    int lane = threadIdx.x & 31, wid = threadIdx.x >> 5;
    int v = (idx < n) ? cnt[idx] : 0;
    #pragma unroll
    for (int s = 16; s; s >>= 1) v += __shfl_down_sync(0xffffffffu, v, s);
    if (lane == 0) wsum[wid] = v;
    __syncthreads();
    if (wid == 0) {
        int t = wsum[lane];
        #pragma unroll
        for (int s = 16; s; s >>= 1) t += __shfl_down_sync(0xffffffffu, t, s);
        if (lane == 0) bsums[blockIdx.x] = t;
    }
}

__global__ void scan_bsums_kernel(int* bsums, int nb) {
    __shared__ int ws[4];
    int tid = threadIdx.x;
    int lane = tid & 31, wid = tid >> 5;
    int v = (tid < nb) ? bsums[tid] : 0;
    int incl = v;
    #pragma unroll
    for (int s = 1; s < 32; s <<= 1) {
        int t = __shfl_up_sync(0xffffffffu, incl, s);
        if (lane >= s) incl += t;
    }
    if (lane == 31) ws[wid] = incl;
    __syncthreads();
    if (tid == 0) {
        int a = 0;
        #pragma unroll
        for (int i = 0; i < 4; i++) { int t = ws[i]; ws[i] = a; a += t; }
    }
    __syncthreads();
    if (tid < nb) bsums[tid] = incl - v + ws[wid];
}

__global__ void scan_final_kernel(const int* __restrict__ cnt, const int* __restrict__ boff,
                                  int* rowptr, int* cursor, int n) {
    __shared__ int wsum[32];
    int idx = blockIdx.x * 1024 + threadIdx.x;
    int lane = threadIdx.x & 31, wid = threadIdx.x >> 5;
    int v = (idx < n) ? cnt[idx] : 0;
    int incl = v;
    #pragma unroll
    for (int s = 1; s < 32; s <<= 1) {
        int t = __shfl_up_sync(0xffffffffu, incl, s);
        if (lane >= s) incl += t;
    }
    if (lane == 31) wsum[wid] = incl;
    __syncthreads();
    if (wid == 0) {
        int w = wsum[lane];
        int wi = w;
        #pragma unroll
        for (int s = 1; s < 32; s <<= 1) {
            int t = __shfl_up_sync(0xffffffffu, wi, s);
            if (lane >= s) wi += t;
        }
        wsum[lane] = wi - w;
    }
    __syncthreads();
    int excl = incl - v + wsum[wid] + __ldg(&boff[blockIdx.x]);
    if (idx < n) {
        rowptr[idx] = excl;
        cursor[idx] = excl;
        if (idx == n - 1) rowptr[n] = excl + v;
    }
}

__global__ void fill_kernel(const int* __restrict__ erow, const int* __restrict__ ecol,
                            int* cursor, int* esrc, int e) {
    int i = blockIdx.x * blockDim.x + threadIdx.x;
    if (i < e) {
        int pos = atomicAdd(&cursor[ecol[i]], 1);
        esrc[pos] = erow[i];
    }
}

// ---------------- gather aggregation: warp-per-node, bf16 hi/lo output --------
template <int COLS>   // COLS = F/32 floats per lane
__global__ void gather_row_kernel(const float* __restrict__ h,
                                  const float* __restrict__ dinv,
                                  const int* __restrict__ rowptr,
                                  const int* __restrict__ esrc,
                                  __nv_bfloat16* __restrict__ aggHi,
                                  __nv_bfloat16* __restrict__ aggLo,
                                  int n, int F) {
    int node = (blockIdx.x * blockDim.x + threadIdx.x) >> 5;
    int lane = threadIdx.x & 31;
    if (node >= n) return;
    const int c0 = lane * COLS;
    float dn = __ldg(&dinv[node]);
    float sum[COLS];
    {
        const float* r = h + (size_t)node * F + c0;
        #pragma unroll
        for (int j = 0; j < COLS; j++) sum[j] = dn * __ldg(&r[j]);
    }
    int s = __ldg(&rowptr[node]);
    int e = __ldg(&rowptr[node + 1]);
    int i = s;
    for (; i + 3 < e; i += 4) {
        int s0 = __ldg(&esrc[i]);
        int s1 = __ldg(&esrc[i + 1]);
        int s2 = __ldg(&esrc[i + 2]);
        int s3 = __ldg(&esrc[i + 3]);
        float d0 = __ldg(&dinv[s0]);
        float d1 = __ldg(&dinv[s1]);
        float d2 = __ldg(&dinv[s2]);
        float d3 = __ldg(&dinv[s3]);
        const float* r0 = h + (size_t)s0 * F + c0;
        const float* r1 = h + (size_t)s1 * F + c0;
        const float* r2 = h + (size_t)s2 * F + c0;
        const float* r3 = h + (size_t)s3 * F + c0;
        #pragma unroll
        for (int j = 0; j < COLS; j++) sum[j] += d0 * __ldg(&r0[j]);
        #pragma unroll
        for (int j = 0; j < COLS; j++) sum[j] += d1 * __ldg(&r1[j]);
        #pragma unroll
        for (int j = 0; j < COLS; j++) sum[j] += d2 * __ldg(&r2[j]);
        #pragma unroll
        for (int j = 0; j < COLS; j++) sum[j] += d3 * __ldg(&r3[j]);
    }
    for (; i < e; i++) {
        int s0 = __ldg(&esrc[i]);
        float d0 = __ldg(&dinv[s0]);
        const float* r0 = h + (size_t)s0 * F + c0;
        #pragma unroll
        for (int j = 0; j < COLS; j++) sum[j] += d0 * __ldg(&r0[j]);
    }
    __nv_bfloat16* oh = aggHi + (size_t)node * F + c0;
    __nv_bfloat16* ol = aggLo + (size_t)node * F + c0;
    #pragma unroll
    for (int j = 0; j < COLS; j++) {
        float v = dn * sum[j];
        __nv_bfloat16 hb = __float2bfloat16_rn(v);
        oh[j] = hb;
        ol[j] = __float2bfloat16_rn(v - __bfloat162float(hb));
    }
}

__global__ void zero_kernel(float* p, int n) {
    int i = blockIdx.x * blockDim.x + threadIdx.x;
    if (i < n) p[i] = 0.0f;
}

// ---------------- weight pre-split: W[MK,N] -> Wt_{hi,lo}[N,MK] bf16 ----------
__global__ void wsplit_kernel(const float* __restrict__ W,
                              __nv_bfloat16* __restrict__ whi,
                              __nv_bfloat16* __restrict__ wlo,
                              int MK, int N) {
    int idx = blockIdx.x * blockDim.x + threadIdx.x;
    if (idx >= N * MK) return;
    int n = idx / MK;
    int k = idx % MK;
    float v = W[(size_t)k * N + n];
    __nv_bfloat16 h = __float2bfloat16_rn(v);
    __nv_bfloat16 l = __float2bfloat16_rn(v - __bfloat162float(h));
    whi[(size_t)n * MK + k] = h;
    wlo[(size_t)n * MK + k] = l;
}

// ---------------- bf16x3 tensor-core GEMM with cp.async -----------------------
// N-tile NT == Kout exactly (128 / 192 / 256): one CTA per 128-row block,
// gx = 1 -> A streamed exactly once, zero padding waste.
// Tiles stored with 80-byte row stride: (addr/16) mod 8 = (5r+c) mod 8 bijective
// over 8 consecutive rows -> conflict-free ldmatrix. 16B-aligned (80 = 5*16).
#define RS 80

#define LDSM_X4(R, ADDR) \
    asm volatile("ldmatrix.sync.aligned.m8n8.x4.shared.b16 {%0,%1,%2,%3}, [%4];" \
        : "=r"((R)[0]), "=r"((R)[1]), "=r"((R)[2]), "=r"((R)[3]) : "r"(ADDR))

#define MMA_BF16(CC, AA, B0, B1) \
    asm volatile("mma.sync.aligned.m16n8k16.row.col.f32.bf16.bf16.f32 " \
        "{%0,%1,%2,%3}, {%4,%5,%6,%7}, {%8,%9}, {%0,%1,%2,%3};" \
        : "+f"((CC)[0]), "+f"((CC)[1]), "+f"((CC)[2]), "+f"((CC)[3]) \
        : "r"((AA)[0]), "r"((AA)[1]), "r"((AA)[2]), "r"((AA)[3]), \
          "r"(B0), "r"(B1))

#define CP16(DST, SRC, SZ) \
    asm volatile("cp.async.ca.shared.global [%0], [%1], 16, %2;" \
        :: "r"(DST), "l"(SRC), "r"(SZ) : "memory")

template <int NT>
__global__ void __launch_bounds__(256, 1)
gemm_mma_kernel(const __nv_bfloat16* __restrict__ aHi,
                const __nv_bfloat16* __restrict__ aLo,
                const __nv_bfloat16* __restrict__ wHi,
                const __nv_bfloat16* __restrict__ wLo,
                const float* __restrict__ bias,
                float* __restrict__ C, int Nr, int MK, int relu,
                const float* __restrict__ mu_in, const float* __restrict__ eps_in,
                float* __restrict__ amvo_out,
                const int* __restrict__ batch, float* __restrict__ pool) {
    extern __shared__ char smem[];
    const int tid = threadIdx.x;
    const int w = tid >> 5, lid = tid & 31;
    const int wr = w >> 2, wc = w & 3;            // warp grid 2x4 over 128xNT
    const int row0 = blockIdx.y * 128;
    const uint32_t sbase = (uint32_t)__cvta_generic_to_shared(smem);

    constexpr int ATILE = 128 * RS;               // per A plane
    constexpr int BTILE = NT * RS;                // per B plane
    constexpr int STAGE = 2 * ATILE + 2 * BTILE;
    constexpr int NPW = NT / 4;                   // cols per warp
    constexpr int P = NPW / 16;                   // 16-col n-tile pairs per warp

    float acc[4][2 * P][4];
    #pragma unroll
    for (int a = 0; a < 4; a++)
        #pragma unroll
        for (int b = 0; b < 2 * P; b++)
            #pragma unroll
            for (int c = 0; c < 4; c++) acc[a][b][c] = 0.f;

    const int nc = MK >> 5;               // chunks of 32

    const int lr = tid >> 1;              // 0..127
    const int lhalf = tid & 1;            // 0/1 (32B halves of the 64B row)

    auto issue_chunk = [&](int ci, int s) {
        const int k0 = ci << 5;
        const uint32_t st = sbase + s * STAGE;
        const uint32_t dstA = st + lr * RS + lhalf * 32;
        int gr = row0 + lr;
        int sz = (gr < Nr) ? 16 : 0;
        const __nv_bfloat16* sh = aHi + (size_t)(gr < Nr ? gr : 0) * MK + k0 + lhalf * 16;
        const __nv_bfloat16* sl = aLo + (size_t)(gr < Nr ? gr : 0) * MK + k0 + lhalf * 16;
        CP16(dstA,               sh,     sz);
        CP16(dstA + 16,          sh + 8, sz);
        CP16(dstA + ATILE,       sl,     sz);
        CP16(dstA + ATILE + 16,  sl + 8, sz);
        #pragma unroll
        for (int r = lr; r < NT; r += 128) {
            const __nv_bfloat16* bh = wHi + (size_t)r * MK + k0 + lhalf * 16;
            const __nv_bfloat16* bl = wLo + (size_t)r * MK + k0 + lhalf * 16;
            const uint32_t dstB = st + 2 * ATILE + r * RS + lhalf * 32;
            CP16(dstB,               bh,     16);
            CP16(dstB + 16,          bh + 8, 16);
            CP16(dstB + BTILE,       bl,     16);
            CP16(dstB + BTILE + 16,  bl + 8, 16);
        }
        asm volatile("cp.async.commit_group;" ::: "memory");
    };

    auto compute = [&](int s) {
        const uint32_t aHiB = sbase + s * STAGE;
        const uint32_t aLoB = aHiB + ATILE;
        const uint32_t bHiB = aHiB + 2 * ATILE;
        const uint32_t bLoB = bHiB + BTILE;
        const int sub = lid & 7;
        const int g1 = (lid >> 3) & 1;
        const int g2 = (lid >> 4) & 1;
        #pragma unroll
        for (int ks = 0; ks < 2; ks++) {
            uint32_t bh[P][4], bl[P][4];
            #pragma unroll
            for (int np = 0; np < P; np++) {
                uint32_t r = wc * NPW + np * 16 + g2 * 8 + sub;
                uint32_t off = r * RS + (ks * 2 + g1) * 16;
                LDSM_X4(bh[np], bHiB + off);
                LDSM_X4(bl[np], bLoB + off);
            }
            uint32_t af[4][4];
            #pragma unroll
            for (int mt = 0; mt < 4; mt++) {
                uint32_t r = wr * 64 + mt * 16 + g1 * 8 + sub;
                uint32_t off = r * RS + (ks * 2 + g2) * 16;
                LDSM_X4(af[mt], aHiB + off);
            }
            #pragma unroll
            for (int mt = 0; mt < 4; mt++)
                #pragma unroll
                for (int nt = 0; nt < 2 * P; nt++) {
                    const uint32_t* BH = &bh[nt >> 1][(nt & 1) * 2];
                    const uint32_t* BL = &bl[nt >> 1][(nt & 1) * 2];
                    MMA_BF16(acc[mt][nt], af[mt], BH[0], BH[1]);
                    MMA_BF16(acc[mt][nt], af[mt], BL[0], BL[1]);
                }
            #pragma unroll
            for (int mt = 0; mt < 4; mt++) {
                uint32_t r = wr * 64 + mt * 16 + g1 * 8 + sub;
                uint32_t off = r * RS + (ks * 2 + g2) * 16;
                LDSM_X4(af[mt], aLoB + off);
            }
            #pragma unroll
            for (int mt = 0; mt < 4; mt++)
                #pragma unroll
                for (int nt = 0; nt < 2 * P; nt++) {
                    const uint32_t* BH = &bh[nt >> 1][(nt & 1) * 2];
                    MMA_BF16(acc[mt][nt], af[mt], BH[0], BH[1]);
                }
        }
    };

    // ---- mainloop: 2-stage cp.async pipeline ----
    issue_chunk(0, 0);
    if (nc > 1) issue_chunk(1, 1);
    for (int ci = 0; ci < nc; ci++) {
        int s = ci & 1;
        if (ci < nc - 1) {
            asm volatile("cp.async.wait_group 1;" ::: "memory");
        } else {
            asm volatile("cp.async.wait_group 0;" ::: "memory");
        }
        __syncthreads();
        compute(s);
        __syncthreads();
        if (ci + 2 < nc) issue_chunk(ci + 2, s);
    }

    // ---- epilogue ----
    const int g = lid >> 2, tg = lid & 3;
    auto emit = [&](int row, int col, float v0, float v1) {
        if (row >= Nr) return;
        v0 += __ldg(&bias[col]);
        v1 += __ldg(&bias[col + 1]);
        if (relu) { v0 = fmaxf(v0, 0.f); v1 = fmaxf(v1, 0.f); }
        float2 v = make_float2(v0, v1);
        *(float2*)&C[(size_t)row * NT + col] = v;
        if (pool != nullptr) {
            int bp = __ldg(&batch[row]);
            atomicMax((int*)&pool[(size_t)bp * NT + col],     __float_as_int(v0));
            atomicMax((int*)&pool[(size_t)bp * NT + col + 1], __float_as_int(v1));
        }
        if (amvo_out != nullptr) {
            float2 m = *(const float2*)&mu_in[(size_t)row * NT + col];
            float2 e = *(const float2*)&eps_in[(size_t)row * NT + col];
            float2 a;
            a.x = fmaf(e.x, __expf(0.5f * v0), m.x);
            a.y = fmaf(e.y, __expf(0.5f * v1), m.y);
            *(float2*)&amvo_out[(size_t)row * NT + col] = a;
        }
    };
    #pragma unroll
    for (int mt = 0; mt < 4; mt++) {
        int rowb = row0 + wr * 64 + mt * 16 + g;
        #pragma unroll
        for (int nt = 0; nt < 2 * P; nt++) {
            int col = wc * NPW + nt * 8 + 2 * tg;
            emit(rowb,     col, acc[mt][nt][0], acc[mt][nt][1]);
            emit(rowb + 8, col, acc[mt][nt][2], acc[mt][nt][3]);
        }
    }
}

// ---------------- fp32 SGEMM for the tiny FC head ----------------
__global__ __launch_bounds__(256) void sgemm_bias_kernel(
    const float* __restrict__ A, const float* __restrict__ W,
    const float* __restrict__ bias, float* __restrict__ C,
    int Nr, int M, int K, int relu) {
    const int BM = 128, BN = 64, BK = 16, TM = 8, TN = 4;
    __shared__ float As[BK][BM + 4];
    __shared__ float Bs[BK][BN];
    int row0 = blockIdx.y * BM;
    int col0 = blockIdx.x * BN;
    int tid = threadIdx.x;
    int tr = (tid / 16) * TM;
    int tc = (tid % 16) * TN;
    float acc[TM][TN] = {};

    for (int k0 = 0; k0 < M; k0 += BK) {
        #pragma unroll
        for (int l = tid; l < (BM * BK) / 4; l += 256) {
            int r = l >> 2;
            int m4 = (l & 3) << 2;
            float4 v = make_float4(0.f, 0.f, 0.f, 0.f);
            int gr = row0 + r;
            if (gr < Nr) v = *(const float4*)&A[(size_t)gr * M + k0 + m4];
            As[m4 + 0][r] = v.x;
            As[m4 + 1][r] = v.y;
            As[m4 + 2][r] = v.z;
            As[m4 + 3][r] = v.w;
        }
        {
            int m = tid >> 4;
            int c4 = (tid & 15) << 2;
            float4 v = *(const float4*)&W[(size_t)(k0 + m) * K + col0 + c4];
            *(float4*)&Bs[m][c4] = v;
        }
        __syncthreads();
        #pragma unroll
        for (int kk = 0; kk < BK; kk++) {
            float a[TM], b[TN];
            #pragma unroll
            for (int i = 0; i < TM; i++) a[i] = As[kk][tr + i];
            #pragma unroll
            for (int j = 0; j < TN; j++) b[j] = Bs[kk][tc + j];
            #pragma unroll
            for (int i = 0; i < TM; i++)
                #pragma unroll
                for (int j = 0; j < TN; j++)
                    acc[i][j] = fmaf(a[i], b[j], acc[i][j]);
        }
        __syncthreads();
    }

    #pragma unroll
    for (int i = 0; i < TM; i++) {
        int gr = row0 + tr + i;
        if (gr >= Nr) continue;
        #pragma unroll
        for (int j = 0; j < TN; j++) {
            int gc = col0 + tc + j;
            float v = acc[i][j] + bias[gc];
            if (relu) v = fmaxf(v, 0.0f);
            C[(size_t)gr * K + gc] = v;
        }
    }
}

// ---------------- launch orchestration ----------------
static inline void run_aggregate(const float* h, const float* dinv,
                                 const int* rowptr, const int* esrc,
                                 __nv_bfloat16* aggHi, __nv_bfloat16* aggLo, int F) {
    int blocks = (NN * 32 + 255) / 256;
    switch (F) {
        case 64:  gather_row_kernel<2><<<blocks, 256>>>(h, dinv, rowptr, esrc, aggHi, aggLo, NN, F); break;
        case 128: gather_row_kernel<4><<<blocks, 256>>>(h, dinv, rowptr, esrc, aggHi, aggLo, NN, F); break;
        case 192: gather_row_kernel<6><<<blocks, 256>>>(h, dinv, rowptr, esrc, aggHi, aggLo, NN, F); break;
        default:  gather_row_kernel<8><<<blocks, 256>>>(h, dinv, rowptr, esrc, aggHi, aggLo, NN, F); break;
    }
}

template <int NT>
static inline void launch_gemm(const __nv_bfloat16* aHi, const __nv_bfloat16* aLo,
                               const __nv_bfloat16* wHi, const __nv_bfloat16* wLo,
                               const float* bias, float* C, int Nr, int MK, int relu,
                               const float* mu_in, const float* eps_in, float* amvo_out,
                               const int* batch, float* pool) {
    constexpr int SMEM = 2 * (2 * 128 * RS + 2 * NT * RS);
    cudaFuncSetAttribute(gemm_mma_kernel<NT>,
                         cudaFuncAttributeMaxDynamicSharedMemorySize, SMEM);
    dim3 grid(1, (Nr + 127) / 128);
    gemm_mma_kernel<NT><<<grid, 256, SMEM>>>(aHi, aLo, wHi, wLo, bias, C, Nr, MK,
                                             relu, mu_in, eps_in, amvo_out, batch, pool);
}

static inline void run_gemm_mma(const __nv_bfloat16* aHi, const __nv_bfloat16* aLo,
                                const __nv_bfloat16* wHi, const __nv_bfloat16* wLo,
                                const float* bias,
                                float* C, int Nr, int MK, int Kout, int relu,
                                const float* mu_in = nullptr,
                                const float* eps_in = nullptr,
                                float* amvo_out = nullptr,
                                const int* batch = nullptr,
                                float* pool = nullptr) {
    if (Kout == 128)
        launch_gemm<128>(aHi, aLo, wHi, wLo, bias, C, Nr, MK, relu, mu_in, eps_in, amvo_out, batch, pool);
    else if (Kout == 192)
        launch_gemm<192>(aHi, aLo, wHi, wLo, bias, C, Nr, MK, relu, mu_in, eps_in, amvo_out, batch, pool);
    else
        launch_gemm<256>(aHi, aLo, wHi, wLo, bias, C, Nr, MK, relu, mu_in, eps_in, amvo_out, batch, pool);
}

extern "C" void kernel_launch(void* const* d_in, const int* in_sizes, int n_in,
                              void* d_out, int out_size) {
    const float* x     = (const float*)d_in[0];
    const int*   ei    = (const int*)d_in[1];
    const int*   batch = (const int*)d_in[2];
    const float* eps   = (const float*)d_in[3];
    const float* W1 = (const float*)d_in[4];  const float* b1 = (const float*)d_in[5];
    const float* W2 = (const float*)d_in[6];  const float* b2 = (const float*)d_in[7];
    const float* W3 = (const float*)d_in[8];  const float* b3 = (const float*)d_in[9];
    const float* Wmu = (const float*)d_in[10]; const float* bmu = (const float*)d_in[11];
    const float* Wlv = (const float*)d_in[12]; const float* blv = (const float*)d_in[13];
    const float* fc1w = (const float*)d_in[14]; const float* fc1b = (const float*)d_in[15];
    const float* fc2w = (const float*)d_in[16]; const float* fc2b = (const float*)d_in[17];

    float* out = (float*)d_out;
    float* out_amvo = out;
    float* out_mu   = out + (size_t)NN * 256;
    float* out_lv   = out + 2 * (size_t)NN * 256;
    float* out_pmvo = out + 3 * (size_t)NN * 256;

    float *dinv, *bufB, *x2, *hidden;
    int *cnt, *rowptr, *cursor, *esrc, *bsums;
    __nv_bfloat16 *aggHi, *aggLo, *wtHi, *wtLo;
    cudaGetSymbolAddress((void**)&dinv, g_dinv);
    cudaGetSymbolAddress((void**)&cnt, g_cnt);
    cudaGetSymbolAddress((void**)&rowptr, g_rowptr);
    cudaGetSymbolAddress((void**)&cursor, g_cursor);
    cudaGetSymbolAddress((void**)&esrc, g_esrc);
    cudaGetSymbolAddress((void**)&bsums, g_bsums);
    cudaGetSymbolAddress((void**)&aggHi, g_aggHi);
    cudaGetSymbolAddress((void**)&aggLo, g_aggLo);
    cudaGetSymbolAddress((void**)&bufB, g_bufB);
    cudaGetSymbolAddress((void**)&x2, g_x2);
    cudaGetSymbolAddress((void**)&hidden, g_hidden);
    cudaGetSymbolAddress((void**)&wtHi, g_wt_hi);
    cudaGetSymbolAddress((void**)&wtLo, g_wt_lo);

    const int* erow = ei;
    const int* ecol = ei + EE;

    const int SCAN_BLOCKS = (NN + 1023) / 1024;   // 98

    // all weight pre-splits up front (dedicated, exact-size buffers)
    wsplit_kernel<<<(128 * 64  + 255) / 256, 256>>>(W1,  wtHi + WOFF_L1, wtLo + WOFF_L1, 64,  128);
    wsplit_kernel<<<(192 * 128 + 255) / 256, 256>>>(W2,  wtHi + WOFF_L2, wtLo + WOFF_L2, 128, 192);
    wsplit_kernel<<<(256 * 192 + 255) / 256, 256>>>(W3,  wtHi + WOFF_L3, wtLo + WOFF_L3, 192, 256);
    wsplit_kernel<<<(256 * 256 + 255) / 256, 256>>>(Wmu, wtHi + WOFF_MU, wtLo + WOFF_MU, 256, 256);
    wsplit_kernel<<<(256 * 256 + 255) / 256, 256>>>(Wlv, wtHi + WOFF_LV, wtLo + WOFF_LV, 256, 256);

    // CSR build + normalization + pool init
    zero_int_kernel<<<(NN + 255) / 256, 256>>>(cnt, NN);
    count_kernel<<<(EE + 255) / 256, 256>>>(ecol, cnt, EE);
    dinv_kernel<<<(NN + 255) / 256, 256>>>(cnt, dinv, NN);
    block_reduce_kernel<<<SCAN_BLOCKS, 1024>>>(cnt, bsums, NN);
    scan_bsums_kernel<<<1, 128>>>(bsums, SCAN_BLOCKS);
    scan_final_kernel<<<SCAN_BLOCKS, 1024>>>(cnt, bsums, rowptr, cursor, NN);
    fill_kernel<<<(EE + 255) / 256, 256>>>(erow, ecol, cursor, esrc, EE);
    zero_kernel<<<(BB * 256 + 255) / 256, 256>>>(x2, BB * 256);

    // layer 1: aggregate(x,64) -> gemm 64->128 +relu
    run_aggregate(x, dinv, rowptr, esrc, aggHi, aggLo, 64);
    run_gemm_mma(aggHi, aggLo, wtHi + WOFF_L1, wtLo + WOFF_L1, b1, bufB, NN, 64, 128, 1);

    // layer 2: aggregate(h1,128) -> gemm 128->192 +relu
    run_aggregate(bufB, dinv, rowptr, esrc, aggHi, aggLo, 128);
    run_gemm_mma(aggHi, aggLo, wtHi + WOFF_L2, wtLo + WOFF_L2, b2, bufB, NN, 128, 192, 1);

    // layer 3: aggregate(h2,192) -> gemm 192->256 +relu, fused segment-max pool
    run_aggregate(bufB, dinv, rowptr, esrc, aggHi, aggLo, 192);
    run_gemm_mma(aggHi, aggLo, wtHi + WOFF_L3, wtLo + WOFF_L3, b3, bufB, NN, 192, 256, 1,
                 nullptr, nullptr, nullptr, batch, x2);

    // shared aggregation for mu / logvar heads
    run_aggregate(bufB, dinv, rowptr, esrc, aggHi, aggLo, 256);
    run_gemm_mma(aggHi, aggLo, wtHi + WOFF_MU, wtLo + WOFF_MU, bmu, out_mu, NN, 256, 256, 0);
    run_gemm_mma(aggHi, aggLo, wtHi + WOFF_LV, wtLo + WOFF_LV, blv, out_lv, NN, 256, 256, 0,
                 out_mu, eps, out_amvo);

    // MLP head on pooled features (tiny, fp32)
    {
        dim3 g1(1024 / 64, (BB + 127) / 128);
        sgemm_bias_kernel<<<g1, 256>>>(x2, fc1w, fc1b, hidden, BB, 256, 1024, 1);
        dim3 g2(128 / 64, (BB + 127) / 128);
        sgemm_bias_kernel<<<g2, 256>>>(hidden, fc2w, fc2b, out_pmvo, BB, 1024, 128, 0);
    }
}

// round 10
// speedup vs baseline: 1.0075x; 1.0075x over previous
#include <cuda_runtime.h>
#include <cuda_bf16.h>
#include <math.h>
#include <stdint.h>

#define NN 100000
#define EE 400000
#define BB 512

// ---------------- scratch (no allocations allowed) ----------------
__device__ float g_dinv[NN];
__device__ int   g_cnt[NN];
__device__ int   g_rowptr[NN + 1];
__device__ int   g_cursor[NN];
__device__ int   g_esrc[EE];
__device__ int   g_bsums[128];
__device__ __nv_bfloat16 g_aggHi[(size_t)NN * 256];  // aggregated A, high bf16
__device__ __nv_bfloat16 g_aggLo[(size_t)NN * 256];  // aggregated A, low  bf16
__device__ float g_bufB[(size_t)NN * 256];           // post-GEMM features (fp32)
__device__ float g_x2[BB * 256];                     // pooled max
__device__ float g_hidden[BB * 1024];                // fc1 output
// per-layer W^T split buffers (hi/lo planes), padded to 128-col multiples
#define WT_TOTAL (8192 + 32768 + 49152 + 65536 + 65536)
__device__ __nv_bfloat16 g_wt_hi[WT_TOTAL];
__device__ __nv_bfloat16 g_wt_lo[WT_TOTAL];
#define WOFF_L1 0
#define WOFF_L2 8192
#define WOFF_L3 40960
#define WOFF_MU 90112
#define WOFF_LV 155648

// ---------------- CSR construction ----------------
__global__ void zero_int_kernel(int* p, int n) {
    int i = blockIdx.x * blockDim.x + threadIdx.x;
    if (i < n) p[i] = 0;
}

__global__ void count_kernel(const int* __restrict__ col, int* cnt, int e) {
    int i = blockIdx.x * blockDim.x + threadIdx.x;
    if (i < e) atomicAdd(&cnt[col[i]], 1);
}

__global__ void dinv_kernel(const int* __restrict__ cnt, float* dinv, int n) {
    int i = blockIdx.x * blockDim.x + threadIdx.x;
    if (i < n) dinv[i] = rsqrtf(1.0f + (float)cnt[i]);   // +1 self-loop
}

__global__ void block_reduce_kernel(const int* __restrict__ cnt, int* bsums, int n) {
    __shared__ int wsum[32];
    int idx = blockIdx.x * 1024 + threadIdx.x;
    int lane = threadIdx.x & 31, wid = threadIdx.x >> 5;
    int v = (idx < n) ? cnt[idx] : 0;
    #pragma unroll
    for (int s = 16; s; s >>= 1) v += __shfl_down_sync(0xffffffffu, v, s);
    if (lane == 0) wsum[wid] = v;
    __syncthreads();
    if (wid == 0) {
        int t = wsum[lane];
        #pragma unroll
        for (int s = 16; s; s >>= 1) t += __shfl_down_sync(0xffffffffu, t, s);
        if (lane == 0) bsums[blockIdx.x] = t;
    }
}

__global__ void scan_bsums_kernel(int* bsums, int nb) {
    __shared__ int ws[4];
    int tid = threadIdx.x;
    int lane = tid & 31, wid = tid >> 5;
    int v = (tid < nb) ? bsums[tid] : 0;
    int incl = v;
    #pragma unroll
    for (int s = 1; s < 32; s <<= 1) {
        int t = __shfl_up_sync(0xffffffffu, incl, s);
        if (lane >= s) incl += t;
    }
    if (lane == 31) ws[wid] = incl;
    __syncthreads();
    if (tid == 0) {
        int a = 0;
        #pragma unroll
        for (int i = 0; i < 4; i++) { int t = ws[i]; ws[i] = a; a += t; }
    }
    __syncthreads();
    if (tid < nb) bsums[tid] = incl - v + ws[wid];
}

__global__ void scan_final_kernel(const int* __restrict__ cnt, const int* __restrict__ boff,
                                  int* rowptr, int* cursor, int n) {
    __shared__ int wsum[32];
    int idx = blockIdx.x * 1024 + threadIdx.x;
    int lane = threadIdx.x & 31, wid = threadIdx.x >> 5;
    int v = (idx < n) ? cnt[idx] : 0;
    int incl = v;
    #pragma unroll
    for (int s = 1; s < 32; s <<= 1) {
        int t = __shfl_up_sync(0xffffffffu, incl, s);
        if (lane >= s) incl += t;
    }
    if (lane == 31) wsum[wid] = incl;
    __syncthreads();
    if (wid == 0) {
        int w = wsum[lane];
        int wi = w;
        #pragma unroll
        for (int s = 1; s < 32; s <<= 1) {
            int t = __shfl_up_sync(0xffffffffu, wi, s);
            if (lane >= s) wi += t;
        }
        wsum[lane] = wi - w;
    }
    __syncthreads();
    int excl = incl - v + wsum[wid] + __ldg(&boff[blockIdx.x]);
    if (idx < n) {
        rowptr[idx] = excl;
        cursor[idx] = excl;
        if (idx == n - 1) rowptr[n] = excl + v;
    }
}

__global__ void fill_kernel(const int* __restrict__ erow, const int* __restrict__ ecol,
                            int* cursor, int* esrc, int e) {
    int i = blockIdx.x * blockDim.x + threadIdx.x;
    if (i < e) {
        int pos = atomicAdd(&cursor[ecol[i]], 1);
        esrc[pos] = erow[i];
    }
}

// ---------------- gather aggregation: warp-per-node, vectorized loads --------
template <int COLS>
__device__ __forceinline__ void load_cols(const float* __restrict__ p, float* v) {
    if constexpr ((COLS & 3) == 0) {
        #pragma unroll
        for (int j = 0; j < COLS / 4; j++) {
            float4 t = __ldg((const float4*)p + j);
            v[4 * j + 0] = t.x; v[4 * j + 1] = t.y;
            v[4 * j + 2] = t.z; v[4 * j + 3] = t.w;
        }
    } else {
        #pragma unroll
        for (int j = 0; j < COLS / 2; j++) {
            float2 t = __ldg((const float2*)p + j);
            v[2 * j + 0] = t.x; v[2 * j + 1] = t.y;
        }
    }
}

template <int COLS>   // COLS = F/32 floats per lane
__global__ void gather_row_kernel(const float* __restrict__ h,
                                  const float* __restrict__ dinv,
                                  const int* __restrict__ rowptr,
                                  const int* __restrict__ esrc,
                                  __nv_bfloat16* __restrict__ aggHi,
                                  __nv_bfloat16* __restrict__ aggLo,
                                  int n, int F) {
    int node = (blockIdx.x * blockDim.x + threadIdx.x) >> 5;
    int lane = threadIdx.x & 31;
    if (node >= n) return;
    const int c0 = lane * COLS;
    float dn = __ldg(&dinv[node]);
    float sum[COLS];
    {
        float v[COLS];
        load_cols<COLS>(h + (size_t)node * F + c0, v);
        #pragma unroll
        for (int j = 0; j < COLS; j++) sum[j] = dn * v[j];
    }
    int s = __ldg(&rowptr[node]);
    int e = __ldg(&rowptr[node + 1]);
    int i = s;
    for (; i + 3 < e; i += 4) {
        int s0 = __ldg(&esrc[i]);
        int s1 = __ldg(&esrc[i + 1]);
        int s2 = __ldg(&esrc[i + 2]);
        int s3 = __ldg(&esrc[i + 3]);
        float d0 = __ldg(&dinv[s0]);
        float d1 = __ldg(&dinv[s1]);
        float d2 = __ldg(&dinv[s2]);
        float d3 = __ldg(&dinv[s3]);
        float v0[COLS], v1[COLS], v2[COLS], v3[COLS];
        load_cols<COLS>(h + (size_t)s0 * F + c0, v0);
        load_cols<COLS>(h + (size_t)s1 * F + c0, v1);
        load_cols<COLS>(h + (size_t)s2 * F + c0, v2);
        load_cols<COLS>(h + (size_t)s3 * F + c0, v3);
        #pragma unroll
        for (int j = 0; j < COLS; j++)
            sum[j] += d0 * v0[j] + d1 * v1[j] + d2 * v2[j] + d3 * v3[j];
    }
    for (; i < e; i++) {
        int s0 = __ldg(&esrc[i]);
        float d0 = __ldg(&dinv[s0]);
        float v0[COLS];
        load_cols<COLS>(h + (size_t)s0 * F + c0, v0);
        #pragma unroll
        for (int j = 0; j < COLS; j++) sum[j] += d0 * v0[j];
    }
    __nv_bfloat16* oh = aggHi + (size_t)node * F + c0;
    __nv_bfloat16* ol = aggLo + (size_t)node * F + c0;
    #pragma unroll
    for (int j = 0; j < COLS; j++) {
        float v = dn * sum[j];
        __nv_bfloat16 hb = __float2bfloat16_rn(v);
        oh[j] = hb;
        ol[j] = __float2bfloat16_rn(v - __bfloat162float(hb));
    }
}

__global__ void zero_kernel(float* p, int n) {
    int i = blockIdx.x * blockDim.x + threadIdx.x;
    if (i < n) p[i] = 0.0f;
}

// ---------------- weight pre-split: W[MK,N] -> Wt_{hi,lo}[Npad,MK] bf16 -------
__global__ void wsplit_kernel(const float* __restrict__ W,
                              __nv_bfloat16* __restrict__ whi,
                              __nv_bfloat16* __restrict__ wlo,
                              int MK, int N, int Npad) {
    int idx = blockIdx.x * blockDim.x + threadIdx.x;
    if (idx >= Npad * MK) return;
    int n = idx / MK;
    int k = idx % MK;
    float v = (n < N) ? W[(size_t)k * N + n] : 0.0f;
    __nv_bfloat16 h = __float2bfloat16_rn(v);
    __nv_bfloat16 l = __float2bfloat16_rn(v - __bfloat162float(h));
    whi[(size_t)n * MK + k] = h;
    wlo[(size_t)n * MK + k] = l;
}

// ---------------- bf16x3 tensor-core GEMM with 3-stage cp.async ---------------
// R7-proven shape: 128x128 CTA tile, 2x4 warp grid, 64-reg accumulators.
// Tiles stored with 80-byte row stride: (addr/16) mod 8 = (5r+c) mod 8 bijective
// over 8 consecutive rows -> conflict-free ldmatrix. 16B-aligned (80 = 5*16).
#define RS 80

#define LDSM_X4(R, ADDR) \
    asm volatile("ldmatrix.sync.aligned.m8n8.x4.shared.b16 {%0,%1,%2,%3}, [%4];" \
        : "=r"((R)[0]), "=r"((R)[1]), "=r"((R)[2]), "=r"((R)[3]) : "r"(ADDR))

#define MMA_BF16(CC, AA, B0, B1) \
    asm volatile("mma.sync.aligned.m16n8k16.row.col.f32.bf16.bf16.f32 " \
        "{%0,%1,%2,%3}, {%4,%5,%6,%7}, {%8,%9}, {%0,%1,%2,%3};" \
        : "+f"((CC)[0]), "+f"((CC)[1]), "+f"((CC)[2]), "+f"((CC)[3]) \
        : "r"((AA)[0]), "r"((AA)[1]), "r"((AA)[2]), "r"((AA)[3]), \
          "r"(B0), "r"(B1))

#define CP16(DST, SRC, SZ) \
    asm volatile("cp.async.ca.shared.global [%0], [%1], 16, %2;" \
        :: "r"(DST), "l"(SRC), "r"(SZ) : "memory")

__global__ void __launch_bounds__(256)
gemm_mma_kernel(const __nv_bfloat16* __restrict__ aHi,
                const __nv_bfloat16* __restrict__ aLo,
                const __nv_bfloat16* __restrict__ wHi,
                const __nv_bfloat16* __restrict__ wLo,
                const float* __restrict__ bias,
                float* __restrict__ C, int Nr, int MK, int Kout, int relu,
                const float* __restrict__ mu_in, const float* __restrict__ eps_in,
                float* __restrict__ amvo_out,
                const int* __restrict__ batch, float* __restrict__ pool) {
    extern __shared__ char smem[];
    const int tid = threadIdx.x;
    const int w = tid >> 5, lid = tid & 31;
    const int wr = w >> 2, wc = w & 3;          // warp grid 2x4 over 128x128
    const int row0 = blockIdx.y * 128, col0 = blockIdx.x * 128;
    const uint32_t sbase = (uint32_t)__cvta_generic_to_shared(smem);

    const int TILE = 128 * RS;                   // 10240 B per plane
    const int STAGE = 4 * TILE;                  // AsHi | AsLo | BsHi | BsLo

    float acc[4][4][4] = {};

    const int nc = MK >> 5;               // chunks of 32

    const int lr = tid >> 1;              // 0..127
    const int lhalf = tid & 1;            // 0/1 (32B halves of the 64B row)

    auto issue_chunk = [&](int ci, int s) {
        const int k0 = ci << 5;
        const uint32_t st = sbase + s * STAGE;
        const uint32_t dstA = st + lr * RS + lhalf * 32;
        int gr = row0 + lr;
        int sz = (gr < Nr) ? 16 : 0;
        const __nv_bfloat16* sh = aHi + (size_t)(gr < Nr ? gr : 0) * MK + k0 + lhalf * 16;
        const __nv_bfloat16* sl = aLo + (size_t)(gr < Nr ? gr : 0) * MK + k0 + lhalf * 16;
        CP16(dstA,              sh,     sz);
        CP16(dstA + 16,         sh + 8, sz);
        CP16(dstA + TILE,       sl,     sz);
        CP16(dstA + TILE + 16,  sl + 8, sz);
        int n = col0 + lr;   // padded rows always valid
        const __nv_bfloat16* bh = wHi + (size_t)n * MK + k0 + lhalf * 16;
        const __nv_bfloat16* bl = wLo + (size_t)n * MK + k0 + lhalf * 16;
        const uint32_t dstB = st + 2 * TILE + lr * RS + lhalf * 32;
        CP16(dstB,              bh,     16);
        CP16(dstB + 16,         bh + 8, 16);
        CP16(dstB + TILE,       bl,     16);
        CP16(dstB + TILE + 16,  bl + 8, 16);
        asm volatile("cp.async.commit_group;" ::: "memory");
    };

    auto compute = [&](int s) {
        const uint32_t aHiB = sbase + s * STAGE;
        const uint32_t aLoB = aHiB + TILE;
        const uint32_t bHiB = aHiB + 2 * TILE;
        const uint32_t bLoB = aHiB + 3 * TILE;
        const int sub = lid & 7;
        const int g1 = (lid >> 3) & 1;
        const int g2 = (lid >> 4) & 1;
        #pragma unroll
        for (int ks = 0; ks < 2; ks++) {
            uint32_t bh[2][4], bl[2][4];
            #pragma unroll
            for (int np = 0; np < 2; np++) {
                uint32_t r = wc * 32 + np * 16 + g2 * 8 + sub;
                uint32_t off = r * RS + (ks * 2 + g1) * 16;
                LDSM_X4(bh[np], bHiB + off);
                LDSM_X4(bl[np], bLoB + off);
            }
            {
                uint32_t af[4][4];
                #pragma unroll
                for (int mt = 0; mt < 4; mt++) {
                    uint32_t r = wr * 64 + mt * 16 + g1 * 8 + sub;
                    uint32_t off = r * RS + (ks * 2 + g2) * 16;
                    LDSM_X4(af[mt], aHiB + off);
                }
                #pragma unroll
                for (int mt = 0; mt < 4; mt++)
                    #pragma unroll
                    for (int nt = 0; nt < 4; nt++) {
                        const uint32_t* BH = &bh[nt >> 1][(nt & 1) * 2];
                        const uint32_t* BL = &bl[nt >> 1][(nt & 1) * 2];
                        MMA_BF16(acc[mt][nt], af[mt], BH[0], BH[1]);
                        MMA_BF16(acc[mt][nt], af[mt], BL[0], BL[1]);
                    }
                #pragma unroll
                for (int mt = 0; mt < 4; mt++) {
                    uint32_t r = wr * 64 + mt * 16 + g1 * 8 + sub;
                    uint32_t off = r * RS + (ks * 2 + g2) * 16;
                    LDSM_X4(af[mt], aLoB + off);
                }
                #pragma unroll
                for (int mt = 0; mt < 4; mt++)
                    #pragma unroll
                    for (int nt = 0; nt < 4; nt++) {
                        const uint32_t* BH = &bh[nt >> 1][(nt & 1) * 2];
                        MMA_BF16(acc[mt][nt], af[mt], BH[0], BH[1]);
                    }
            }
        }
    };

    // ---- mainloop: 3-stage cp.async pipeline ----
    issue_chunk(0, 0);
    if (nc > 1) issue_chunk(1, 1);
    if (nc > 2) issue_chunk(2, 2);
    int s = 0;
    for (int ci = 0; ci < nc; ci++) {
        int younger = nc - 1 - ci;
        if (younger >= 2)      { asm volatile("cp.async.wait_group 2;" ::: "memory"); }
        else if (younger == 1) { asm volatile("cp.async.wait_group 1;" ::: "memory"); }
        else                   { asm volatile("cp.async.wait_group 0;" ::: "memory"); }
        __syncthreads();
        compute(s);
        __syncthreads();
        if (ci + 3 < nc) issue_chunk(ci + 3, s);
        s = (s == 2) ? 0 : s + 1;
    }

    // ---- epilogue ----
    const int g = lid >> 2, tg = lid & 3;
    auto emit = [&](int row, int col, float v0, float v1) {
        if (row >= Nr) return;
        v0 += __ldg(&bias[col]);
        v1 += __ldg(&bias[col + 1]);
        if (relu) { v0 = fmaxf(v0, 0.f); v1 = fmaxf(v1, 0.f); }
        float2 v = make_float2(v0, v1);
        *(float2*)&C[(size_t)row * Kout + col] = v;
        if (pool != nullptr) {
            int bp = __ldg(&batch[row]);
            atomicMax((int*)&pool[(size_t)bp * Kout + col],     __float_as_int(v0));
            atomicMax((int*)&pool[(size_t)bp * Kout + col + 1], __float_as_int(v1));
        }
        if (amvo_out != nullptr) {
            float2 m = *(const float2*)&mu_in[(size_t)row * Kout + col];
            float2 e = *(const float2*)&eps_in[(size_t)row * Kout + col];
            float2 a;
            a.x = fmaf(e.x, __expf(0.5f * v0), m.x);
            a.y = fmaf(e.y, __expf(0.5f * v1), m.y);
            *(float2*)&amvo_out[(size_t)row * Kout + col] = a;
        }
    };
    #pragma unroll
    for (int mt = 0; mt < 4; mt++) {
        int rowb = row0 + wr * 64 + mt * 16 + g;
        #pragma unroll
        for (int nt = 0; nt < 4; nt++) {
            int col = col0 + wc * 32 + nt * 8 + 2 * tg;
            if (col >= Kout) continue;
            emit(rowb,     col, acc[mt][nt][0], acc[mt][nt][1]);
            emit(rowb + 8, col, acc[mt][nt][2], acc[mt][nt][3]);
        }
    }
}

// ---------------- fp32 SGEMM for the tiny FC head ----------------
__global__ __launch_bounds__(256) void sgemm_bias_kernel(
    const float* __restrict__ A, const float* __restrict__ W,
    const float* __restrict__ bias, float* __restrict__ C,
    int Nr, int M, int K, int relu) {
    const int BM = 128, BN = 64, BK = 16, TM = 8, TN = 4;
    __shared__ float As[BK][BM + 4];
    __shared__ float Bs[BK][BN];
    int row0 = blockIdx.y * BM;
    int col0 = blockIdx.x * BN;
    int tid = threadIdx.x;
    int tr = (tid / 16) * TM;
    int tc = (tid % 16) * TN;
    float acc[TM][TN] = {};

    for (int k0 = 0; k0 < M; k0 += BK) {
        #pragma unroll
        for (int l = tid; l < (BM * BK) / 4; l += 256) {
            int r = l >> 2;
            int m4 = (l & 3) << 2;
            float4 v = make_float4(0.f, 0.f, 0.f, 0.f);
            int gr = row0 + r;
            if (gr < Nr) v = *(const float4*)&A[(size_t)gr * M + k0 + m4];
            As[m4 + 0][r] = v.x;
            As[m4 + 1][r] = v.y;
            As[m4 + 2][r] = v.z;
            As[m4 + 3][r] = v.w;
        }
        {
            int m = tid >> 4;
            int c4 = (tid & 15) << 2;
            float4 v = *(const float4*)&W[(size_t)(k0 + m) * K + col0 + c4];
            *(float4*)&Bs[m][c4] = v;
        }
        __syncthreads();
        #pragma unroll
        for (int kk = 0; kk < BK; kk++) {
            float a[TM], b[TN];
            #pragma unroll
            for (int i = 0; i < TM; i++) a[i] = As[kk][tr + i];
            #pragma unroll
            for (int j = 0; j < TN; j++) b[j] = Bs[kk][tc + j];
            #pragma unroll
            for (int i = 0; i < TM; i++)
                #pragma unroll
                for (int j = 0; j < TN; j++)
                    acc[i][j] = fmaf(a[i], b[j], acc[i][j]);
        }
        __syncthreads();
    }

    #pragma unroll
    for (int i = 0; i < TM; i++) {
        int gr = row0 + tr + i;
        if (gr >= Nr) continue;
        #pragma unroll
        for (int j = 0; j < TN; j++) {
            int gc = col0 + tc + j;
            float v = acc[i][j] + bias[gc];
            if (relu) v = fmaxf(v, 0.0f);
            C[(size_t)gr * K + gc] = v;
        }
    }
}

// ---------------- launch orchestration ----------------
static inline void run_aggregate(const float* h, const float* dinv,
                                 const int* rowptr, const int* esrc,
                                 __nv_bfloat16* aggHi, __nv_bfloat16* aggLo, int F) {
    int blocks = (NN * 32 + 255) / 256;
    switch (F) {
        case 64:  gather_row_kernel<2><<<blocks, 256>>>(h, dinv, rowptr, esrc, aggHi, aggLo, NN, F); break;
        case 128: gather_row_kernel<4><<<blocks, 256>>>(h, dinv, rowptr, esrc, aggHi, aggLo, NN, F); break;
        case 192: gather_row_kernel<6><<<blocks, 256>>>(h, dinv, rowptr, esrc, aggHi, aggLo, NN, F); break;
        default:  gather_row_kernel<8><<<blocks, 256>>>(h, dinv, rowptr, esrc, aggHi, aggLo, NN, F); break;
    }
}

static inline void run_gemm_mma(const __nv_bfloat16* aHi, const __nv_bfloat16* aLo,
                                const __nv_bfloat16* wHi, const __nv_bfloat16* wLo,
                                const float* bias,
                                float* C, int Nr, int MK, int Kout, int relu,
                                const float* mu_in = nullptr,
                                const float* eps_in = nullptr,
                                float* amvo_out = nullptr,
                                const int* batch = nullptr,
                                float* pool = nullptr) {
    int gx = (Kout + 127) / 128;
    const int SMEM = 3 * 4 * 128 * RS;   // 3 stages x 40960 = 122880
    cudaFuncSetAttribute(gemm_mma_kernel,
                         cudaFuncAttributeMaxDynamicSharedMemorySize, SMEM);
    dim3 grid(gx, (Nr + 127) / 128);
    gemm_mma_kernel<<<grid, 256, SMEM>>>(aHi, aLo, wHi, wLo, bias, C, Nr, MK, Kout,
                                         relu, mu_in, eps_in, amvo_out, batch, pool);
}

extern "C" void kernel_launch(void* const* d_in, const int* in_sizes, int n_in,
                              void* d_out, int out_size) {
    const float* x     = (const float*)d_in[0];
    const int*   ei    = (const int*)d_in[1];
    const int*   batch = (const int*)d_in[2];
    const float* eps   = (const float*)d_in[3];
    const float* W1 = (const float*)d_in[4];  const float* b1 = (const float*)d_in[5];
    const float* W2 = (const float*)d_in[6];  const float* b2 = (const float*)d_in[7];
    const float* W3 = (const float*)d_in[8];  const float* b3 = (const float*)d_in[9];
    const float* Wmu = (const float*)d_in[10]; const float* bmu = (const float*)d_in[11];
    const float* Wlv = (const float*)d_in[12]; const float* blv = (const float*)d_in[13];
    const float* fc1w = (const float*)d_in[14]; const float* fc1b = (const float*)d_in[15];
    const float* fc2w = (const float*)d_in[16]; const float* fc2b = (const float*)d_in[17];

    float* out = (float*)d_out;
    float* out_amvo = out;
    float* out_mu   = out + (size_t)NN * 256;
    float* out_lv   = out + 2 * (size_t)NN * 256;
    float* out_pmvo = out + 3 * (size_t)NN * 256;

    float *dinv, *bufB, *x2, *hidden;
    int *cnt, *rowptr, *cursor, *esrc, *bsums;
    __nv_bfloat16 *aggHi, *aggLo, *wtHi, *wtLo;
    cudaGetSymbolAddress((void**)&dinv, g_dinv);
    cudaGetSymbolAddress((void**)&cnt, g_cnt);
    cudaGetSymbolAddress((void**)&rowptr, g_rowptr);
    cudaGetSymbolAddress((void**)&cursor, g_cursor);
    cudaGetSymbolAddress((void**)&esrc, g_esrc);
    cudaGetSymbolAddress((void**)&bsums, g_bsums);
    cudaGetSymbolAddress((void**)&aggHi, g_aggHi);
    cudaGetSymbolAddress((void**)&aggLo, g_aggLo);
    cudaGetSymbolAddress((void**)&bufB, g_bufB);
    cudaGetSymbolAddress((void**)&x2, g_x2);
    cudaGetSymbolAddress((void**)&hidden, g_hidden);
    cudaGetSymbolAddress((void**)&wtHi, g_wt_hi);
    cudaGetSymbolAddress((void**)&wtLo, g_wt_lo);

    const int* erow = ei;
    const int* ecol = ei + EE;

    const int SCAN_BLOCKS = (NN + 1023) / 1024;   // 98

    // all weight pre-splits up front (dedicated buffers, padded to 128-col mult)
    wsplit_kernel<<<(128 * 64  + 255) / 256, 256>>>(W1,  wtHi + WOFF_L1, wtLo + WOFF_L1, 64,  128, 128);
    wsplit_kernel<<<(256 * 128 + 255) / 256, 256>>>(W2,  wtHi + WOFF_L2, wtLo + WOFF_L2, 128, 192, 256);
    wsplit_kernel<<<(256 * 192 + 255) / 256, 256>>>(W3,  wtHi + WOFF_L3, wtLo + WOFF_L3, 192, 256, 256);
    wsplit_kernel<<<(256 * 256 + 255) / 256, 256>>>(Wmu, wtHi + WOFF_MU, wtLo + WOFF_MU, 256, 256, 256);
    wsplit_kernel<<<(256 * 256 + 255) / 256, 256>>>(Wlv, wtHi + WOFF_LV, wtLo + WOFF_LV, 256, 256, 256);

    // CSR build + normalization + pool init
    zero_int_kernel<<<(NN + 255) / 256, 256>>>(cnt, NN);
    count_kernel<<<(EE + 255) / 256, 256>>>(ecol, cnt, EE);
    dinv_kernel<<<(NN + 255) / 256, 256>>>(cnt, dinv, NN);
    block_reduce_kernel<<<SCAN_BLOCKS, 1024>>>(cnt, bsums, NN);
    scan_bsums_kernel<<<1, 128>>>(bsums, SCAN_BLOCKS);
    scan_final_kernel<<<SCAN_BLOCKS, 1024>>>(cnt, bsums, rowptr, cursor, NN);
    fill_kernel<<<(EE + 255) / 256, 256>>>(erow, ecol, cursor, esrc, EE);
    zero_kernel<<<(BB * 256 + 255) / 256, 256>>>(x2, BB * 256);

    // layer 1: aggregate(x,64) -> gemm 64->128 +relu
    run_aggregate(x, dinv, rowptr, esrc, aggHi, aggLo, 64);
    run_gemm_mma(aggHi, aggLo, wtHi + WOFF_L1, wtLo + WOFF_L1, b1, bufB, NN, 64, 128, 1);

    // layer 2: aggregate(h1,128) -> gemm 128->192 +relu
    run_aggregate(bufB, dinv, rowptr, esrc, aggHi, aggLo, 128);
    run_gemm_mma(aggHi, aggLo, wtHi + WOFF_L2, wtLo + WOFF_L2, b2, bufB, NN, 128, 192, 1);

    // layer 3: aggregate(h2,192) -> gemm 192->256 +relu, fused segment-max pool
    run_aggregate(bufB, dinv, rowptr, esrc, aggHi, aggLo, 192);
    run_gemm_mma(aggHi, aggLo, wtHi + WOFF_L3, wtLo + WOFF_L3, b3, bufB, NN, 192, 256, 1,
                 nullptr, nullptr, nullptr, batch, x2);

    // shared aggregation for mu / logvar heads
    run_aggregate(bufB, dinv, rowptr, esrc, aggHi, aggLo, 256);
    run_gemm_mma(aggHi, aggLo, wtHi + WOFF_MU, wtLo + WOFF_MU, bmu, out_mu, NN, 256, 256, 0);
    run_gemm_mma(aggHi, aggLo, wtHi + WOFF_LV, wtLo + WOFF_LV, blv, out_lv, NN, 256, 256, 0,
                 out_mu, eps, out_amvo);

    // MLP head on pooled features (tiny, fp32)
    {
        dim3 g1(1024 / 64, (BB + 127) / 128);
        sgemm_bias_kernel<<<g1, 256>>>(x2, fc1w, fc1b, hidden, BB, 256, 1024, 1);
        dim3 g2(128 / 64, (BB + 127) / 128);
        sgemm_bias_kernel<<<g2, 256>>>(hidden, fc2w, fc2b, out_pmvo, BB, 1024, 128, 0);
    }
}

// round 11
// speedup vs baseline: 1.1203x; 1.1119x over previous
#include <cuda_runtime.h>
#include <cuda_bf16.h>
#include <math.h>
#include <stdint.h>

#define NN 100000
#define EE 400000
#define BB 512

// ---------------- scratch (no allocations allowed) ----------------
__device__ float g_dinv[NN];
__device__ int   g_cnt[NN];
__device__ int   g_rowptr[NN + 1];
__device__ int   g_cursor[NN];
__device__ int   g_esrc[EE];
__device__ int   g_bsums[128];
__device__ __nv_bfloat16 g_aggHi[(size_t)NN * 256];  // aggregated A, high bf16
__device__ __nv_bfloat16 g_aggLo[(size_t)NN * 256];  // aggregated A, low  bf16
__device__ float g_bufB[(size_t)NN * 256];           // post-GEMM features (fp32)
__device__ float g_x2[BB * 256];                     // pooled max
__device__ float g_hidden[BB * 1024];                // fc1 output
// per-layer W^T split buffers (hi/lo planes), padded to 128-col multiples
#define WT_TOTAL (8192 + 32768 + 49152 + 65536 + 65536)
__device__ __nv_bfloat16 g_wt_hi[WT_TOTAL];
__device__ __nv_bfloat16 g_wt_lo[WT_TOTAL];
#define WOFF_L1 0
#define WOFF_L2 8192
#define WOFF_L3 40960
#define WOFF_MU 90112
#define WOFF_LV 155648

// ---------------- CSR construction ----------------
__global__ void count_kernel(const int* __restrict__ col, int* cnt, int e) {
    int i = blockIdx.x * blockDim.x + threadIdx.x;
    if (i < e) atomicAdd(&cnt[col[i]], 1);
}

__global__ void block_reduce_kernel(const int* __restrict__ cnt, int* bsums, int n) {
    __shared__ int wsum[32];
    int idx = blockIdx.x * 1024 + threadIdx.x;
    int lane = threadIdx.x & 31, wid = threadIdx.x >> 5;
    int v = (idx < n) ? cnt[idx] : 0;
    #pragma unroll
    for (int s = 16; s; s >>= 1) v += __shfl_down_sync(0xffffffffu, v, s);
    if (lane == 0) wsum[wid] = v;
    __syncthreads();
    if (wid == 0) {
        int t = wsum[lane];
        #pragma unroll
        for (int s = 16; s; s >>= 1) t += __shfl_down_sync(0xffffffffu, t, s);
        if (lane == 0) bsums[blockIdx.x] = t;
    }
}

__global__ void scan_bsums_kernel(int* bsums, int nb) {
    __shared__ int ws[4];
    int tid = threadIdx.x;
    int lane = tid & 31, wid = tid >> 5;
    int v = (tid < nb) ? bsums[tid] : 0;
    int incl = v;
    #pragma unroll
    for (int s = 1; s < 32; s <<= 1) {
        int t = __shfl_up_sync(0xffffffffu, incl, s);
        if (lane >= s) incl += t;
    }
    if (lane == 31) ws[wid] = incl;
    __syncthreads();
    if (tid == 0) {
        int a = 0;
        #pragma unroll
        for (int i = 0; i < 4; i++) { int t = ws[i]; ws[i] = a; a += t; }
    }
    __syncthreads();
    if (tid < nb) bsums[tid] = incl - v + ws[wid];
}

// also computes dinv (fused to save a launch)
__global__ void scan_final_kernel(const int* __restrict__ cnt, const int* __restrict__ boff,
                                  int* rowptr, int* cursor, float* dinv, int n) {
    __shared__ int wsum[32];
    int idx = blockIdx.x * 1024 + threadIdx.x;
    int lane = threadIdx.x & 31, wid = threadIdx.x >> 5;
    int v = (idx < n) ? cnt[idx] : 0;
    int incl = v;
    #pragma unroll
    for (int s = 1; s < 32; s <<= 1) {
        int t = __shfl_up_sync(0xffffffffu, incl, s);
        if (lane >= s) incl += t;
    }
    if (lane == 31) wsum[wid] = incl;
    __syncthreads();
    if (wid == 0) {
        int w = wsum[lane];
        int wi = w;
        #pragma unroll
        for (int s = 1; s < 32; s <<= 1) {
            int t = __shfl_up_sync(0xffffffffu, wi, s);
            if (lane >= s) wi += t;
        }
        wsum[lane] = wi - w;
    }
    __syncthreads();
    int excl = incl - v + wsum[wid] + __ldg(&boff[blockIdx.x]);
    if (idx < n) {
        rowptr[idx] = excl;
        cursor[idx] = excl;
        dinv[idx] = rsqrtf(1.0f + (float)v);   // +1 self-loop
        if (idx == n - 1) rowptr[n] = excl + v;
    }
}

__global__ void fill_kernel(const int* __restrict__ erow, const int* __restrict__ ecol,
                            int* cursor, int* esrc, int e) {
    int i = blockIdx.x * blockDim.x + threadIdx.x;
    if (i < e) {
        int pos = atomicAdd(&cursor[ecol[i]], 1);
        esrc[pos] = erow[i];
    }
}

// ---------------- gather aggregation: warp-per-node, bf16 hi/lo output --------
template <int COLS>   // COLS = F/32 floats per lane
__global__ void gather_row_kernel(const float* __restrict__ h,
                                  const float* __restrict__ dinv,
                                  const int* __restrict__ rowptr,
                                  const int* __restrict__ esrc,
                                  __nv_bfloat16* __restrict__ aggHi,
                                  __nv_bfloat16* __restrict__ aggLo,
                                  int n, int F) {
    int node = (blockIdx.x * blockDim.x + threadIdx.x) >> 5;
    int lane = threadIdx.x & 31;
    if (node >= n) return;
    const int c0 = lane * COLS;
    float dn = __ldg(&dinv[node]);
    float sum[COLS];
    {
        const float* r = h + (size_t)node * F + c0;
        #pragma unroll
        for (int j = 0; j < COLS; j++) sum[j] = dn * __ldg(&r[j]);
    }
    int s = __ldg(&rowptr[node]);
    int e = __ldg(&rowptr[node + 1]);
    int i = s;
    for (; i + 3 < e; i += 4) {
        int s0 = __ldg(&esrc[i]);
        int s1 = __ldg(&esrc[i + 1]);
        int s2 = __ldg(&esrc[i + 2]);
        int s3 = __ldg(&esrc[i + 3]);
        float d0 = __ldg(&dinv[s0]);
        float d1 = __ldg(&dinv[s1]);
        float d2 = __ldg(&dinv[s2]);
        float d3 = __ldg(&dinv[s3]);
        const float* r0 = h + (size_t)s0 * F + c0;
        const float* r1 = h + (size_t)s1 * F + c0;
        const float* r2 = h + (size_t)s2 * F + c0;
        const float* r3 = h + (size_t)s3 * F + c0;
        #pragma unroll
        for (int j = 0; j < COLS; j++) sum[j] += d0 * __ldg(&r0[j]);
        #pragma unroll
        for (int j = 0; j < COLS; j++) sum[j] += d1 * __ldg(&r1[j]);
        #pragma unroll
        for (int j = 0; j < COLS; j++) sum[j] += d2 * __ldg(&r2[j]);
        #pragma unroll
        for (int j = 0; j < COLS; j++) sum[j] += d3 * __ldg(&r3[j]);
    }
    for (; i < e; i++) {
        int s0 = __ldg(&esrc[i]);
        float d0 = __ldg(&dinv[s0]);
        const float* r0 = h + (size_t)s0 * F + c0;
        #pragma unroll
        for (int j = 0; j < COLS; j++) sum[j] += d0 * __ldg(&r0[j]);
    }
    __nv_bfloat16* oh = aggHi + (size_t)node * F + c0;
    __nv_bfloat16* ol = aggLo + (size_t)node * F + c0;
    #pragma unroll
    for (int j = 0; j < COLS; j++) {
        float v = dn * sum[j];
        __nv_bfloat16 hb = __float2bfloat16_rn(v);
        oh[j] = hb;
        ol[j] = __float2bfloat16_rn(v - __bfloat162float(hb));
    }
}

// ---------------- weight pre-split: W[MK,N] -> Wt_{hi,lo}[Npad,MK] bf16 -------
__global__ void wsplit_kernel(const float* __restrict__ W,
                              __nv_bfloat16* __restrict__ whi,
                              __nv_bfloat16* __restrict__ wlo,
                              int MK, int N, int Npad) {
    int idx = blockIdx.x * blockDim.x + threadIdx.x;
    if (idx >= Npad * MK) return;
    int n = idx / MK;
    int k = idx % MK;
    float v = (n < N) ? W[(size_t)k * N + n] : 0.0f;
    __nv_bfloat16 h = __float2bfloat16_rn(v);
    __nv_bfloat16 l = __float2bfloat16_rn(v - __bfloat162float(h));
    whi[(size_t)n * MK + k] = h;
    wlo[(size_t)n * MK + k] = l;
}

// ---------------- bf16x3 tensor-core GEMM with cp.async (R7-proven shape) -----
// 128x128 CTA tile, 2x4 warp grid, 2-stage pipeline, 80 KB smem.
// Tiles stored with 80-byte row stride: (addr/16) mod 8 = (5r+c) mod 8 bijective
// over 8 consecutive rows -> conflict-free ldmatrix. 16B-aligned (80 = 5*16).
#define RS 80

#define LDSM_X4(R, ADDR) \
    asm volatile("ldmatrix.sync.aligned.m8n8.x4.shared.b16 {%0,%1,%2,%3}, [%4];" \
        : "=r"((R)[0]), "=r"((R)[1]), "=r"((R)[2]), "=r"((R)[3]) : "r"(ADDR))

#define MMA_BF16(CC, AA, B0, B1) \
    asm volatile("mma.sync.aligned.m16n8k16.row.col.f32.bf16.bf16.f32 " \
        "{%0,%1,%2,%3}, {%4,%5,%6,%7}, {%8,%9}, {%0,%1,%2,%3};" \
        : "+f"((CC)[0]), "+f"((CC)[1]), "+f"((CC)[2]), "+f"((CC)[3]) \
        : "r"((AA)[0]), "r"((AA)[1]), "r"((AA)[2]), "r"((AA)[3]), \
          "r"(B0), "r"(B1))

#define CP16(DST, SRC, SZ) \
    asm volatile("cp.async.ca.shared.global [%0], [%1], 16, %2;" \
        :: "r"(DST), "l"(SRC), "r"(SZ) : "memory")

__global__ void __launch_bounds__(256)
gemm_mma_kernel(const __nv_bfloat16* __restrict__ aHi,
                const __nv_bfloat16* __restrict__ aLo,
                const __nv_bfloat16* __restrict__ wHi,
                const __nv_bfloat16* __restrict__ wLo,
                const float* __restrict__ bias,
                float* __restrict__ C, int Nr, int MK, int Kout, int relu,
                const float* __restrict__ mu_in, const float* __restrict__ eps_in,
                float* __restrict__ amvo_out,
                const int* __restrict__ batch, float* __restrict__ pool) {
    extern __shared__ char smem[];
    const int tid = threadIdx.x;
    const int w = tid >> 5, lid = tid & 31;
    const int wr = w >> 2, wc = w & 3;          // warp grid 2x4 over 128x128
    const int row0 = blockIdx.y * 128, col0 = blockIdx.x * 128;
    const uint32_t sbase = (uint32_t)__cvta_generic_to_shared(smem);

    const int TILE = 128 * RS;                   // 10240 B per plane
    const int STAGE = 4 * TILE;                  // AsHi | AsLo | BsHi | BsLo

    float acc[4][4][4] = {};

    const int nc = MK >> 5;               // chunks of 32

    const int lr = tid >> 1;              // 0..127
    const int lhalf = tid & 1;            // 0/1 (32B halves of the 64B row)

    auto issue_chunk = [&](int ci, int s) {
        const int k0 = ci << 5;
        const uint32_t st = sbase + s * STAGE;
        const uint32_t dstA = st + lr * RS + lhalf * 32;
        int gr = row0 + lr;
        int sz = (gr < Nr) ? 16 : 0;
        const __nv_bfloat16* sh = aHi + (size_t)(gr < Nr ? gr : 0) * MK + k0 + lhalf * 16;
        const __nv_bfloat16* sl = aLo + (size_t)(gr < Nr ? gr : 0) * MK + k0 + lhalf * 16;
        CP16(dstA,              sh,     sz);
        CP16(dstA + 16,         sh + 8, sz);
        CP16(dstA + TILE,       sl,     sz);
        CP16(dstA + TILE + 16,  sl + 8, sz);
        int n = col0 + lr;   // padded rows always valid
        const __nv_bfloat16* bh = wHi + (size_t)n * MK + k0 + lhalf * 16;
        const __nv_bfloat16* bl = wLo + (size_t)n * MK + k0 + lhalf * 16;
        const uint32_t dstB = st + 2 * TILE + lr * RS + lhalf * 32;
        CP16(dstB,              bh,     16);
        CP16(dstB + 16,         bh + 8, 16);
        CP16(dstB + TILE,       bl,     16);
        CP16(dstB + TILE + 16,  bl + 8, 16);
        asm volatile("cp.async.commit_group;" ::: "memory");
    };

    auto compute = [&](int s) {
        const uint32_t aHiB = sbase + s * STAGE;
        const uint32_t aLoB = aHiB + TILE;
        const uint32_t bHiB = aHiB + 2 * TILE;
        const uint32_t bLoB = aHiB + 3 * TILE;
        const int sub = lid & 7;
        const int g1 = (lid >> 3) & 1;
        const int g2 = (lid >> 4) & 1;
        #pragma unroll
        for (int ks = 0; ks < 2; ks++) {
            uint32_t bh[2][4], bl[2][4];
            #pragma unroll
            for (int np = 0; np < 2; np++) {
                uint32_t r = wc * 32 + np * 16 + g2 * 8 + sub;
                uint32_t off = r * RS + (ks * 2 + g1) * 16;
                LDSM_X4(bh[np], bHiB + off);
                LDSM_X4(bl[np], bLoB + off);
            }
            {
                uint32_t af[4][4];
                #pragma unroll
                for (int mt = 0; mt < 4; mt++) {
                    uint32_t r = wr * 64 + mt * 16 + g1 * 8 + sub;
                    uint32_t off = r * RS + (ks * 2 + g2) * 16;
                    LDSM_X4(af[mt], aHiB + off);
                }
                #pragma unroll
                for (int mt = 0; mt < 4; mt++)
                    #pragma unroll
                    for (int nt = 0; nt < 4; nt++) {
                        const uint32_t* BH = &bh[nt >> 1][(nt & 1) * 2];
                        const uint32_t* BL = &bl[nt >> 1][(nt & 1) * 2];
                        MMA_BF16(acc[mt][nt], af[mt], BH[0], BH[1]);
                        MMA_BF16(acc[mt][nt], af[mt], BL[0], BL[1]);
                    }
                #pragma unroll
                for (int mt = 0; mt < 4; mt++) {
                    uint32_t r = wr * 64 + mt * 16 + g1 * 8 + sub;
                    uint32_t off = r * RS + (ks * 2 + g2) * 16;
                    LDSM_X4(af[mt], aLoB + off);
                }
                #pragma unroll
                for (int mt = 0; mt < 4; mt++)
                    #pragma unroll
                    for (int nt = 0; nt < 4; nt++) {
                        const uint32_t* BH = &bh[nt >> 1][(nt & 1) * 2];
                        MMA_BF16(acc[mt][nt], af[mt], BH[0], BH[1]);
                    }
            }
        }
    };

    // ---- mainloop: 2-stage cp.async pipeline (R7) ----
    issue_chunk(0, 0);
    if (nc > 1) issue_chunk(1, 1);
    for (int ci = 0; ci < nc; ci++) {
        int s = ci & 1;
        if (ci < nc - 1) {
            asm volatile("cp.async.wait_group 1;" ::: "memory");
        } else {
            asm volatile("cp.async.wait_group 0;" ::: "memory");
        }
        __syncthreads();
        compute(s);
        __syncthreads();
        if (ci + 2 < nc) issue_chunk(ci + 2, s);
    }

    // ---- epilogue (pool path uses warp-reduced atomics; batch is sorted) ----
    const int g = lid >> 2, tg = lid & 3;
    #pragma unroll
    for (int mt = 0; mt < 4; mt++) {
        const int ra = row0 + wr * 64 + mt * 16 + g;   // row A (g in 0..7)
        const int rb = ra + 8;                          // row B
        // batch uniformity across this 16-row group (pool only)
        int ba = 0, bb = 0;
        bool grp_uniform = false;
        if (pool != nullptr) {
            ba = __ldg(&batch[ra < Nr ? ra : (Nr - 1)]);
            bb = __ldg(&batch[rb < Nr ? rb : (Nr - 1)]);
            int bmin = min(ba, bb), bmax = max(ba, bb);
            #pragma unroll
            for (int msk = 4; msk <= 16; msk <<= 1) {
                bmin = min(bmin, __shfl_xor_sync(0xffffffffu, bmin, msk));
                bmax = max(bmax, __shfl_xor_sync(0xffffffffu, bmax, msk));
            }
            grp_uniform = (bmin == bmax);
        }
        #pragma unroll
        for (int nt = 0; nt < 4; nt++) {
            int col = col0 + wc * 32 + nt * 8 + 2 * tg;
            if (col >= Kout) continue;   // warp-uniform (tiles are 8-col aligned)
            float bs0 = __ldg(&bias[col]);
            float bs1 = __ldg(&bias[col + 1]);
            float a0 = acc[mt][nt][0] + bs0, a1 = acc[mt][nt][1] + bs1;
            float b0 = acc[mt][nt][2] + bs0, b1 = acc[mt][nt][3] + bs1;
            if (relu) {
                a0 = fmaxf(a0, 0.f); a1 = fmaxf(a1, 0.f);
                b0 = fmaxf(b0, 0.f); b1 = fmaxf(b1, 0.f);
            }
            if (ra < Nr) {
                *(float2*)&C[(size_t)ra * Kout + col] = make_float2(a0, a1);
                if (amvo_out != nullptr) {
                    float2 m = *(const float2*)&mu_in[(size_t)ra * Kout + col];
                    float2 e = *(const float2*)&eps_in[(size_t)ra * Kout + col];
                    float2 o;
                    o.x = fmaf(e.x, __expf(0.5f * a0), m.x);
                    o.y = fmaf(e.y, __expf(0.5f * a1), m.y);
                    *(float2*)&amvo_out[(size_t)ra * Kout + col] = o;
                }
            }
            if (rb < Nr) {
                *(float2*)&C[(size_t)rb * Kout + col] = make_float2(b0, b1);
                if (amvo_out != nullptr) {
                    float2 m = *(const float2*)&mu_in[(size_t)rb * Kout + col];
                    float2 e = *(const float2*)&eps_in[(size_t)rb * Kout + col];
                    float2 o;
                    o.x = fmaf(e.x, __expf(0.5f * b0), m.x);
                    o.y = fmaf(e.y, __expf(0.5f * b1), m.y);
                    *(float2*)&amvo_out[(size_t)rb * Kout + col] = o;
                }
            }
            if (pool != nullptr) {
                // values >= 0 post-relu: 0 contribution is harmless, int-max valid
                float va0 = (ra < Nr) ? a0 : 0.f, va1 = (ra < Nr) ? a1 : 0.f;
                float vb0 = (rb < Nr) ? b0 : 0.f, vb1 = (rb < Nr) ? b1 : 0.f;
                if (grp_uniform) {
                    float m0 = fmaxf(va0, vb0), m1 = fmaxf(va1, vb1);
                    #pragma unroll
                    for (int msk = 4; msk <= 16; msk <<= 1) {
                        m0 = fmaxf(m0, __shfl_xor_sync(0xffffffffu, m0, msk));
                        m1 = fmaxf(m1, __shfl_xor_sync(0xffffffffu, m1, msk));
                    }
                    if (g == 0) {
                        atomicMax((int*)&pool[(size_t)ba * Kout + col],     __float_as_int(m0));
                        atomicMax((int*)&pool[(size_t)ba * Kout + col + 1], __float_as_int(m1));
                    }
                } else {
                    if (ra < Nr) {
                        atomicMax((int*)&pool[(size_t)ba * Kout + col],     __float_as_int(a0));
                        atomicMax((int*)&pool[(size_t)ba * Kout + col + 1], __float_as_int(a1));
                    }
                    if (rb < Nr) {
                        atomicMax((int*)&pool[(size_t)bb * Kout + col],     __float_as_int(b0));
                        atomicMax((int*)&pool[(size_t)bb * Kout + col + 1], __float_as_int(b1));
                    }
                }
            }
        }
    }
}

// ---------------- fp32 SGEMM for the tiny FC head ----------------
__global__ __launch_bounds__(256) void sgemm_bias_kernel(
    const float* __restrict__ A, const float* __restrict__ W,
    const float* __restrict__ bias, float* __restrict__ C,
    int Nr, int M, int K, int relu) {
    const int BM = 128, BN = 64, BK = 16, TM = 8, TN = 4;
    __shared__ float As[BK][BM + 4];
    __shared__ float Bs[BK][BN];
    int row0 = blockIdx.y * BM;
    int col0 = blockIdx.x * BN;
    int tid = threadIdx.x;
    int tr = (tid / 16) * TM;
    int tc = (tid % 16) * TN;
    float acc[TM][TN] = {};

    for (int k0 = 0; k0 < M; k0 += BK) {
        #pragma unroll
        for (int l = tid; l < (BM * BK) / 4; l += 256) {
            int r = l >> 2;
            int m4 = (l & 3) << 2;
            float4 v = make_float4(0.f, 0.f, 0.f, 0.f);
            int gr = row0 + r;
            if (gr < Nr) v = *(const float4*)&A[(size_t)gr * M + k0 + m4];
            As[m4 + 0][r] = v.x;
            As[m4 + 1][r] = v.y;
            As[m4 + 2][r] = v.z;
            As[m4 + 3][r] = v.w;
        }
        {
            int m = tid >> 4;
            int c4 = (tid & 15) << 2;
            float4 v = *(const float4*)&W[(size_t)(k0 + m) * K + col0 + c4];
            *(float4*)&Bs[m][c4] = v;
        }
        __syncthreads();
        #pragma unroll
        for (int kk = 0; kk < BK; kk++) {
            float a[TM], b[TN];
            #pragma unroll
            for (int i = 0; i < TM; i++) a[i] = As[kk][tr + i];
            #pragma unroll
            for (int j = 0; j < TN; j++) b[j] = Bs[kk][tc + j];
            #pragma unroll
            for (int i = 0; i < TM; i++)
                #pragma unroll
                for (int j = 0; j < TN; j++)
                    acc[i][j] = fmaf(a[i], b[j], acc[i][j]);
        }
        __syncthreads();
    }

    #pragma unroll
    for (int i = 0; i < TM; i++) {
        int gr = row0 + tr + i;
        if (gr >= Nr) continue;
        #pragma unroll
        for (int j = 0; j < TN; j++) {
            int gc = col0 + tc + j;
            float v = acc[i][j] + bias[gc];
            if (relu) v = fmaxf(v, 0.0f);
            C[(size_t)gr * K + gc] = v;
        }
    }
}

// ---------------- launch orchestration ----------------
static inline void run_aggregate(const float* h, const float* dinv,
                                 const int* rowptr, const int* esrc,
                                 __nv_bfloat16* aggHi, __nv_bfloat16* aggLo, int F) {
    int blocks = (NN * 32 + 255) / 256;
    switch (F) {
        case 64:  gather_row_kernel<2><<<blocks, 256>>>(h, dinv, rowptr, esrc, aggHi, aggLo, NN, F); break;
        case 128: gather_row_kernel<4><<<blocks, 256>>>(h, dinv, rowptr, esrc, aggHi, aggLo, NN, F); break;
        case 192: gather_row_kernel<6><<<blocks, 256>>>(h, dinv, rowptr, esrc, aggHi, aggLo, NN, F); break;
        default:  gather_row_kernel<8><<<blocks, 256>>>(h, dinv, rowptr, esrc, aggHi, aggLo, NN, F); break;
    }
}

static inline void run_gemm_mma(const __nv_bfloat16* aHi, const __nv_bfloat16* aLo,
                                const __nv_bfloat16* wHi, const __nv_bfloat16* wLo,
                                const float* bias,
                                float* C, int Nr, int MK, int Kout, int relu,
                                const float* mu_in = nullptr,
                                const float* eps_in = nullptr,
                                float* amvo_out = nullptr,
                                const int* batch = nullptr,
                                float* pool = nullptr) {
    int gx = (Kout + 127) / 128;
    const int SMEM = 2 * 4 * 128 * RS;   // 81920 (R7-proven)
    cudaFuncSetAttribute(gemm_mma_kernel,
                         cudaFuncAttributeMaxDynamicSharedMemorySize, SMEM);
    dim3 grid(gx, (Nr + 127) / 128);
    gemm_mma_kernel<<<grid, 256, SMEM>>>(aHi, aLo, wHi, wLo, bias, C, Nr, MK, Kout,
                                         relu, mu_in, eps_in, amvo_out, batch, pool);
}

extern "C" void kernel_launch(void* const* d_in, const int* in_sizes, int n_in,
                              void* d_out, int out_size) {
    const float* x     = (const float*)d_in[0];
    const int*   ei    = (const int*)d_in[1];
    const int*   batch = (const int*)d_in[2];
    const float* eps   = (const float*)d_in[3];
    const float* W1 = (const float*)d_in[4];  const float* b1 = (const float*)d_in[5];
    const float* W2 = (const float*)d_in[6];  const float* b2 = (const float*)d_in[7];
    const float* W3 = (const float*)d_in[8];  const float* b3 = (const float*)d_in[9];
    const float* Wmu = (const float*)d_in[10]; const float* bmu = (const float*)d_in[11];
    const float* Wlv = (const float*)d_in[12]; const float* blv = (const float*)d_in[13];
    const float* fc1w = (const float*)d_in[14]; const float* fc1b = (const float*)d_in[15];
    const float* fc2w = (const float*)d_in[16]; const float* fc2b = (const float*)d_in[17];

    float* out = (float*)d_out;
    float* out_amvo = out;
    float* out_mu   = out + (size_t)NN * 256;
    float* out_lv   = out + 2 * (size_t)NN * 256;
    float* out_pmvo = out + 3 * (size_t)NN * 256;

    float *dinv, *bufB, *x2, *hidden;
    int *cnt, *rowptr, *cursor, *esrc, *bsums;
    __nv_bfloat16 *aggHi, *aggLo, *wtHi, *wtLo;
    cudaGetSymbolAddress((void**)&dinv, g_dinv);
    cudaGetSymbolAddress((void**)&cnt, g_cnt);
    cudaGetSymbolAddress((void**)&rowptr, g_rowptr);
    cudaGetSymbolAddress((void**)&cursor, g_cursor);
    cudaGetSymbolAddress((void**)&esrc, g_esrc);
    cudaGetSymbolAddress((void**)&bsums, g_bsums);
    cudaGetSymbolAddress((void**)&aggHi, g_aggHi);
    cudaGetSymbolAddress((void**)&aggLo, g_aggLo);
    cudaGetSymbolAddress((void**)&bufB, g_bufB);
    cudaGetSymbolAddress((void**)&x2, g_x2);
    cudaGetSymbolAddress((void**)&hidden, g_hidden);
    cudaGetSymbolAddress((void**)&wtHi, g_wt_hi);
    cudaGetSymbolAddress((void**)&wtLo, g_wt_lo);

    const int* erow = ei;
    const int* ecol = ei + EE;

    const int SCAN_BLOCKS = (NN + 1023) / 1024;   // 98

    // zero scratch via memset nodes (graph-capturable, no kernel launches)
    cudaMemsetAsync(cnt, 0, NN * sizeof(int));
    cudaMemsetAsync(x2, 0, BB * 256 * sizeof(float));

    // all weight pre-splits up front (dedicated buffers, padded to 128-col mult)
    wsplit_kernel<<<(128 * 64  + 255) / 256, 256>>>(W1,  wtHi + WOFF_L1, wtLo + WOFF_L1, 64,  128, 128);
    wsplit_kernel<<<(256 * 128 + 255) / 256, 256>>>(W2,  wtHi + WOFF_L2, wtLo + WOFF_L2, 128, 192, 256);
    wsplit_kernel<<<(256 * 192 + 255) / 256, 256>>>(W3,  wtHi + WOFF_L3, wtLo + WOFF_L3, 192, 256, 256);
    wsplit_kernel<<<(256 * 256 + 255) / 256, 256>>>(Wmu, wtHi + WOFF_MU, wtLo + WOFF_MU, 256, 256, 256);
    wsplit_kernel<<<(256 * 256 + 255) / 256, 256>>>(Wlv, wtHi + WOFF_LV, wtLo + WOFF_LV, 256, 256, 256);

    // CSR build + normalization (dinv fused into scan_final)
    count_kernel<<<(EE + 255) / 256, 256>>>(ecol, cnt, EE);
    block_reduce_kernel<<<SCAN_BLOCKS, 1024>>>(cnt, bsums, NN);
    scan_bsums_kernel<<<1, 128>>>(bsums, SCAN_BLOCKS);
    scan_final_kernel<<<SCAN_BLOCKS, 1024>>>(cnt, bsums, rowptr, cursor, dinv, NN);
    fill_kernel<<<(EE + 255) / 256, 256>>>(erow, ecol, cursor, esrc, EE);

    // layer 1: aggregate(x,64) -> gemm 64->128 +relu
    run_aggregate(x, dinv, rowptr, esrc, aggHi, aggLo, 64);
    run_gemm_mma(aggHi, aggLo, wtHi + WOFF_L1, wtLo + WOFF_L1, b1, bufB, NN, 64, 128, 1);

    // layer 2: aggregate(h1,128) -> gemm 128->192 +relu
    run_aggregate(bufB, dinv, rowptr, esrc, aggHi, aggLo, 128);
    run_gemm_mma(aggHi, aggLo, wtHi + WOFF_L2, wtLo + WOFF_L2, b2, bufB, NN, 128, 192, 1);

    // layer 3: aggregate(h2,192) -> gemm 192->256 +relu, fused segment-max pool
    run_aggregate(bufB, dinv, rowptr, esrc, aggHi, aggLo, 192);
    run_gemm_mma(aggHi, aggLo, wtHi + WOFF_L3, wtLo + WOFF_L3, b3, bufB, NN, 192, 256, 1,
                 nullptr, nullptr, nullptr, batch, x2);

    // shared aggregation for mu / logvar heads
    run_aggregate(bufB, dinv, rowptr, esrc, aggHi, aggLo, 256);
    run_gemm_mma(aggHi, aggLo, wtHi + WOFF_MU, wtLo + WOFF_MU, bmu, out_mu, NN, 256, 256, 0);
    run_gemm_mma(aggHi, aggLo, wtHi + WOFF_LV, wtLo + WOFF_LV, blv, out_lv, NN, 256, 256, 0,
                 out_mu, eps, out_amvo);

    // MLP head on pooled features (tiny, fp32)
    {
        dim3 g1(1024 / 64, (BB + 127) / 128);
        sgemm_bias_kernel<<<g1, 256>>>(x2, fc1w, fc1b, hidden, BB, 256, 1024, 1);
        dim3 g2(128 / 64, (BB + 127) / 128);
        sgemm_bias_kernel<<<g2, 256>>>(hidden, fc2w, fc2b, out_pmvo, BB, 1024, 128, 0);
    }
}

// round 12
// speedup vs baseline: 1.2665x; 1.1306x over previous
#include <cuda_runtime.h>
#include <cuda_bf16.h>
#include <math.h>
#include <stdint.h>

#define NN 100000
#define EE 400000
#define BB 512

// ---------------- scratch (no allocations allowed) ----------------
__device__ float g_dinv[NN];
__device__ int   g_cnt[NN];
__device__ int   g_rowptr[NN + 1];
__device__ int   g_cursor[NN];
__device__ int   g_esrc[EE];
__device__ int   g_bsums[128];
__device__ __nv_bfloat16 g_aggHi[(size_t)NN * 256];  // aggregated A, high bf16
__device__ __nv_bfloat16 g_aggLo[(size_t)NN * 256];  // aggregated A, low  bf16
__device__ float g_bufB[(size_t)NN * 256];           // post-GEMM features (fp32)
__device__ float g_x2[BB * 256];                     // pooled max
__device__ float g_hidden[BB * 1024];                // fc1 output
// per-layer W^T split buffers (hi/lo planes), padded to 128-col multiples
#define WT_TOTAL (8192 + 32768 + 49152 + 65536 + 65536)
__device__ __nv_bfloat16 g_wt_hi[WT_TOTAL];
__device__ __nv_bfloat16 g_wt_lo[WT_TOTAL];
#define WOFF_L1 0
#define WOFF_L2 8192
#define WOFF_L3 40960
#define WOFF_MU 90112
#define WOFF_LV 155648

// ---------------- CSR construction ----------------
__global__ void count_kernel(const int* __restrict__ col, int* cnt, int e) {
    int i = blockIdx.x * blockDim.x + threadIdx.x;
    if (i < e) atomicAdd(&cnt[col[i]], 1);
}

__global__ void block_reduce_kernel(const int* __restrict__ cnt, int* bsums, int n) {
    __shared__ int wsum[32];
    int idx = blockIdx.x * 1024 + threadIdx.x;
    int lane = threadIdx.x & 31, wid = threadIdx.x >> 5;
    int v = (idx < n) ? cnt[idx] : 0;
    #pragma unroll
    for (int s = 16; s; s >>= 1) v += __shfl_down_sync(0xffffffffu, v, s);
    if (lane == 0) wsum[wid] = v;
    __syncthreads();
    if (wid == 0) {
        int t = wsum[lane];
        #pragma unroll
        for (int s = 16; s; s >>= 1) t += __shfl_down_sync(0xffffffffu, t, s);
        if (lane == 0) bsums[blockIdx.x] = t;
    }
}

__global__ void scan_bsums_kernel(int* bsums, int nb) {
    __shared__ int ws[4];
    int tid = threadIdx.x;
    int lane = tid & 31, wid = tid >> 5;
    int v = (tid < nb) ? bsums[tid] : 0;
    int incl = v;
    #pragma unroll
    for (int s = 1; s < 32; s <<= 1) {
        int t = __shfl_up_sync(0xffffffffu, incl, s);
        if (lane >= s) incl += t;
    }
    if (lane == 31) ws[wid] = incl;
    __syncthreads();
    if (tid == 0) {
        int a = 0;
        #pragma unroll
        for (int i = 0; i < 4; i++) { int t = ws[i]; ws[i] = a; a += t; }
    }
    __syncthreads();
    if (tid < nb) bsums[tid] = incl - v + ws[wid];
}

// also computes dinv (fused to save a launch)
__global__ void scan_final_kernel(const int* __restrict__ cnt, const int* __restrict__ boff,
                                  int* rowptr, int* cursor, float* dinv, int n) {
    __shared__ int wsum[32];
    int idx = blockIdx.x * 1024 + threadIdx.x;
    int lane = threadIdx.x & 31, wid = threadIdx.x >> 5;
    int v = (idx < n) ? cnt[idx] : 0;
    int incl = v;
    #pragma unroll
    for (int s = 1; s < 32; s <<= 1) {
        int t = __shfl_up_sync(0xffffffffu, incl, s);
        if (lane >= s) incl += t;
    }
    if (lane == 31) wsum[wid] = incl;
    __syncthreads();
    if (wid == 0) {
        int w = wsum[lane];
        int wi = w;
        #pragma unroll
        for (int s = 1; s < 32; s <<= 1) {
            int t = __shfl_up_sync(0xffffffffu, wi, s);
            if (lane >= s) wi += t;
        }
        wsum[lane] = wi - w;
    }
    __syncthreads();
    int excl = incl - v + wsum[wid] + __ldg(&boff[blockIdx.x]);
    if (idx < n) {
        rowptr[idx] = excl;
        cursor[idx] = excl;
        dinv[idx] = rsqrtf(1.0f + (float)v);   // +1 self-loop
        if (idx == n - 1) rowptr[n] = excl + v;
    }
}

__global__ void fill_kernel(const int* __restrict__ erow, const int* __restrict__ ecol,
                            int* cursor, int* esrc, int e) {
    int i = blockIdx.x * blockDim.x + threadIdx.x;
    if (i < e) {
        int pos = atomicAdd(&cursor[ecol[i]], 1);
        esrc[pos] = erow[i];
    }
}

// ---------------- gather aggregation: warp-per-node, COALESCED columns --------
// Lane owns strided columns c = j*32 + lane  ->  every load instruction covers
// one contiguous 128 B line (1 L1tex wavefront) instead of 8.
template <int COLS>   // COLS = F/32 floats per lane
__global__ void gather_row_kernel(const float* __restrict__ h,
                                  const float* __restrict__ dinv,
                                  const int* __restrict__ rowptr,
                                  const int* __restrict__ esrc,
                                  __nv_bfloat16* __restrict__ aggHi,
                                  __nv_bfloat16* __restrict__ aggLo,
                                  int n, int F) {
    int node = (blockIdx.x * blockDim.x + threadIdx.x) >> 5;
    int lane = threadIdx.x & 31;
    if (node >= n) return;
    float dn = __ldg(&dinv[node]);
    float sum[COLS];
    {
        const float* r = h + (size_t)node * F + lane;
        #pragma unroll
        for (int j = 0; j < COLS; j++) sum[j] = dn * __ldg(&r[j * 32]);
    }
    int s = __ldg(&rowptr[node]);
    int e = __ldg(&rowptr[node + 1]);
    int i = s;
    for (; i + 3 < e; i += 4) {
        int s0 = __ldg(&esrc[i]);
        int s1 = __ldg(&esrc[i + 1]);
        int s2 = __ldg(&esrc[i + 2]);
        int s3 = __ldg(&esrc[i + 3]);
        float d0 = __ldg(&dinv[s0]);
        float d1 = __ldg(&dinv[s1]);
        float d2 = __ldg(&dinv[s2]);
        float d3 = __ldg(&dinv[s3]);
        const float* r0 = h + (size_t)s0 * F + lane;
        const float* r1 = h + (size_t)s1 * F + lane;
        const float* r2 = h + (size_t)s2 * F + lane;
        const float* r3 = h + (size_t)s3 * F + lane;
        #pragma unroll
        for (int j = 0; j < COLS; j++) sum[j] += d0 * __ldg(&r0[j * 32]);
        #pragma unroll
        for (int j = 0; j < COLS; j++) sum[j] += d1 * __ldg(&r1[j * 32]);
        #pragma unroll
        for (int j = 0; j < COLS; j++) sum[j] += d2 * __ldg(&r2[j * 32]);
        #pragma unroll
        for (int j = 0; j < COLS; j++) sum[j] += d3 * __ldg(&r3[j * 32]);
    }
    for (; i < e; i++) {
        int s0 = __ldg(&esrc[i]);
        float d0 = __ldg(&dinv[s0]);
        const float* r0 = h + (size_t)s0 * F + lane;
        #pragma unroll
        for (int j = 0; j < COLS; j++) sum[j] += d0 * __ldg(&r0[j * 32]);
    }
    __nv_bfloat16* oh = aggHi + (size_t)node * F + lane;
    __nv_bfloat16* ol = aggLo + (size_t)node * F + lane;
    #pragma unroll
    for (int j = 0; j < COLS; j++) {
        float v = dn * sum[j];
        __nv_bfloat16 hb = __float2bfloat16_rn(v);
        oh[j * 32] = hb;
        ol[j * 32] = __float2bfloat16_rn(v - __bfloat162float(hb));
    }
}

// ---------------- weight pre-split: W[MK,N] -> Wt_{hi,lo}[Npad,MK] bf16 -------
__global__ void wsplit_kernel(const float* __restrict__ W,
                              __nv_bfloat16* __restrict__ whi,
                              __nv_bfloat16* __restrict__ wlo,
                              int MK, int N, int Npad) {
    int idx = blockIdx.x * blockDim.x + threadIdx.x;
    if (idx >= Npad * MK) return;
    int n = idx / MK;
    int k = idx % MK;
    float v = (n < N) ? W[(size_t)k * N + n] : 0.0f;
    __nv_bfloat16 h = __float2bfloat16_rn(v);
    __nv_bfloat16 l = __float2bfloat16_rn(v - __bfloat162float(h));
    whi[(size_t)n * MK + k] = h;
    wlo[(size_t)n * MK + k] = l;
}

// ---------------- bf16x3 tensor-core GEMM with cp.async (R7-proven shape) -----
// 128x128 CTA tile, 2x4 warp grid, 2-stage pipeline, 80 KB smem.
// Tiles stored with 80-byte row stride: (addr/16) mod 8 = (5r+c) mod 8 bijective
// over 8 consecutive rows -> conflict-free ldmatrix. 16B-aligned (80 = 5*16).
#define RS 80

#define LDSM_X4(R, ADDR) \
    asm volatile("ldmatrix.sync.aligned.m8n8.x4.shared.b16 {%0,%1,%2,%3}, [%4];" \
        : "=r"((R)[0]), "=r"((R)[1]), "=r"((R)[2]), "=r"((R)[3]) : "r"(ADDR))

#define MMA_BF16(CC, AA, B0, B1) \
    asm volatile("mma.sync.aligned.m16n8k16.row.col.f32.bf16.bf16.f32 " \
        "{%0,%1,%2,%3}, {%4,%5,%6,%7}, {%8,%9}, {%0,%1,%2,%3};" \
        : "+f"((CC)[0]), "+f"((CC)[1]), "+f"((CC)[2]), "+f"((CC)[3]) \
        : "r"((AA)[0]), "r"((AA)[1]), "r"((AA)[2]), "r"((AA)[3]), \
          "r"(B0), "r"(B1))

#define CP16(DST, SRC, SZ) \
    asm volatile("cp.async.ca.shared.global [%0], [%1], 16, %2;" \
        :: "r"(DST), "l"(SRC), "r"(SZ) : "memory")

__global__ void __launch_bounds__(256)
gemm_mma_kernel(const __nv_bfloat16* __restrict__ aHi,
                const __nv_bfloat16* __restrict__ aLo,
                const __nv_bfloat16* __restrict__ wHi,
                const __nv_bfloat16* __restrict__ wLo,
                const float* __restrict__ bias,
                float* __restrict__ C, int Nr, int MK, int Kout, int relu,
                const float* __restrict__ mu_in, const float* __restrict__ eps_in,
                float* __restrict__ amvo_out,
                const int* __restrict__ batch, float* __restrict__ pool) {
    extern __shared__ char smem[];
    const int tid = threadIdx.x;
    const int w = tid >> 5, lid = tid & 31;
    const int wr = w >> 2, wc = w & 3;          // warp grid 2x4 over 128x128
    const int row0 = blockIdx.y * 128, col0 = blockIdx.x * 128;
    const uint32_t sbase = (uint32_t)__cvta_generic_to_shared(smem);

    const int TILE = 128 * RS;                   // 10240 B per plane
    const int STAGE = 4 * TILE;                  // AsHi | AsLo | BsHi | BsLo

    float acc[4][4][4] = {};

    const int nc = MK >> 5;               // chunks of 32

    const int lr = tid >> 1;              // 0..127
    const int lhalf = tid & 1;            // 0/1 (32B halves of the 64B row)

    auto issue_chunk = [&](int ci, int s) {
        const int k0 = ci << 5;
        const uint32_t st = sbase + s * STAGE;
        const uint32_t dstA = st + lr * RS + lhalf * 32;
        int gr = row0 + lr;
        int sz = (gr < Nr) ? 16 : 0;
        const __nv_bfloat16* sh = aHi + (size_t)(gr < Nr ? gr : 0) * MK + k0 + lhalf * 16;
        const __nv_bfloat16* sl = aLo + (size_t)(gr < Nr ? gr : 0) * MK + k0 + lhalf * 16;
        CP16(dstA,              sh,     sz);
        CP16(dstA + 16,         sh + 8, sz);
        CP16(dstA + TILE,       sl,     sz);
        CP16(dstA + TILE + 16,  sl + 8, sz);
        int n = col0 + lr;   // padded rows always valid
        const __nv_bfloat16* bh = wHi + (size_t)n * MK + k0 + lhalf * 16;
        const __nv_bfloat16* bl = wLo + (size_t)n * MK + k0 + lhalf * 16;
        const uint32_t dstB = st + 2 * TILE + lr * RS + lhalf * 32;
        CP16(dstB,              bh,     16);
        CP16(dstB + 16,         bh + 8, 16);
        CP16(dstB + TILE,       bl,     16);
        CP16(dstB + TILE + 16,  bl + 8, 16);
        asm volatile("cp.async.commit_group;" ::: "memory");
    };

    auto compute = [&](int s) {
        const uint32_t aHiB = sbase + s * STAGE;
        const uint32_t aLoB = aHiB + TILE;
        const uint32_t bHiB = aHiB + 2 * TILE;
        const uint32_t bLoB = aHiB + 3 * TILE;
        const int sub = lid & 7;
        const int g1 = (lid >> 3) & 1;
        const int g2 = (lid >> 4) & 1;
        #pragma unroll
        for (int ks = 0; ks < 2; ks++) {
            uint32_t bh[2][4], bl[2][4];
            #pragma unroll
            for (int np = 0; np < 2; np++) {
                uint32_t r = wc * 32 + np * 16 + g2 * 8 + sub;
                uint32_t off = r * RS + (ks * 2 + g1) * 16;
                LDSM_X4(bh[np], bHiB + off);
                LDSM_X4(bl[np], bLoB + off);
            }
            {
                uint32_t af[4][4];
                #pragma unroll
                for (int mt = 0; mt < 4; mt++) {
                    uint32_t r = wr * 64 + mt * 16 + g1 * 8 + sub;
                    uint32_t off = r * RS + (ks * 2 + g2) * 16;
                    LDSM_X4(af[mt], aHiB + off);
                }
                #pragma unroll
                for (int mt = 0; mt < 4; mt++)
                    #pragma unroll
                    for (int nt = 0; nt < 4; nt++) {
                        const uint32_t* BH = &bh[nt >> 1][(nt & 1) * 2];
                        const uint32_t* BL = &bl[nt >> 1][(nt & 1) * 2];
                        MMA_BF16(acc[mt][nt], af[mt], BH[0], BH[1]);
                        MMA_BF16(acc[mt][nt], af[mt], BL[0], BL[1]);
                    }
                #pragma unroll
                for (int mt = 0; mt < 4; mt++) {
                    uint32_t r = wr * 64 + mt * 16 + g1 * 8 + sub;
                    uint32_t off = r * RS + (ks * 2 + g2) * 16;
                    LDSM_X4(af[mt], aLoB + off);
                }
                #pragma unroll
                for (int mt = 0; mt < 4; mt++)
                    #pragma unroll
                    for (int nt = 0; nt < 4; nt++) {
                        const uint32_t* BH = &bh[nt >> 1][(nt & 1) * 2];
                        MMA_BF16(acc[mt][nt], af[mt], BH[0], BH[1]);
                    }
            }
        }
    };

    // ---- mainloop: 2-stage cp.async pipeline (R7) ----
    issue_chunk(0, 0);
    if (nc > 1) issue_chunk(1, 1);
    for (int ci = 0; ci < nc; ci++) {
        int s = ci & 1;
        if (ci < nc - 1) {
            asm volatile("cp.async.wait_group 1;" ::: "memory");
        } else {
            asm volatile("cp.async.wait_group 0;" ::: "memory");
        }
        __syncthreads();
        compute(s);
        __syncthreads();
        if (ci + 2 < nc) issue_chunk(ci + 2, s);
    }

    // ---- epilogue (pool path uses warp-reduced atomics; batch is sorted) ----
    const int g = lid >> 2, tg = lid & 3;
    #pragma unroll
    for (int mt = 0; mt < 4; mt++) {
        const int ra = row0 + wr * 64 + mt * 16 + g;   // row A (g in 0..7)
        const int rb = ra + 8;                          // row B
        int ba = 0, bb = 0;
        bool grp_uniform = false;
        if (pool != nullptr) {
            ba = __ldg(&batch[ra < Nr ? ra : (Nr - 1)]);
            bb = __ldg(&batch[rb < Nr ? rb : (Nr - 1)]);
            int bmin = min(ba, bb), bmax = max(ba, bb);
            #pragma unroll
            for (int msk = 4; msk <= 16; msk <<= 1) {
                bmin = min(bmin, __shfl_xor_sync(0xffffffffu, bmin, msk));
                bmax = max(bmax, __shfl_xor_sync(0xffffffffu, bmax, msk));
            }
            grp_uniform = (bmin == bmax);
        }
        #pragma unroll
        for (int nt = 0; nt < 4; nt++) {
            int col = col0 + wc * 32 + nt * 8 + 2 * tg;
            if (col >= Kout) continue;   // warp-uniform (tiles are 8-col aligned)
            float bs0 = __ldg(&bias[col]);
            float bs1 = __ldg(&bias[col + 1]);
            float a0 = acc[mt][nt][0] + bs0, a1 = acc[mt][nt][1] + bs1;
            float b0 = acc[mt][nt][2] + bs0, b1 = acc[mt][nt][3] + bs1;
            if (relu) {
                a0 = fmaxf(a0, 0.f); a1 = fmaxf(a1, 0.f);
                b0 = fmaxf(b0, 0.f); b1 = fmaxf(b1, 0.f);
            }
            if (ra < Nr) {
                *(float2*)&C[(size_t)ra * Kout + col] = make_float2(a0, a1);
                if (amvo_out != nullptr) {
                    float2 m = *(const float2*)&mu_in[(size_t)ra * Kout + col];
                    float2 e = *(const float2*)&eps_in[(size_t)ra * Kout + col];
                    float2 o;
                    o.x = fmaf(e.x, __expf(0.5f * a0), m.x);
                    o.y = fmaf(e.y, __expf(0.5f * a1), m.y);
                    *(float2*)&amvo_out[(size_t)ra * Kout + col] = o;
                }
            }
            if (rb < Nr) {
                *(float2*)&C[(size_t)rb * Kout + col] = make_float2(b0, b1);
                if (amvo_out != nullptr) {
                    float2 m = *(const float2*)&mu_in[(size_t)rb * Kout + col];
                    float2 e = *(const float2*)&eps_in[(size_t)rb * Kout + col];
                    float2 o;
                    o.x = fmaf(e.x, __expf(0.5f * b0), m.x);
                    o.y = fmaf(e.y, __expf(0.5f * b1), m.y);
                    *(float2*)&amvo_out[(size_t)rb * Kout + col] = o;
                }
            }
            if (pool != nullptr) {
                float va0 = (ra < Nr) ? a0 : 0.f, va1 = (ra < Nr) ? a1 : 0.f;
                float vb0 = (rb < Nr) ? b0 : 0.f, vb1 = (rb < Nr) ? b1 : 0.f;
                if (grp_uniform) {
                    float m0 = fmaxf(va0, vb0), m1 = fmaxf(va1, vb1);
                    #pragma unroll
                    for (int msk = 4; msk <= 16; msk <<= 1) {
                        m0 = fmaxf(m0, __shfl_xor_sync(0xffffffffu, m0, msk));
                        m1 = fmaxf(m1, __shfl_xor_sync(0xffffffffu, m1, msk));
                    }
                    if (g == 0) {
                        atomicMax((int*)&pool[(size_t)ba * Kout + col],     __float_as_int(m0));
                        atomicMax((int*)&pool[(size_t)ba * Kout + col + 1], __float_as_int(m1));
                    }
                } else {
                    if (ra < Nr) {
                        atomicMax((int*)&pool[(size_t)ba * Kout + col],     __float_as_int(a0));
                        atomicMax((int*)&pool[(size_t)ba * Kout + col + 1], __float_as_int(a1));
                    }
                    if (rb < Nr) {
                        atomicMax((int*)&pool[(size_t)bb * Kout + col],     __float_as_int(b0));
                        atomicMax((int*)&pool[(size_t)bb * Kout + col + 1], __float_as_int(b1));
                    }
                }
            }
        }
    }
}

// ---------------- fp32 SGEMM for the tiny FC head ----------------
__global__ __launch_bounds__(256) void sgemm_bias_kernel(
    const float* __restrict__ A, const float* __restrict__ W,
    const float* __restrict__ bias, float* __restrict__ C,
    int Nr, int M, int K, int relu) {
    const int BM = 128, BN = 64, BK = 16, TM = 8, TN = 4;
    __shared__ float As[BK][BM + 4];
    __shared__ float Bs[BK][BN];
    int row0 = blockIdx.y * BM;
    int col0 = blockIdx.x * BN;
    int tid = threadIdx.x;
    int tr = (tid / 16) * TM;
    int tc = (tid % 16) * TN;
    float acc[TM][TN] = {};

    for (int k0 = 0; k0 < M; k0 += BK) {
        #pragma unroll
        for (int l = tid; l < (BM * BK) / 4; l += 256) {
            int r = l >> 2;
            int m4 = (l & 3) << 2;
            float4 v = make_float4(0.f, 0.f, 0.f, 0.f);
            int gr = row0 + r;
            if (gr < Nr) v = *(const float4*)&A[(size_t)gr * M + k0 + m4];
            As[m4 + 0][r] = v.x;
            As[m4 + 1][r] = v.y;
            As[m4 + 2][r] = v.z;
            As[m4 + 3][r] = v.w;
        }
        {
            int m = tid >> 4;
            int c4 = (tid & 15) << 2;
            float4 v = *(const float4*)&W[(size_t)(k0 + m) * K + col0 + c4];
            *(float4*)&Bs[m][c4] = v;
        }
        __syncthreads();
        #pragma unroll
        for (int kk = 0; kk < BK; kk++) {
            float a[TM], b[TN];
            #pragma unroll
            for (int i = 0; i < TM; i++) a[i] = As[kk][tr + i];
            #pragma unroll
            for (int j = 0; j < TN; j++) b[j] = Bs[kk][tc + j];
            #pragma unroll
            for (int i = 0; i < TM; i++)
                #pragma unroll
                for (int j = 0; j < TN; j++)
                    acc[i][j] = fmaf(a[i], b[j], acc[i][j]);
        }
        __syncthreads();
    }

    #pragma unroll
    for (int i = 0; i < TM; i++) {
        int gr = row0 + tr + i;
        if (gr >= Nr) continue;
        #pragma unroll
        for (int j = 0; j < TN; j++) {
            int gc = col0 + tc + j;
            float v = acc[i][j] + bias[gc];
            if (relu) v = fmaxf(v, 0.0f);
            C[(size_t)gr * K + gc] = v;
        }
    }
}

// ---------------- launch orchestration ----------------
static inline void run_aggregate(const float* h, const float* dinv,
                                 const int* rowptr, const int* esrc,
                                 __nv_bfloat16* aggHi, __nv_bfloat16* aggLo, int F) {
    int blocks = (NN * 32 + 255) / 256;
    switch (F) {
        case 64:  gather_row_kernel<2><<<blocks, 256>>>(h, dinv, rowptr, esrc, aggHi, aggLo, NN, F); break;
        case 128: gather_row_kernel<4><<<blocks, 256>>>(h, dinv, rowptr, esrc, aggHi, aggLo, NN, F); break;
        case 192: gather_row_kernel<6><<<blocks, 256>>>(h, dinv, rowptr, esrc, aggHi, aggLo, NN, F); break;
        default:  gather_row_kernel<8><<<blocks, 256>>>(h, dinv, rowptr, esrc, aggHi, aggLo, NN, F); break;
    }
}

static inline void run_gemm_mma(const __nv_bfloat16* aHi, const __nv_bfloat16* aLo,
                                const __nv_bfloat16* wHi, const __nv_bfloat16* wLo,
                                const float* bias,
                                float* C, int Nr, int MK, int Kout, int relu,
                                const float* mu_in = nullptr,
                                const float* eps_in = nullptr,
                                float* amvo_out = nullptr,
                                const int* batch = nullptr,
                                float* pool = nullptr) {
    int gx = (Kout + 127) / 128;
    const int SMEM = 2 * 4 * 128 * RS;   // 81920 (R7-proven)
    cudaFuncSetAttribute(gemm_mma_kernel,
                         cudaFuncAttributeMaxDynamicSharedMemorySize, SMEM);
    dim3 grid(gx, (Nr + 127) / 128);
    gemm_mma_kernel<<<grid, 256, SMEM>>>(aHi, aLo, wHi, wLo, bias, C, Nr, MK, Kout,
                                         relu, mu_in, eps_in, amvo_out, batch, pool);
}

extern "C" void kernel_launch(void* const* d_in, const int* in_sizes, int n_in,
                              void* d_out, int out_size) {
    const float* x     = (const float*)d_in[0];
    const int*   ei    = (const int*)d_in[1];
    const int*   batch = (const int*)d_in[2];
    const float* eps   = (const float*)d_in[3];
    const float* W1 = (const float*)d_in[4];  const float* b1 = (const float*)d_in[5];
    const float* W2 = (const float*)d_in[6];  const float* b2 = (const float*)d_in[7];
    const float* W3 = (const float*)d_in[8];  const float* b3 = (const float*)d_in[9];
    const float* Wmu = (const float*)d_in[10]; const float* bmu = (const float*)d_in[11];
    const float* Wlv = (const float*)d_in[12]; const float* blv = (const float*)d_in[13];
    const float* fc1w = (const float*)d_in[14]; const float* fc1b = (const float*)d_in[15];
    const float* fc2w = (const float*)d_in[16]; const float* fc2b = (const float*)d_in[17];

    float* out = (float*)d_out;
    float* out_amvo = out;
    float* out_mu   = out + (size_t)NN * 256;
    float* out_lv   = out + 2 * (size_t)NN * 256;
    float* out_pmvo = out + 3 * (size_t)NN * 256;

    float *dinv, *bufB, *x2, *hidden;
    int *cnt, *rowptr, *cursor, *esrc, *bsums;
    __nv_bfloat16 *aggHi, *aggLo, *wtHi, *wtLo;
    cudaGetSymbolAddress((void**)&dinv, g_dinv);
    cudaGetSymbolAddress((void**)&cnt, g_cnt);
    cudaGetSymbolAddress((void**)&rowptr, g_rowptr);
    cudaGetSymbolAddress((void**)&cursor, g_cursor);
    cudaGetSymbolAddress((void**)&esrc, g_esrc);
    cudaGetSymbolAddress((void**)&bsums, g_bsums);
    cudaGetSymbolAddress((void**)&aggHi, g_aggHi);
    cudaGetSymbolAddress((void**)&aggLo, g_aggLo);
    cudaGetSymbolAddress((void**)&bufB, g_bufB);
    cudaGetSymbolAddress((void**)&x2, g_x2);
    cudaGetSymbolAddress((void**)&hidden, g_hidden);
    cudaGetSymbolAddress((void**)&wtHi, g_wt_hi);
    cudaGetSymbolAddress((void**)&wtLo, g_wt_lo);

    const int* erow = ei;
    const int* ecol = ei + EE;

    const int SCAN_BLOCKS = (NN + 1023) / 1024;   // 98

    // zero scratch via memset nodes (graph-capturable)
    cudaMemsetAsync(cnt, 0, NN * sizeof(int));
    cudaMemsetAsync(x2, 0, BB * 256 * sizeof(float));

    // all weight pre-splits up front (dedicated buffers, padded to 128-col mult)
    wsplit_kernel<<<(128 * 64  + 255) / 256, 256>>>(W1,  wtHi + WOFF_L1, wtLo + WOFF_L1, 64,  128, 128);
    wsplit_kernel<<<(256 * 128 + 255) / 256, 256>>>(W2,  wtHi + WOFF_L2, wtLo + WOFF_L2, 128, 192, 256);
    wsplit_kernel<<<(256 * 192 + 255) / 256, 256>>>(W3,  wtHi + WOFF_L3, wtLo + WOFF_L3, 192, 256, 256);
    wsplit_kernel<<<(256 * 256 + 255) / 256, 256>>>(Wmu, wtHi + WOFF_MU, wtLo + WOFF_MU, 256, 256, 256);
    wsplit_kernel<<<(256 * 256 + 255) / 256, 256>>>(Wlv, wtHi + WOFF_LV, wtLo + WOFF_LV, 256, 256, 256);

    // CSR build + normalization (dinv fused into scan_final)
    count_kernel<<<(EE + 255) / 256, 256>>>(ecol, cnt, EE);
    block_reduce_kernel<<<SCAN_BLOCKS, 1024>>>(cnt, bsums, NN);
    scan_bsums_kernel<<<1, 128>>>(bsums, SCAN_BLOCKS);
    scan_final_kernel<<<SCAN_BLOCKS, 1024>>>(cnt, bsums, rowptr, cursor, dinv, NN);
    fill_kernel<<<(EE + 255) / 256, 256>>>(erow, ecol, cursor, esrc, EE);

    // layer 1: aggregate(x,64) -> gemm 64->128 +relu
    run_aggregate(x, dinv, rowptr, esrc, aggHi, aggLo, 64);
    run_gemm_mma(aggHi, aggLo, wtHi + WOFF_L1, wtLo + WOFF_L1, b1, bufB, NN, 64, 128, 1);

    // layer 2: aggregate(h1,128) -> gemm 128->192 +relu
    run_aggregate(bufB, dinv, rowptr, esrc, aggHi, aggLo, 128);
    run_gemm_mma(aggHi, aggLo, wtHi + WOFF_L2, wtLo + WOFF_L2, b2, bufB, NN, 128, 192, 1);

    // layer 3: aggregate(h2,192) -> gemm 192->256 +relu, fused segment-max pool
    run_aggregate(bufB, dinv, rowptr, esrc, aggHi, aggLo, 192);
    run_gemm_mma(aggHi, aggLo, wtHi + WOFF_L3, wtLo + WOFF_L3, b3, bufB, NN, 192, 256, 1,
                 nullptr, nullptr, nullptr, batch, x2);

    // shared aggregation for mu / logvar heads
    run_aggregate(bufB, dinv, rowptr, esrc, aggHi, aggLo, 256);
    run_gemm_mma(aggHi, aggLo, wtHi + WOFF_MU, wtLo + WOFF_MU, bmu, out_mu, NN, 256, 256, 0);
    run_gemm_mma(aggHi, aggLo, wtHi + WOFF_LV, wtLo + WOFF_LV, blv, out_lv, NN, 256, 256, 0,
                 out_mu, eps, out_amvo);

    // MLP head on pooled features (tiny, fp32)
    {
        dim3 g1(1024 / 64, (BB + 127) / 128);
        sgemm_bias_kernel<<<g1, 256>>>(x2, fc1w, fc1b, hidden, BB, 256, 1024, 1);
        dim3 g2(128 / 64, (BB + 127) / 128);
        sgemm_bias_kernel<<<g2, 256>>>(hidden, fc2w, fc2b, out_pmvo, BB, 1024, 128, 0);
    }
}

// round 13
// speedup vs baseline: 1.3403x; 1.0583x over previous
#include <cuda_runtime.h>
#include <cuda_bf16.h>
#include <math.h>
#include <stdint.h>

#define NN 100000
#define EE 400000
#define BB 512

// ---------------- scratch (no allocations allowed) ----------------
__device__ float g_dinv[NN];
__device__ int   g_cnt[NN];
__device__ int   g_rowptr[NN + 1];
__device__ int   g_cursor[NN];
__device__ int   g_esrc[EE];
__device__ int   g_bsums[128];
__device__ __nv_bfloat16 g_aggHi[(size_t)NN * 256];  // aggregated A, high bf16
__device__ __nv_bfloat16 g_aggLo[(size_t)NN * 256];  // aggregated A, low  bf16
__device__ float g_bufB[(size_t)NN * 256];           // post-GEMM features (fp32)
__device__ float g_x2[BB * 256];                     // pooled max
__device__ float g_hidden[BB * 1024];                // fc1 output
// per-layer W^T split buffers (hi/lo planes), padded to 128-col multiples
#define WT_TOTAL (8192 + 32768 + 49152 + 65536 + 65536)
__device__ __nv_bfloat16 g_wt_hi[WT_TOTAL];
__device__ __nv_bfloat16 g_wt_lo[WT_TOTAL];
#define WOFF_L1 0
#define WOFF_L2 8192
#define WOFF_L3 40960
#define WOFF_MU 90112
#define WOFF_LV 155648
// FC head buffers (bf16 path)
__device__ __nv_bfloat16 g_wtfc1_hi[1024 * 256];
__device__ __nv_bfloat16 g_wtfc1_lo[1024 * 256];
__device__ __nv_bfloat16 g_wtfc2_hi[128 * 1024];
__device__ __nv_bfloat16 g_wtfc2_lo[128 * 1024];
__device__ __nv_bfloat16 g_x2hi[BB * 256];
__device__ __nv_bfloat16 g_x2lo[BB * 256];
__device__ __nv_bfloat16 g_hidhi[BB * 1024];
__device__ __nv_bfloat16 g_hidlo[BB * 1024];

// ---------------- CSR construction ----------------
__global__ void count_kernel(const int* __restrict__ col, int* cnt, int e) {
    int i = blockIdx.x * blockDim.x + threadIdx.x;
    if (i < e) atomicAdd(&cnt[col[i]], 1);
}

__global__ void block_reduce_kernel(const int* __restrict__ cnt, int* bsums, int n) {
    __shared__ int wsum[32];
    int idx = blockIdx.x * 1024 + threadIdx.x;
    int lane = threadIdx.x & 31, wid = threadIdx.x >> 5;
    int v = (idx < n) ? cnt[idx] : 0;
    #pragma unroll
    for (int s = 16; s; s >>= 1) v += __shfl_down_sync(0xffffffffu, v, s);
    if (lane == 0) wsum[wid] = v;
    __syncthreads();
    if (wid == 0) {
        int t = wsum[lane];
        #pragma unroll
        for (int s = 16; s; s >>= 1) t += __shfl_down_sync(0xffffffffu, t, s);
        if (lane == 0) bsums[blockIdx.x] = t;
    }
}

__global__ void scan_bsums_kernel(int* bsums, int nb) {
    __shared__ int ws[4];
    int tid = threadIdx.x;
    int lane = tid & 31, wid = tid >> 5;
    int v = (tid < nb) ? bsums[tid] : 0;
    int incl = v;
    #pragma unroll
    for (int s = 1; s < 32; s <<= 1) {
        int t = __shfl_up_sync(0xffffffffu, incl, s);
        if (lane >= s) incl += t;
    }
    if (lane == 31) ws[wid] = incl;
    __syncthreads();
    if (tid == 0) {
        int a = 0;
        #pragma unroll
        for (int i = 0; i < 4; i++) { int t = ws[i]; ws[i] = a; a += t; }
    }
    __syncthreads();
    if (tid < nb) bsums[tid] = incl - v + ws[wid];
}

// also computes dinv (fused to save a launch)
__global__ void scan_final_kernel(const int* __restrict__ cnt, const int* __restrict__ boff,
                                  int* rowptr, int* cursor, float* dinv, int n) {
    __shared__ int wsum[32];
    int idx = blockIdx.x * 1024 + threadIdx.x;
    int lane = threadIdx.x & 31, wid = threadIdx.x >> 5;
    int v = (idx < n) ? cnt[idx] : 0;
    int incl = v;
    #pragma unroll
    for (int s = 1; s < 32; s <<= 1) {
        int t = __shfl_up_sync(0xffffffffu, incl, s);
        if (lane >= s) incl += t;
    }
    if (lane == 31) wsum[wid] = incl;
    __syncthreads();
    if (wid == 0) {
        int w = wsum[lane];
        int wi = w;
        #pragma unroll
        for (int s = 1; s < 32; s <<= 1) {
            int t = __shfl_up_sync(0xffffffffu, wi, s);
            if (lane >= s) wi += t;
        }
        wsum[lane] = wi - w;
    }
    __syncthreads();
    int excl = incl - v + wsum[wid] + __ldg(&boff[blockIdx.x]);
    if (idx < n) {
        rowptr[idx] = excl;
        cursor[idx] = excl;
        dinv[idx] = rsqrtf(1.0f + (float)v);   // +1 self-loop
        if (idx == n - 1) rowptr[n] = excl + v;
    }
}

__global__ void fill_kernel(const int* __restrict__ erow, const int* __restrict__ ecol,
                            int* cursor, int* esrc, int e) {
    int i = blockIdx.x * blockDim.x + threadIdx.x;
    if (i < e) {
        int pos = atomicAdd(&cursor[ecol[i]], 1);
        esrc[pos] = erow[i];
    }
}

// ---------------- gather aggregation: warp-per-node, COALESCED columns --------
// Lane owns strided columns c = j*32 + lane  ->  every load instruction covers
// one contiguous 128 B line (1 L1tex wavefront).
template <int COLS>   // COLS = F/32 floats per lane
__global__ void gather_row_kernel(const float* __restrict__ h,
                                  const float* __restrict__ dinv,
                                  const int* __restrict__ rowptr,
                                  const int* __restrict__ esrc,
                                  __nv_bfloat16* __restrict__ aggHi,
                                  __nv_bfloat16* __restrict__ aggLo,
                                  int n, int F) {
    int node = (blockIdx.x * blockDim.x + threadIdx.x) >> 5;
    int lane = threadIdx.x & 31;
    if (node >= n) return;
    float dn = __ldg(&dinv[node]);
    float sum[COLS];
    {
        const float* r = h + (size_t)node * F + lane;
        #pragma unroll
        for (int j = 0; j < COLS; j++) sum[j] = dn * __ldg(&r[j * 32]);
    }
    int s = __ldg(&rowptr[node]);
    int e = __ldg(&rowptr[node + 1]);
    int i = s;
    for (; i + 3 < e; i += 4) {
        int s0 = __ldg(&esrc[i]);
        int s1 = __ldg(&esrc[i + 1]);
        int s2 = __ldg(&esrc[i + 2]);
        int s3 = __ldg(&esrc[i + 3]);
        float d0 = __ldg(&dinv[s0]);
        float d1 = __ldg(&dinv[s1]);
        float d2 = __ldg(&dinv[s2]);
        float d3 = __ldg(&dinv[s3]);
        const float* r0 = h + (size_t)s0 * F + lane;
        const float* r1 = h + (size_t)s1 * F + lane;
        const float* r2 = h + (size_t)s2 * F + lane;
        const float* r3 = h + (size_t)s3 * F + lane;
        #pragma unroll
        for (int j = 0; j < COLS; j++) sum[j] += d0 * __ldg(&r0[j * 32]);
        #pragma unroll
        for (int j = 0; j < COLS; j++) sum[j] += d1 * __ldg(&r1[j * 32]);
        #pragma unroll
        for (int j = 0; j < COLS; j++) sum[j] += d2 * __ldg(&r2[j * 32]);
        #pragma unroll
        for (int j = 0; j < COLS; j++) sum[j] += d3 * __ldg(&r3[j * 32]);
    }
    for (; i < e; i++) {
        int s0 = __ldg(&esrc[i]);
        float d0 = __ldg(&dinv[s0]);
        const float* r0 = h + (size_t)s0 * F + lane;
        #pragma unroll
        for (int j = 0; j < COLS; j++) sum[j] += d0 * __ldg(&r0[j * 32]);
    }
    __nv_bfloat16* oh = aggHi + (size_t)node * F + lane;
    __nv_bfloat16* ol = aggLo + (size_t)node * F + lane;
    #pragma unroll
    for (int j = 0; j < COLS; j++) {
        float v = dn * sum[j];
        __nv_bfloat16 hb = __float2bfloat16_rn(v);
        oh[j * 32] = hb;
        ol[j * 32] = __float2bfloat16_rn(v - __bfloat162float(hb));
    }
}

// ---------------- weight pre-split (tiled transpose, coalesced both ways) -----
// W[MK,N] -> Wt_{hi,lo}[Npad,MK]
__global__ void wsplit_kernel(const float* __restrict__ W,
                              __nv_bfloat16* __restrict__ whi,
                              __nv_bfloat16* __restrict__ wlo,
                              int MK, int N, int Npad) {
    __shared__ float t[32][33];
    const int kb = blockIdx.x * 32, nb = blockIdx.y * 32;
    const int tx = threadIdx.x & 31, ty = threadIdx.x >> 5;   // 256 thr: ty 0..7
    #pragma unroll
    for (int r = 0; r < 4; r++) {
        int k = kb + ty + 8 * r;
        int n = nb + tx;
        float v = (k < MK && n < N) ? W[(size_t)k * N + n] : 0.0f;
        t[ty + 8 * r][tx] = v;
    }
    __syncthreads();
    #pragma unroll
    for (int r = 0; r < 4; r++) {
        int n = nb + ty + 8 * r;
        int k = kb + tx;
        if (n < Npad && k < MK) {
            float v = t[tx][ty + 8 * r];
            __nv_bfloat16 h = __float2bfloat16_rn(v);
            whi[(size_t)n * MK + k] = h;
            wlo[(size_t)n * MK + k] = __float2bfloat16_rn(v - __bfloat162float(h));
        }
    }
}

// ---------------- elementwise fp32 -> bf16 hi/lo split ----------------
__global__ void split_f32_kernel(const float* __restrict__ src,
                                 __nv_bfloat16* __restrict__ hi,
                                 __nv_bfloat16* __restrict__ lo, int n) {
    int i = blockIdx.x * blockDim.x + threadIdx.x;
    if (i < n) {
        float v = src[i];
        __nv_bfloat16 h = __float2bfloat16_rn(v);
        hi[i] = h;
        lo[i] = __float2bfloat16_rn(v - __bfloat162float(h));
    }
}

// ---------------- bf16x3 tensor-core GEMM with cp.async (R7-proven shape) -----
// 128x128 CTA tile, 2x4 warp grid, 2-stage pipeline, 80 KB smem.
// Tiles stored with 80-byte row stride: (addr/16) mod 8 = (5r+c) mod 8 bijective
// over 8 consecutive rows -> conflict-free ldmatrix. 16B-aligned (80 = 5*16).
#define RS 80

#define LDSM_X4(R, ADDR) \
    asm volatile("ldmatrix.sync.aligned.m8n8.x4.shared.b16 {%0,%1,%2,%3}, [%4];" \
        : "=r"((R)[0]), "=r"((R)[1]), "=r"((R)[2]), "=r"((R)[3]) : "r"(ADDR))

#define MMA_BF16(CC, AA, B0, B1) \
    asm volatile("mma.sync.aligned.m16n8k16.row.col.f32.bf16.bf16.f32 " \
        "{%0,%1,%2,%3}, {%4,%5,%6,%7}, {%8,%9}, {%0,%1,%2,%3};" \
        : "+f"((CC)[0]), "+f"((CC)[1]), "+f"((CC)[2]), "+f"((CC)[3]) \
        : "r"((AA)[0]), "r"((AA)[1]), "r"((AA)[2]), "r"((AA)[3]), \
          "r"(B0), "r"(B1))

#define CP16(DST, SRC, SZ) \
    asm volatile("cp.async.ca.shared.global [%0], [%1], 16, %2;" \
        :: "r"(DST), "l"(SRC), "r"(SZ) : "memory")

__global__ void __launch_bounds__(256)
gemm_mma_kernel(const __nv_bfloat16* __restrict__ aHi,
                const __nv_bfloat16* __restrict__ aLo,
                const __nv_bfloat16* __restrict__ wHi,
                const __nv_bfloat16* __restrict__ wLo,
                const float* __restrict__ bias,
                float* __restrict__ C, int Nr, int MK, int Kout, int relu,
                const float* __restrict__ mu_in, const float* __restrict__ eps_in,
                float* __restrict__ amvo_out,
                const int* __restrict__ batch, float* __restrict__ pool) {
    extern __shared__ char smem[];
    const int tid = threadIdx.x;
    const int w = tid >> 5, lid = tid & 31;
    const int wr = w >> 2, wc = w & 3;          // warp grid 2x4 over 128x128
    const int row0 = blockIdx.y * 128, col0 = blockIdx.x * 128;
    const uint32_t sbase = (uint32_t)__cvta_generic_to_shared(smem);

    const int TILE = 128 * RS;                   // 10240 B per plane
    const int STAGE = 4 * TILE;                  // AsHi | AsLo | BsHi | BsLo

    float acc[4][4][4] = {};

    const int nc = MK >> 5;               // chunks of 32

    const int lr = tid >> 1;              // 0..127
    const int lhalf = tid & 1;            // 0/1 (32B halves of the 64B row)

    auto issue_chunk = [&](int ci, int s) {
        const int k0 = ci << 5;
        const uint32_t st = sbase + s * STAGE;
        const uint32_t dstA = st + lr * RS + lhalf * 32;
        int gr = row0 + lr;
        int sz = (gr < Nr) ? 16 : 0;
        const __nv_bfloat16* sh = aHi + (size_t)(gr < Nr ? gr : 0) * MK + k0 + lhalf * 16;
        const __nv_bfloat16* sl = aLo + (size_t)(gr < Nr ? gr : 0) * MK + k0 + lhalf * 16;
        CP16(dstA,              sh,     sz);
        CP16(dstA + 16,         sh + 8, sz);
        CP16(dstA + TILE,       sl,     sz);
        CP16(dstA + TILE + 16,  sl + 8, sz);
        int n = col0 + lr;   // padded rows always valid
        const __nv_bfloat16* bh = wHi + (size_t)n * MK + k0 + lhalf * 16;
        const __nv_bfloat16* bl = wLo + (size_t)n * MK + k0 + lhalf * 16;
        const uint32_t dstB = st + 2 * TILE + lr * RS + lhalf * 32;
        CP16(dstB,              bh,     16);
        CP16(dstB + 16,         bh + 8, 16);
        CP16(dstB + TILE,       bl,     16);
        CP16(dstB + TILE + 16,  bl + 8, 16);
        asm volatile("cp.async.commit_group;" ::: "memory");
    };

    auto compute = [&](int s) {
        const uint32_t aHiB = sbase + s * STAGE;
        const uint32_t aLoB = aHiB + TILE;
        const uint32_t bHiB = aHiB + 2 * TILE;
        const uint32_t bLoB = aHiB + 3 * TILE;
        const int sub = lid & 7;
        const int g1 = (lid >> 3) & 1;
        const int g2 = (lid >> 4) & 1;
        #pragma unroll
        for (int ks = 0; ks < 2; ks++) {
            uint32_t bh[2][4], bl[2][4];
            #pragma unroll
            for (int np = 0; np < 2; np++) {
                uint32_t r = wc * 32 + np * 16 + g2 * 8 + sub;
                uint32_t off = r * RS + (ks * 2 + g1) * 16;
                LDSM_X4(bh[np], bHiB + off);
                LDSM_X4(bl[np], bLoB + off);
            }
            {
                uint32_t af[4][4];
                #pragma unroll
                for (int mt = 0; mt < 4; mt++) {
                    uint32_t r = wr * 64 + mt * 16 + g1 * 8 + sub;
                    uint32_t off = r * RS + (ks * 2 + g2) * 16;
                    LDSM_X4(af[mt], aHiB + off);
                }
                #pragma unroll
                for (int mt = 0; mt < 4; mt++)
                    #pragma unroll
                    for (int nt = 0; nt < 4; nt++) {
                        const uint32_t* BH = &bh[nt >> 1][(nt & 1) * 2];
                        const uint32_t* BL = &bl[nt >> 1][(nt & 1) * 2];
                        MMA_BF16(acc[mt][nt], af[mt], BH[0], BH[1]);
                        MMA_BF16(acc[mt][nt], af[mt], BL[0], BL[1]);
                    }
                #pragma unroll
                for (int mt = 0; mt < 4; mt++) {
                    uint32_t r = wr * 64 + mt * 16 + g1 * 8 + sub;
                    uint32_t off = r * RS + (ks * 2 + g2) * 16;
                    LDSM_X4(af[mt], aLoB + off);
                }
                #pragma unroll
                for (int mt = 0; mt < 4; mt++)
                    #pragma unroll
                    for (int nt = 0; nt < 4; nt++) {
                        const uint32_t* BH = &bh[nt >> 1][(nt & 1) * 2];
                        MMA_BF16(acc[mt][nt], af[mt], BH[0], BH[1]);
                    }
            }
        }
    };

    // ---- mainloop: 2-stage cp.async pipeline (R7) ----
    issue_chunk(0, 0);
    if (nc > 1) issue_chunk(1, 1);
    for (int ci = 0; ci < nc; ci++) {
        int s = ci & 1;
        if (ci < nc - 1) {
            asm volatile("cp.async.wait_group 1;" ::: "memory");
        } else {
            asm volatile("cp.async.wait_group 0;" ::: "memory");
        }
        __syncthreads();
        compute(s);
        __syncthreads();
        if (ci + 2 < nc) issue_chunk(ci + 2, s);
    }

    // ---- epilogue (pool path uses warp-reduced atomics; batch is sorted) ----
    const int g = lid >> 2, tg = lid & 3;
    #pragma unroll
    for (int mt = 0; mt < 4; mt++) {
        const int ra = row0 + wr * 64 + mt * 16 + g;   // row A (g in 0..7)
        const int rb = ra + 8;                          // row B
        int ba = 0, bb = 0;
        bool grp_uniform = false;
        if (pool != nullptr) {
            ba = __ldg(&batch[ra < Nr ? ra : (Nr - 1)]);
            bb = __ldg(&batch[rb < Nr ? rb : (Nr - 1)]);
            int bmin = min(ba, bb), bmax = max(ba, bb);
            #pragma unroll
            for (int msk = 4; msk <= 16; msk <<= 1) {
                bmin = min(bmin, __shfl_xor_sync(0xffffffffu, bmin, msk));
                bmax = max(bmax, __shfl_xor_sync(0xffffffffu, bmax, msk));
            }
            grp_uniform = (bmin == bmax);
        }
        #pragma unroll
        for (int nt = 0; nt < 4; nt++) {
            int col = col0 + wc * 32 + nt * 8 + 2 * tg;
            if (col >= Kout) continue;   // warp-uniform (tiles are 8-col aligned)
            float bs0 = __ldg(&bias[col]);
            float bs1 = __ldg(&bias[col + 1]);
            float a0 = acc[mt][nt][0] + bs0, a1 = acc[mt][nt][1] + bs1;
            float b0 = acc[mt][nt][2] + bs0, b1 = acc[mt][nt][3] + bs1;
            if (relu) {
                a0 = fmaxf(a0, 0.f); a1 = fmaxf(a1, 0.f);
                b0 = fmaxf(b0, 0.f); b1 = fmaxf(b1, 0.f);
            }
            if (ra < Nr) {
                *(float2*)&C[(size_t)ra * Kout + col] = make_float2(a0, a1);
                if (amvo_out != nullptr) {
                    float2 m = *(const float2*)&mu_in[(size_t)ra * Kout + col];
                    float2 e = *(const float2*)&eps_in[(size_t)ra * Kout + col];
                    float2 o;
                    o.x = fmaf(e.x, __expf(0.5f * a0), m.x);
                    o.y = fmaf(e.y, __expf(0.5f * a1), m.y);
                    *(float2*)&amvo_out[(size_t)ra * Kout + col] = o;
                }
            }
            if (rb < Nr) {
                *(float2*)&C[(size_t)rb * Kout + col] = make_float2(b0, b1);
                if (amvo_out != nullptr) {
                    float2 m = *(const float2*)&mu_in[(size_t)rb * Kout + col];
                    float2 e = *(const float2*)&eps_in[(size_t)rb * Kout + col];
                    float2 o;
                    o.x = fmaf(e.x, __expf(0.5f * b0), m.x);
                    o.y = fmaf(e.y, __expf(0.5f * b1), m.y);
                    *(float2*)&amvo_out[(size_t)rb * Kout + col] = o;
                }
            }
            if (pool != nullptr) {
                float va0 = (ra < Nr) ? a0 : 0.f, va1 = (ra < Nr) ? a1 : 0.f;
                float vb0 = (rb < Nr) ? b0 : 0.f, vb1 = (rb < Nr) ? b1 : 0.f;
                if (grp_uniform) {
                    float m0 = fmaxf(va0, vb0), m1 = fmaxf(va1, vb1);
                    #pragma unroll
                    for (int msk = 4; msk <= 16; msk <<= 1) {
                        m0 = fmaxf(m0, __shfl_xor_sync(0xffffffffu, m0, msk));
                        m1 = fmaxf(m1, __shfl_xor_sync(0xffffffffu, m1, msk));
                    }
                    if (g == 0) {
                        atomicMax((int*)&pool[(size_t)ba * Kout + col],     __float_as_int(m0));
                        atomicMax((int*)&pool[(size_t)ba * Kout + col + 1], __float_as_int(m1));
                    }
                } else {
                    if (ra < Nr) {
                        atomicMax((int*)&pool[(size_t)ba * Kout + col],     __float_as_int(a0));
                        atomicMax((int*)&pool[(size_t)ba * Kout + col + 1], __float_as_int(a1));
                    }
                    if (rb < Nr) {
                        atomicMax((int*)&pool[(size_t)bb * Kout + col],     __float_as_int(b0));
                        atomicMax((int*)&pool[(size_t)bb * Kout + col + 1], __float_as_int(b1));
                    }
                }
            }
        }
    }
}

// ---------------- launch orchestration ----------------
static inline void run_aggregate(const float* h, const float* dinv,
                                 const int* rowptr, const int* esrc,
                                 __nv_bfloat16* aggHi, __nv_bfloat16* aggLo, int F) {
    int blocks = (NN * 32 + 255) / 256;
    switch (F) {
        case 64:  gather_row_kernel<2><<<blocks, 256>>>(h, dinv, rowptr, esrc, aggHi, aggLo, NN, F); break;
        case 128: gather_row_kernel<4><<<blocks, 256>>>(h, dinv, rowptr, esrc, aggHi, aggLo, NN, F); break;
        case 192: gather_row_kernel<6><<<blocks, 256>>>(h, dinv, rowptr, esrc, aggHi, aggLo, NN, F); break;
        default:  gather_row_kernel<8><<<blocks, 256>>>(h, dinv, rowptr, esrc, aggHi, aggLo, NN, F); break;
    }
}

static inline void run_gemm_mma(const __nv_bfloat16* aHi, const __nv_bfloat16* aLo,
                                const __nv_bfloat16* wHi, const __nv_bfloat16* wLo,
                                const float* bias,
                                float* C, int Nr, int MK, int Kout, int relu,
                                const float* mu_in = nullptr,
                                const float* eps_in = nullptr,
                                float* amvo_out = nullptr,
                                const int* batch = nullptr,
                                float* pool = nullptr) {
    int gx = (Kout + 127) / 128;
    const int SMEM = 2 * 4 * 128 * RS;   // 81920 (R7-proven)
    cudaFuncSetAttribute(gemm_mma_kernel,
                         cudaFuncAttributeMaxDynamicSharedMemorySize, SMEM);
    dim3 grid(gx, (Nr + 127) / 128);
    gemm_mma_kernel<<<grid, 256, SMEM>>>(aHi, aLo, wHi, wLo, bias, C, Nr, MK, Kout,
                                         relu, mu_in, eps_in, amvo_out, batch, pool);
}

static inline void run_wsplit(const float* W, __nv_bfloat16* whi, __nv_bfloat16* wlo,
                              int MK, int N, int Npad) {
    dim3 grid((MK + 31) / 32, (Npad + 31) / 32);
    wsplit_kernel<<<grid, 256>>>(W, whi, wlo, MK, N, Npad);
}

extern "C" void kernel_launch(void* const* d_in, const int* in_sizes, int n_in,
                              void* d_out, int out_size) {
    const float* x     = (const float*)d_in[0];
    const int*   ei    = (const int*)d_in[1];
    const int*   batch = (const int*)d_in[2];
    const float* eps   = (const float*)d_in[3];
    const float* W1 = (const float*)d_in[4];  const float* b1 = (const float*)d_in[5];
    const float* W2 = (const float*)d_in[6];  const float* b2 = (const float*)d_in[7];
    const float* W3 = (const float*)d_in[8];  const float* b3 = (const float*)d_in[9];
    const float* Wmu = (const float*)d_in[10]; const float* bmu = (const float*)d_in[11];
    const float* Wlv = (const float*)d_in[12]; const float* blv = (const float*)d_in[13];
    const float* fc1w = (const float*)d_in[14]; const float* fc1b = (const float*)d_in[15];
    const float* fc2w = (const float*)d_in[16]; const float* fc2b = (const float*)d_in[17];

    float* out = (float*)d_out;
    float* out_amvo = out;
    float* out_mu   = out + (size_t)NN * 256;
    float* out_lv   = out + 2 * (size_t)NN * 256;
    float* out_pmvo = out + 3 * (size_t)NN * 256;

    float *dinv, *bufB, *x2, *hidden;
    int *cnt, *rowptr, *cursor, *esrc, *bsums;
    __nv_bfloat16 *aggHi, *aggLo, *wtHi, *wtLo;
    __nv_bfloat16 *fc1hi, *fc1lo, *fc2hi, *fc2lo, *x2hi, *x2lo, *hidhi, *hidlo;
    cudaGetSymbolAddress((void**)&dinv, g_dinv);
    cudaGetSymbolAddress((void**)&cnt, g_cnt);
    cudaGetSymbolAddress((void**)&rowptr, g_rowptr);
    cudaGetSymbolAddress((void**)&cursor, g_cursor);
    cudaGetSymbolAddress((void**)&esrc, g_esrc);
    cudaGetSymbolAddress((void**)&bsums, g_bsums);
    cudaGetSymbolAddress((void**)&aggHi, g_aggHi);
    cudaGetSymbolAddress((void**)&aggLo, g_aggLo);
    cudaGetSymbolAddress((void**)&bufB, g_bufB);
    cudaGetSymbolAddress((void**)&x2, g_x2);
    cudaGetSymbolAddress((void**)&hidden, g_hidden);
    cudaGetSymbolAddress((void**)&wtHi, g_wt_hi);
    cudaGetSymbolAddress((void**)&wtLo, g_wt_lo);
    cudaGetSymbolAddress((void**)&fc1hi, g_wtfc1_hi);
    cudaGetSymbolAddress((void**)&fc1lo, g_wtfc1_lo);
    cudaGetSymbolAddress((void**)&fc2hi, g_wtfc2_hi);
    cudaGetSymbolAddress((void**)&fc2lo, g_wtfc2_lo);
    cudaGetSymbolAddress((void**)&x2hi, g_x2hi);
    cudaGetSymbolAddress((void**)&x2lo, g_x2lo);
    cudaGetSymbolAddress((void**)&hidhi, g_hidhi);
    cudaGetSymbolAddress((void**)&hidlo, g_hidlo);

    const int* erow = ei;
    const int* ecol = ei + EE;

    const int SCAN_BLOCKS = (NN + 1023) / 1024;   // 98

    // zero scratch via memset nodes (graph-capturable)
    cudaMemsetAsync(cnt, 0, NN * sizeof(int));
    cudaMemsetAsync(x2, 0, BB * 256 * sizeof(float));

    // all weight pre-splits up front (tiled transpose, coalesced)
    run_wsplit(W1,  wtHi + WOFF_L1, wtLo + WOFF_L1, 64,  128, 128);
    run_wsplit(W2,  wtHi + WOFF_L2, wtLo + WOFF_L2, 128, 192, 256);
    run_wsplit(W3,  wtHi + WOFF_L3, wtLo + WOFF_L3, 192, 256, 256);
    run_wsplit(Wmu, wtHi + WOFF_MU, wtLo + WOFF_MU, 256, 256, 256);
    run_wsplit(Wlv, wtHi + WOFF_LV, wtLo + WOFF_LV, 256, 256, 256);
    run_wsplit(fc1w, fc1hi, fc1lo, 256, 1024, 1024);
    run_wsplit(fc2w, fc2hi, fc2lo, 1024, 128, 128);

    // CSR build + normalization (dinv fused into scan_final)
    count_kernel<<<(EE + 255) / 256, 256>>>(ecol, cnt, EE);
    block_reduce_kernel<<<SCAN_BLOCKS, 1024>>>(cnt, bsums, NN);
    scan_bsums_kernel<<<1, 128>>>(bsums, SCAN_BLOCKS);
    scan_final_kernel<<<SCAN_BLOCKS, 1024>>>(cnt, bsums, rowptr, cursor, dinv, NN);
    fill_kernel<<<(EE + 255) / 256, 256>>>(erow, ecol, cursor, esrc, EE);

    // layer 1: aggregate(x,64) -> gemm 64->128 +relu
    run_aggregate(x, dinv, rowptr, esrc, aggHi, aggLo, 64);
    run_gemm_mma(aggHi, aggLo, wtHi + WOFF_L1, wtLo + WOFF_L1, b1, bufB, NN, 64, 128, 1);

    // layer 2: aggregate(h1,128) -> gemm 128->192 +relu
    run_aggregate(bufB, dinv, rowptr, esrc, aggHi, aggLo, 128);
    run_gemm_mma(aggHi, aggLo, wtHi + WOFF_L2, wtLo + WOFF_L2, b2, bufB, NN, 128, 192, 1);

    // layer 3: aggregate(h2,192) -> gemm 192->256 +relu, fused segment-max pool
    run_aggregate(bufB, dinv, rowptr, esrc, aggHi, aggLo, 192);
    run_gemm_mma(aggHi, aggLo, wtHi + WOFF_L3, wtLo + WOFF_L3, b3, bufB, NN, 192, 256, 1,
                 nullptr, nullptr, nullptr, batch, x2);

    // shared aggregation for mu / logvar heads
    run_aggregate(bufB, dinv, rowptr, esrc, aggHi, aggLo, 256);
    run_gemm_mma(aggHi, aggLo, wtHi + WOFF_MU, wtLo + WOFF_MU, bmu, out_mu, NN, 256, 256, 0);
    run_gemm_mma(aggHi, aggLo, wtHi + WOFF_LV, wtLo + WOFF_LV, blv, out_lv, NN, 256, 256, 0,
                 out_mu, eps, out_amvo);

    // MLP head on pooled features (bf16x3 mma path)
    split_f32_kernel<<<(BB * 256 + 255) / 256, 256>>>(x2, x2hi, x2lo, BB * 256);
    run_gemm_mma(x2hi, x2lo, fc1hi, fc1lo, fc1b, hidden, BB, 256, 1024, 1);
    split_f32_kernel<<<(BB * 1024 + 255) / 256, 256>>>(hidden, hidhi, hidlo, BB * 1024);
    run_gemm_mma(hidhi, hidlo, fc2hi, fc2lo, fc2b, out_pmvo, BB, 1024, 128, 0);
}

// round 14
// speedup vs baseline: 1.3584x; 1.0135x over previous
#include <cuda_runtime.h>
#include <cuda_bf16.h>
#include <math.h>
#include <stdint.h>

#define NN 100000
#define EE 400000
#define BB 512

// ---------------- scratch (no allocations allowed) ----------------
__device__ float g_dinv[NN];
__device__ int   g_cnt[NN];
__device__ int   g_rowptr[NN + 1];
__device__ int   g_cursor[NN];
__device__ int   g_esrc[EE];
__device__ float g_edinv[EE];
__device__ int   g_bsums[128];
__device__ __nv_bfloat16 g_aggHi[(size_t)NN * 256];  // aggregated A, high bf16
__device__ __nv_bfloat16 g_aggLo[(size_t)NN * 256];  // aggregated A, low  bf16
__device__ float g_bufB[(size_t)NN * 256];           // post-GEMM features (fp32)
__device__ float g_x2[BB * 256];                     // pooled max
__device__ float g_hidden[BB * 1024];                // fc1 output
// per-layer W^T split buffers (hi/lo planes), padded to 128-col multiples
#define WT_TOTAL (8192 + 32768 + 49152 + 65536 + 65536)
__device__ __nv_bfloat16 g_wt_hi[WT_TOTAL];
__device__ __nv_bfloat16 g_wt_lo[WT_TOTAL];
#define WOFF_L1 0
#define WOFF_L2 8192
#define WOFF_L3 40960
#define WOFF_MU 90112
#define WOFF_LV 155648
// FC head buffers (bf16 path)
__device__ __nv_bfloat16 g_wtfc1_hi[1024 * 256];
__device__ __nv_bfloat16 g_wtfc1_lo[1024 * 256];
__device__ __nv_bfloat16 g_wtfc2_hi[128 * 1024];
__device__ __nv_bfloat16 g_wtfc2_lo[128 * 1024];
__device__ __nv_bfloat16 g_x2hi[BB * 256];
__device__ __nv_bfloat16 g_x2lo[BB * 256];
__device__ __nv_bfloat16 g_hidhi[BB * 1024];
__device__ __nv_bfloat16 g_hidlo[BB * 1024];

// ---------------- CSR construction ----------------
__global__ void count_kernel(const int* __restrict__ col, int* cnt, int e) {
    int i = blockIdx.x * blockDim.x + threadIdx.x;
    if (i < e) atomicAdd(&cnt[col[i]], 1);
}

__global__ void block_reduce_kernel(const int* __restrict__ cnt, int* bsums, int n) {
    __shared__ int wsum[32];
    int idx = blockIdx.x * 1024 + threadIdx.x;
    int lane = threadIdx.x & 31, wid = threadIdx.x >> 5;
    int v = (idx < n) ? cnt[idx] : 0;
    #pragma unroll
    for (int s = 16; s; s >>= 1) v += __shfl_down_sync(0xffffffffu, v, s);
    if (lane == 0) wsum[wid] = v;
    __syncthreads();
    if (wid == 0) {
        int t = wsum[lane];
        #pragma unroll
        for (int s = 16; s; s >>= 1) t += __shfl_down_sync(0xffffffffu, t, s);
        if (lane == 0) bsums[blockIdx.x] = t;
    }
}

__global__ void scan_bsums_kernel(int* bsums, int nb) {
    __shared__ int ws[4];
    int tid = threadIdx.x;
    int lane = tid & 31, wid = tid >> 5;
    int v = (tid < nb) ? bsums[tid] : 0;
    int incl = v;
    #pragma unroll
    for (int s = 1; s < 32; s <<= 1) {
        int t = __shfl_up_sync(0xffffffffu, incl, s);
        if (lane >= s) incl += t;
    }
    if (lane == 31) ws[wid] = incl;
    __syncthreads();
    if (tid == 0) {
        int a = 0;
        #pragma unroll
        for (int i = 0; i < 4; i++) { int t = ws[i]; ws[i] = a; a += t; }
    }
    __syncthreads();
    if (tid < nb) bsums[tid] = incl - v + ws[wid];
}

// also computes dinv (fused to save a launch)
__global__ void scan_final_kernel(const int* __restrict__ cnt, const int* __restrict__ boff,
                                  int* rowptr, int* cursor, float* dinv, int n) {
    __shared__ int wsum[32];
    int idx = blockIdx.x * 1024 + threadIdx.x;
    int lane = threadIdx.x & 31, wid = threadIdx.x >> 5;
    int v = (idx < n) ? cnt[idx] : 0;
    int incl = v;
    #pragma unroll
    for (int s = 1; s < 32; s <<= 1) {
        int t = __shfl_up_sync(0xffffffffu, incl, s);
        if (lane >= s) incl += t;
    }
    if (lane == 31) wsum[wid] = incl;
    __syncthreads();
    if (wid == 0) {
        int w = wsum[lane];
        int wi = w;
        #pragma unroll
        for (int s = 1; s < 32; s <<= 1) {
            int t = __shfl_up_sync(0xffffffffu, wi, s);
            if (lane >= s) wi += t;
        }
        wsum[lane] = wi - w;
    }
    __syncthreads();
    int excl = incl - v + wsum[wid] + __ldg(&boff[blockIdx.x]);
    if (idx < n) {
        rowptr[idx] = excl;
        cursor[idx] = excl;
        dinv[idx] = rsqrtf(1.0f + (float)v);   // +1 self-loop
        if (idx == n - 1) rowptr[n] = excl + v;
    }
}

// also stores edinv[pos] = dinv[src] so gathers skip one dependent random load
__global__ void fill_kernel(const int* __restrict__ erow, const int* __restrict__ ecol,
                            const float* __restrict__ dinv,
                            int* cursor, int* esrc, float* edinv, int e) {
    int i = blockIdx.x * blockDim.x + threadIdx.x;
    if (i < e) {
        int src = erow[i];
        int pos = atomicAdd(&cursor[ecol[i]], 1);
        esrc[pos] = src;
        edinv[pos] = __ldg(&dinv[src]);
    }
}

// ---------------- gather aggregation: warp-per-node, COALESCED columns --------
// Lane owns strided columns c = j*32 + lane; esrc/edinv load in parallel so the
// only dependent hop is esrc -> h row.
template <int COLS>   // COLS = F/32 floats per lane
__global__ void gather_row_kernel(const float* __restrict__ h,
                                  const float* __restrict__ dinv,
                                  const int* __restrict__ rowptr,
                                  const int* __restrict__ esrc,
                                  const float* __restrict__ edinv,
                                  __nv_bfloat16* __restrict__ aggHi,
                                  __nv_bfloat16* __restrict__ aggLo,
                                  int n, int F) {
    int node = (blockIdx.x * blockDim.x + threadIdx.x) >> 5;
    int lane = threadIdx.x & 31;
    if (node >= n) return;
    float dn = __ldg(&dinv[node]);
    float sum[COLS];
    {
        const float* r = h + (size_t)node * F + lane;
        #pragma unroll
        for (int j = 0; j < COLS; j++) sum[j] = dn * __ldg(&r[j * 32]);
    }
    int s = __ldg(&rowptr[node]);
    int e = __ldg(&rowptr[node + 1]);
    int i = s;
    for (; i + 3 < e; i += 4) {
        int s0 = __ldg(&esrc[i]);
        int s1 = __ldg(&esrc[i + 1]);
        int s2 = __ldg(&esrc[i + 2]);
        int s3 = __ldg(&esrc[i + 3]);
        float d0 = __ldg(&edinv[i]);
        float d1 = __ldg(&edinv[i + 1]);
        float d2 = __ldg(&edinv[i + 2]);
        float d3 = __ldg(&edinv[i + 3]);
        const float* r0 = h + (size_t)s0 * F + lane;
        const float* r1 = h + (size_t)s1 * F + lane;
        const float* r2 = h + (size_t)s2 * F + lane;
        const float* r3 = h + (size_t)s3 * F + lane;
        #pragma unroll
        for (int j = 0; j < COLS; j++) sum[j] += d0 * __ldg(&r0[j * 32]);
        #pragma unroll
        for (int j = 0; j < COLS; j++) sum[j] += d1 * __ldg(&r1[j * 32]);
        #pragma unroll
        for (int j = 0; j < COLS; j++) sum[j] += d2 * __ldg(&r2[j * 32]);
        #pragma unroll
        for (int j = 0; j < COLS; j++) sum[j] += d3 * __ldg(&r3[j * 32]);
    }
    for (; i < e; i++) {
        int s0 = __ldg(&esrc[i]);
        float d0 = __ldg(&edinv[i]);
        const float* r0 = h + (size_t)s0 * F + lane;
        #pragma unroll
        for (int j = 0; j < COLS; j++) sum[j] += d0 * __ldg(&r0[j * 32]);
    }
    __nv_bfloat16* oh = aggHi + (size_t)node * F + lane;
    __nv_bfloat16* ol = aggLo + (size_t)node * F + lane;
    #pragma unroll
    for (int j = 0; j < COLS; j++) {
        float v = dn * sum[j];
        __nv_bfloat16 hb = __float2bfloat16_rn(v);
        oh[j * 32] = hb;
        ol[j * 32] = __float2bfloat16_rn(v - __bfloat162float(hb));
    }
}

// ---------------- weight pre-split (tiled transpose, coalesced both ways) -----
// W[MK,N] -> Wt_{hi,lo}[Npad,MK]
__global__ void wsplit_kernel(const float* __restrict__ W,
                              __nv_bfloat16* __restrict__ whi,
                              __nv_bfloat16* __restrict__ wlo,
                              int MK, int N, int Npad) {
    __shared__ float t[32][33];
    const int kb = blockIdx.x * 32, nb = blockIdx.y * 32;
    const int tx = threadIdx.x & 31, ty = threadIdx.x >> 5;   // 256 thr: ty 0..7
    #pragma unroll
    for (int r = 0; r < 4; r++) {
        int k = kb + ty + 8 * r;
        int n = nb + tx;
        float v = (k < MK && n < N) ? W[(size_t)k * N + n] : 0.0f;
        t[ty + 8 * r][tx] = v;
    }
    __syncthreads();
    #pragma unroll
    for (int r = 0; r < 4; r++) {
        int n = nb + ty + 8 * r;
        int k = kb + tx;
        if (n < Npad && k < MK) {
            float v = t[tx][ty + 8 * r];
            __nv_bfloat16 h = __float2bfloat16_rn(v);
            whi[(size_t)n * MK + k] = h;
            wlo[(size_t)n * MK + k] = __float2bfloat16_rn(v - __bfloat162float(h));
        }
    }
}

// ---------------- elementwise fp32 -> bf16 hi/lo split ----------------
__global__ void split_f32_kernel(const float* __restrict__ src,
                                 __nv_bfloat16* __restrict__ hi,
                                 __nv_bfloat16* __restrict__ lo, int n) {
    int i = blockIdx.x * blockDim.x + threadIdx.x;
    if (i < n) {
        float v = src[i];
        __nv_bfloat16 h = __float2bfloat16_rn(v);
        hi[i] = h;
        lo[i] = __float2bfloat16_rn(v - __bfloat162float(h));
    }
}

// ---------------- bf16x3 tensor-core GEMM with cp.async (R7-proven shape) -----
// 128x128 CTA tile, 2x4 warp grid, 2-stage pipeline, 80 KB smem.
// Tiles stored with 80-byte row stride: (addr/16) mod 8 = (5r+c) mod 8 bijective
// over 8 consecutive rows -> conflict-free ldmatrix. 16B-aligned (80 = 5*16).
#define RS 80

#define LDSM_X4(R, ADDR) \
    asm volatile("ldmatrix.sync.aligned.m8n8.x4.shared.b16 {%0,%1,%2,%3}, [%4];" \
        : "=r"((R)[0]), "=r"((R)[1]), "=r"((R)[2]), "=r"((R)[3]) : "r"(ADDR))

#define MMA_BF16(CC, AA, B0, B1) \
    asm volatile("mma.sync.aligned.m16n8k16.row.col.f32.bf16.bf16.f32 " \
        "{%0,%1,%2,%3}, {%4,%5,%6,%7}, {%8,%9}, {%0,%1,%2,%3};" \
        : "+f"((CC)[0]), "+f"((CC)[1]), "+f"((CC)[2]), "+f"((CC)[3]) \
        : "r"((AA)[0]), "r"((AA)[1]), "r"((AA)[2]), "r"((AA)[3]), \
          "r"(B0), "r"(B1))

#define CP16(DST, SRC, SZ) \
    asm volatile("cp.async.ca.shared.global [%0], [%1], 16, %2;" \
        :: "r"(DST), "l"(SRC), "r"(SZ) : "memory")

__global__ void __launch_bounds__(256)
gemm_mma_kernel(const __nv_bfloat16* __restrict__ aHi,
                const __nv_bfloat16* __restrict__ aLo,
                const __nv_bfloat16* __restrict__ wHi,
                const __nv_bfloat16* __restrict__ wLo,
                const float* __restrict__ bias,
                float* __restrict__ C, int Nr, int MK, int Kout, int relu,
                const float* __restrict__ mu_in, const float* __restrict__ eps_in,
                float* __restrict__ amvo_out,
                const int* __restrict__ batch, float* __restrict__ pool) {
    extern __shared__ char smem[];
    const int tid = threadIdx.x;
    const int w = tid >> 5, lid = tid & 31;
    const int wr = w >> 2, wc = w & 3;          // warp grid 2x4 over 128x128
    const int row0 = blockIdx.y * 128, col0 = blockIdx.x * 128;
    const uint32_t sbase = (uint32_t)__cvta_generic_to_shared(smem);

    const int TILE = 128 * RS;                   // 10240 B per plane
    const int STAGE = 4 * TILE;                  // AsHi | AsLo | BsHi | BsLo

    float acc[4][4][4] = {};

    const int nc = MK >> 5;               // chunks of 32

    const int lr = tid >> 1;              // 0..127
    const int lhalf = tid & 1;            // 0/1 (32B halves of the 64B row)

    auto issue_chunk = [&](int ci, int s) {
        const int k0 = ci << 5;
        const uint32_t st = sbase + s * STAGE;
        const uint32_t dstA = st + lr * RS + lhalf * 32;
        int gr = row0 + lr;
        int sz = (gr < Nr) ? 16 : 0;
        const __nv_bfloat16* sh = aHi + (size_t)(gr < Nr ? gr : 0) * MK + k0 + lhalf * 16;
        const __nv_bfloat16* sl = aLo + (size_t)(gr < Nr ? gr : 0) * MK + k0 + lhalf * 16;
        CP16(dstA,              sh,     sz);
        CP16(dstA + 16,         sh + 8, sz);
        CP16(dstA + TILE,       sl,     sz);
        CP16(dstA + TILE + 16,  sl + 8, sz);
        int n = col0 + lr;   // padded rows always valid
        const __nv_bfloat16* bh = wHi + (size_t)n * MK + k0 + lhalf * 16;
        const __nv_bfloat16* bl = wLo + (size_t)n * MK + k0 + lhalf * 16;
        const uint32_t dstB = st + 2 * TILE + lr * RS + lhalf * 32;
        CP16(dstB,              bh,     16);
        CP16(dstB + 16,         bh + 8, 16);
        CP16(dstB + TILE,       bl,     16);
        CP16(dstB + TILE + 16,  bl + 8, 16);
        asm volatile("cp.async.commit_group;" ::: "memory");
    };

    auto compute = [&](int s) {
        const uint32_t aHiB = sbase + s * STAGE;
        const uint32_t aLoB = aHiB + TILE;
        const uint32_t bHiB = aHiB + 2 * TILE;
        const uint32_t bLoB = aHiB + 3 * TILE;
        const int sub = lid & 7;
        const int g1 = (lid >> 3) & 1;
        const int g2 = (lid >> 4) & 1;
        #pragma unroll
        for (int ks = 0; ks < 2; ks++) {
            uint32_t bh[2][4], bl[2][4];
            #pragma unroll
            for (int np = 0; np < 2; np++) {
                uint32_t r = wc * 32 + np * 16 + g2 * 8 + sub;
                uint32_t off = r * RS + (ks * 2 + g1) * 16;
                LDSM_X4(bh[np], bHiB + off);
                LDSM_X4(bl[np], bLoB + off);
            }
            {
                uint32_t af[4][4];
                #pragma unroll
                for (int mt = 0; mt < 4; mt++) {
                    uint32_t r = wr * 64 + mt * 16 + g1 * 8 + sub;
                    uint32_t off = r * RS + (ks * 2 + g2) * 16;
                    LDSM_X4(af[mt], aHiB + off);
                }
                #pragma unroll
                for (int mt = 0; mt < 4; mt++)
                    #pragma unroll
                    for (int nt = 0; nt < 4; nt++) {
                        const uint32_t* BH = &bh[nt >> 1][(nt & 1) * 2];
                        const uint32_t* BL = &bl[nt >> 1][(nt & 1) * 2];
                        MMA_BF16(acc[mt][nt], af[mt], BH[0], BH[1]);
                        MMA_BF16(acc[mt][nt], af[mt], BL[0], BL[1]);
                    }
                #pragma unroll
                for (int mt = 0; mt < 4; mt++) {
                    uint32_t r = wr * 64 + mt * 16 + g1 * 8 + sub;
                    uint32_t off = r * RS + (ks * 2 + g2) * 16;
                    LDSM_X4(af[mt], aLoB + off);
                }
                #pragma unroll
                for (int mt = 0; mt < 4; mt++)
                    #pragma unroll
                    for (int nt = 0; nt < 4; nt++) {
                        const uint32_t* BH = &bh[nt >> 1][(nt & 1) * 2];
                        MMA_BF16(acc[mt][nt], af[mt], BH[0], BH[1]);
                    }
            }
        }
    };

    // ---- mainloop: 2-stage cp.async pipeline (R7) ----
    issue_chunk(0, 0);
    if (nc > 1) issue_chunk(1, 1);
    for (int ci = 0; ci < nc; ci++) {
        int s = ci & 1;
        if (ci < nc - 1) {
            asm volatile("cp.async.wait_group 1;" ::: "memory");
        } else {
            asm volatile("cp.async.wait_group 0;" ::: "memory");
        }
        __syncthreads();
        compute(s);
        __syncthreads();
        if (ci + 2 < nc) issue_chunk(ci + 2, s);
    }

    // ---- epilogue (pool path uses warp-reduced atomics; batch is sorted) ----
    const int g = lid >> 2, tg = lid & 3;
    #pragma unroll
    for (int mt = 0; mt < 4; mt++) {
        const int ra = row0 + wr * 64 + mt * 16 + g;   // row A (g in 0..7)
        const int rb = ra + 8;                          // row B
        int ba = 0, bb = 0;
        bool grp_uniform = false;
        if (pool != nullptr) {
            ba = __ldg(&batch[ra < Nr ? ra : (Nr - 1)]);
            bb = __ldg(&batch[rb < Nr ? rb : (Nr - 1)]);
            int bmin = min(ba, bb), bmax = max(ba, bb);
            #pragma unroll
            for (int msk = 4; msk <= 16; msk <<= 1) {
                bmin = min(bmin, __shfl_xor_sync(0xffffffffu, bmin, msk));
                bmax = max(bmax, __shfl_xor_sync(0xffffffffu, bmax, msk));
            }
            grp_uniform = (bmin == bmax);
        }
        #pragma unroll
        for (int nt = 0; nt < 4; nt++) {
            int col = col0 + wc * 32 + nt * 8 + 2 * tg;
            if (col >= Kout) continue;   // warp-uniform (tiles are 8-col aligned)
            float bs0 = __ldg(&bias[col]);
            float bs1 = __ldg(&bias[col + 1]);
            float a0 = acc[mt][nt][0] + bs0, a1 = acc[mt][nt][1] + bs1;
            float b0 = acc[mt][nt][2] + bs0, b1 = acc[mt][nt][3] + bs1;
            if (relu) {
                a0 = fmaxf(a0, 0.f); a1 = fmaxf(a1, 0.f);
                b0 = fmaxf(b0, 0.f); b1 = fmaxf(b1, 0.f);
            }
            if (ra < Nr) {
                *(float2*)&C[(size_t)ra * Kout + col] = make_float2(a0, a1);
                if (amvo_out != nullptr) {
                    float2 m = *(const float2*)&mu_in[(size_t)ra * Kout + col];
                    float2 e = *(const float2*)&eps_in[(size_t)ra * Kout + col];
                    float2 o;
                    o.x = fmaf(e.x, __expf(0.5f * a0), m.x);
                    o.y = fmaf(e.y, __expf(0.5f * a1), m.y);
                    *(float2*)&amvo_out[(size_t)ra * Kout + col] = o;
                }
            }
            if (rb < Nr) {
                *(float2*)&C[(size_t)rb * Kout + col] = make_float2(b0, b1);
                if (amvo_out != nullptr) {
                    float2 m = *(const float2*)&mu_in[(size_t)rb * Kout + col];
                    float2 e = *(const float2*)&eps_in[(size_t)rb * Kout + col];
                    float2 o;
                    o.x = fmaf(e.x, __expf(0.5f * b0), m.x);
                    o.y = fmaf(e.y, __expf(0.5f * b1), m.y);
                    *(float2*)&amvo_out[(size_t)rb * Kout + col] = o;
                }
            }
            if (pool != nullptr) {
                float va0 = (ra < Nr) ? a0 : 0.f, va1 = (ra < Nr) ? a1 : 0.f;
                float vb0 = (rb < Nr) ? b0 : 0.f, vb1 = (rb < Nr) ? b1 : 0.f;
                if (grp_uniform) {
                    float m0 = fmaxf(va0, vb0), m1 = fmaxf(va1, vb1);
                    #pragma unroll
                    for (int msk = 4; msk <= 16; msk <<= 1) {
                        m0 = fmaxf(m0, __shfl_xor_sync(0xffffffffu, m0, msk));
                        m1 = fmaxf(m1, __shfl_xor_sync(0xffffffffu, m1, msk));
                    }
                    if (g == 0) {
                        atomicMax((int*)&pool[(size_t)ba * Kout + col],     __float_as_int(m0));
                        atomicMax((int*)&pool[(size_t)ba * Kout + col + 1], __float_as_int(m1));
                    }
                } else {
                    if (ra < Nr) {
                        atomicMax((int*)&pool[(size_t)ba * Kout + col],     __float_as_int(a0));
                        atomicMax((int*)&pool[(size_t)ba * Kout + col + 1], __float_as_int(a1));
                    }
                    if (rb < Nr) {
                        atomicMax((int*)&pool[(size_t)bb * Kout + col],     __float_as_int(b0));
                        atomicMax((int*)&pool[(size_t)bb * Kout + col + 1], __float_as_int(b1));
                    }
                }
            }
        }
    }
}

// ---------------- launch orchestration ----------------
static inline void run_aggregate(const float* h, const float* dinv,
                                 const int* rowptr, const int* esrc, const float* edinv,
                                 __nv_bfloat16* aggHi, __nv_bfloat16* aggLo, int F) {
    int blocks = (NN * 32 + 255) / 256;
    switch (F) {
        case 64:  gather_row_kernel<2><<<blocks, 256>>>(h, dinv, rowptr, esrc, edinv, aggHi, aggLo, NN, F); break;
        case 128: gather_row_kernel<4><<<blocks, 256>>>(h, dinv, rowptr, esrc, edinv, aggHi, aggLo, NN, F); break;
        case 192: gather_row_kernel<6><<<blocks, 256>>>(h, dinv, rowptr, esrc, edinv, aggHi, aggLo, NN, F); break;
        default:  gather_row_kernel<8><<<blocks, 256>>>(h, dinv, rowptr, esrc, edinv, aggHi, aggLo, NN, F); break;
    }
}

static inline void run_gemm_mma(const __nv_bfloat16* aHi, const __nv_bfloat16* aLo,
                                const __nv_bfloat16* wHi, const __nv_bfloat16* wLo,
                                const float* bias,
                                float* C, int Nr, int MK, int Kout, int relu,
                                const float* mu_in = nullptr,
                                const float* eps_in = nullptr,
                                float* amvo_out = nullptr,
                                const int* batch = nullptr,
                                float* pool = nullptr) {
    int gx = (Kout + 127) / 128;
    const int SMEM = 2 * 4 * 128 * RS;   // 81920 (R7-proven)
    cudaFuncSetAttribute(gemm_mma_kernel,
                         cudaFuncAttributeMaxDynamicSharedMemorySize, SMEM);
    dim3 grid(gx, (Nr + 127) / 128);
    gemm_mma_kernel<<<grid, 256, SMEM>>>(aHi, aLo, wHi, wLo, bias, C, Nr, MK, Kout,
                                         relu, mu_in, eps_in, amvo_out, batch, pool);
}

static inline void run_wsplit(const float* W, __nv_bfloat16* whi, __nv_bfloat16* wlo,
                              int MK, int N, int Npad) {
    dim3 grid((MK + 31) / 32, (Npad + 31) / 32);
    wsplit_kernel<<<grid, 256>>>(W, whi, wlo, MK, N, Npad);
}

extern "C" void kernel_launch(void* const* d_in, const int* in_sizes, int n_in,
                              void* d_out, int out_size) {
    const float* x     = (const float*)d_in[0];
    const int*   ei    = (const int*)d_in[1];
    const int*   batch = (const int*)d_in[2];
    const float* eps   = (const float*)d_in[3];
    const float* W1 = (const float*)d_in[4];  const float* b1 = (const float*)d_in[5];
    const float* W2 = (const float*)d_in[6];  const float* b2 = (const float*)d_in[7];
    const float* W3 = (const float*)d_in[8];  const float* b3 = (const float*)d_in[9];
    const float* Wmu = (const float*)d_in[10]; const float* bmu = (const float*)d_in[11];
    const float* Wlv = (const float*)d_in[12]; const float* blv = (const float*)d_in[13];
    const float* fc1w = (const float*)d_in[14]; const float* fc1b = (const float*)d_in[15];
    const float* fc2w = (const float*)d_in[16]; const float* fc2b = (const float*)d_in[17];

    float* out = (float*)d_out;
    float* out_amvo = out;
    float* out_mu   = out + (size_t)NN * 256;
    float* out_lv   = out + 2 * (size_t)NN * 256;
    float* out_pmvo = out + 3 * (size_t)NN * 256;

    float *dinv, *edinv, *bufB, *x2, *hidden;
    int *cnt, *rowptr, *cursor, *esrc, *bsums;
    __nv_bfloat16 *aggHi, *aggLo, *wtHi, *wtLo;
    __nv_bfloat16 *fc1hi, *fc1lo, *fc2hi, *fc2lo, *x2hi, *x2lo, *hidhi, *hidlo;
    cudaGetSymbolAddress((void**)&dinv, g_dinv);
    cudaGetSymbolAddress((void**)&edinv, g_edinv);
    cudaGetSymbolAddress((void**)&cnt, g_cnt);
    cudaGetSymbolAddress((void**)&rowptr, g_rowptr);
    cudaGetSymbolAddress((void**)&cursor, g_cursor);
    cudaGetSymbolAddress((void**)&esrc, g_esrc);
    cudaGetSymbolAddress((void**)&bsums, g_bsums);
    cudaGetSymbolAddress((void**)&aggHi, g_aggHi);
    cudaGetSymbolAddress((void**)&aggLo, g_aggLo);
    cudaGetSymbolAddress((void**)&bufB, g_bufB);
    cudaGetSymbolAddress((void**)&x2, g_x2);
    cudaGetSymbolAddress((void**)&hidden, g_hidden);
    cudaGetSymbolAddress((void**)&wtHi, g_wt_hi);
    cudaGetSymbolAddress((void**)&wtLo, g_wt_lo);
    cudaGetSymbolAddress((void**)&fc1hi, g_wtfc1_hi);
    cudaGetSymbolAddress((void**)&fc1lo, g_wtfc1_lo);
    cudaGetSymbolAddress((void**)&fc2hi, g_wtfc2_hi);
    cudaGetSymbolAddress((void**)&fc2lo, g_wtfc2_lo);
    cudaGetSymbolAddress((void**)&x2hi, g_x2hi);
    cudaGetSymbolAddress((void**)&x2lo, g_x2lo);
    cudaGetSymbolAddress((void**)&hidhi, g_hidhi);
    cudaGetSymbolAddress((void**)&hidlo, g_hidlo);

    const int* erow = ei;
    const int* ecol = ei + EE;

    const int SCAN_BLOCKS = (NN + 1023) / 1024;   // 98

    // zero scratch via memset nodes (graph-capturable)
    cudaMemsetAsync(cnt, 0, NN * sizeof(int));
    cudaMemsetAsync(x2, 0, BB * 256 * sizeof(float));

    // all weight pre-splits up front (tiled transpose, coalesced)
    run_wsplit(W1,  wtHi + WOFF_L1, wtLo + WOFF_L1, 64,  128, 128);
    run_wsplit(W2,  wtHi + WOFF_L2, wtLo + WOFF_L2, 128, 192, 256);
    run_wsplit(W3,  wtHi + WOFF_L3, wtLo + WOFF_L3, 192, 256, 256);
    run_wsplit(Wmu, wtHi + WOFF_MU, wtLo + WOFF_MU, 256, 256, 256);
    run_wsplit(Wlv, wtHi + WOFF_LV, wtLo + WOFF_LV, 256, 256, 256);
    run_wsplit(fc1w, fc1hi, fc1lo, 256, 1024, 1024);
    run_wsplit(fc2w, fc2hi, fc2lo, 1024, 128, 128);

    // CSR build + normalization (dinv fused into scan_final; edinv in fill)
    count_kernel<<<(EE + 255) / 256, 256>>>(ecol, cnt, EE);
    block_reduce_kernel<<<SCAN_BLOCKS, 1024>>>(cnt, bsums, NN);
    scan_bsums_kernel<<<1, 128>>>(bsums, SCAN_BLOCKS);
    scan_final_kernel<<<SCAN_BLOCKS, 1024>>>(cnt, bsums, rowptr, cursor, dinv, NN);
    fill_kernel<<<(EE + 255) / 256, 256>>>(erow, ecol, dinv, cursor, esrc, edinv, EE);

    // layer 1: aggregate(x,64) -> gemm 64->128 +relu
    run_aggregate(x, dinv, rowptr, esrc, edinv, aggHi, aggLo, 64);
    run_gemm_mma(aggHi, aggLo, wtHi + WOFF_L1, wtLo + WOFF_L1, b1, bufB, NN, 64, 128, 1);

    // layer 2: aggregate(h1,128) -> gemm 128->192 +relu
    run_aggregate(bufB, dinv, rowptr, esrc, edinv, aggHi, aggLo, 128);
    run_gemm_mma(aggHi, aggLo, wtHi + WOFF_L2, wtLo + WOFF_L2, b2, bufB, NN, 128, 192, 1);

    // layer 3: aggregate(h2,192) -> gemm 192->256 +relu, fused segment-max pool
    run_aggregate(bufB, dinv, rowptr, esrc, edinv, aggHi, aggLo, 192);
    run_gemm_mma(aggHi, aggLo, wtHi + WOFF_L3, wtLo + WOFF_L3, b3, bufB, NN, 192, 256, 1,
                 nullptr, nullptr, nullptr, batch, x2);

    // shared aggregation for mu / logvar heads
    run_aggregate(bufB, dinv, rowptr, esrc, edinv, aggHi, aggLo, 256);
    run_gemm_mma(aggHi, aggLo, wtHi + WOFF_MU, wtLo + WOFF_MU, bmu, out_mu, NN, 256, 256, 0);
    run_gemm_mma(aggHi, aggLo, wtHi + WOFF_LV, wtLo + WOFF_LV, blv, out_lv, NN, 256, 256, 0,
                 out_mu, eps, out_amvo);

    // MLP head on pooled features (bf16x3 mma path)
    split_f32_kernel<<<(BB * 256 + 255) / 256, 256>>>(x2, x2hi, x2lo, BB * 256);
    run_gemm_mma(x2hi, x2lo, fc1hi, fc1lo, fc1b, hidden, BB, 256, 1024, 1);
    split_f32_kernel<<<(BB * 1024 + 255) / 256, 256>>>(hidden, hidhi, hidlo, BB * 1024);
    run_gemm_mma(hidhi, hidlo, fc2hi, fc2lo, fc2b, out_pmvo, BB, 1024, 128, 0);
}

// round 15
// speedup vs baseline: 1.3765x; 1.0133x over previous
#include <cuda_runtime.h>
#include <cuda_bf16.h>
#include <math.h>
#include <stdint.h>

#define NN 100000
#define EE 400000
#define BB 512

// ---------------- scratch (no allocations allowed) ----------------
__device__ float g_dinv[NN];
__device__ int   g_cnt[NN];
__device__ int   g_rowptr[NN + 1];
__device__ int   g_cursor[NN];
__device__ int   g_esrc[EE];
__device__ float g_edinv[EE];
__device__ int   g_bsums[128];
__device__ __nv_bfloat16 g_aggHi[(size_t)NN * 256];  // aggregated A, high bf16
__device__ __nv_bfloat16 g_aggLo[(size_t)NN * 256];  // aggregated A, low  bf16
__device__ float g_bufB[(size_t)NN * 256];           // post-GEMM features (fp32)
__device__ float g_x2[BB * 256];                     // pooled max
__device__ float g_hidden[BB * 1024];                // fc1 output
// per-layer W^T split buffers (hi/lo planes), padded to 128-col multiples
#define WT_TOTAL (8192 + 32768 + 49152 + 65536 + 65536)
__device__ __nv_bfloat16 g_wt_hi[WT_TOTAL];
__device__ __nv_bfloat16 g_wt_lo[WT_TOTAL];
#define WOFF_L1 0
#define WOFF_L2 8192
#define WOFF_L3 40960
#define WOFF_MU 90112
#define WOFF_LV 155648
// FC head buffers (bf16 path)
__device__ __nv_bfloat16 g_wtfc1_hi[1024 * 256];
__device__ __nv_bfloat16 g_wtfc1_lo[1024 * 256];
__device__ __nv_bfloat16 g_wtfc2_hi[128 * 1024];
__device__ __nv_bfloat16 g_wtfc2_lo[128 * 1024];
__device__ __nv_bfloat16 g_x2hi[BB * 256];
__device__ __nv_bfloat16 g_x2lo[BB * 256];
__device__ __nv_bfloat16 g_hidhi[BB * 1024];
__device__ __nv_bfloat16 g_hidlo[BB * 1024];

// ---------------- CSR construction ----------------
__global__ void count_kernel(const int* __restrict__ col, int* cnt, int e) {
    int i = blockIdx.x * blockDim.x + threadIdx.x;
    if (i < e) atomicAdd(&cnt[col[i]], 1);
}

__global__ void block_reduce_kernel(const int* __restrict__ cnt, int* bsums, int n) {
    __shared__ int wsum[32];
    int idx = blockIdx.x * 1024 + threadIdx.x;
    int lane = threadIdx.x & 31, wid = threadIdx.x >> 5;
    int v = (idx < n) ? cnt[idx] : 0;
    #pragma unroll
    for (int s = 16; s; s >>= 1) v += __shfl_down_sync(0xffffffffu, v, s);
    if (lane == 0) wsum[wid] = v;
    __syncthreads();
    if (wid == 0) {
        int t = wsum[lane];
        #pragma unroll
        for (int s = 16; s; s >>= 1) t += __shfl_down_sync(0xffffffffu, t, s);
        if (lane == 0) bsums[blockIdx.x] = t;
    }
}

__global__ void scan_bsums_kernel(int* bsums, int nb) {
    __shared__ int ws[4];
    int tid = threadIdx.x;
    int lane = tid & 31, wid = tid >> 5;
    int v = (tid < nb) ? bsums[tid] : 0;
    int incl = v;
    #pragma unroll
    for (int s = 1; s < 32; s <<= 1) {
        int t = __shfl_up_sync(0xffffffffu, incl, s);
        if (lane >= s) incl += t;
    }
    if (lane == 31) ws[wid] = incl;
    __syncthreads();
    if (tid == 0) {
        int a = 0;
        #pragma unroll
        for (int i = 0; i < 4; i++) { int t = ws[i]; ws[i] = a; a += t; }
    }
    __syncthreads();
    if (tid < nb) bsums[tid] = incl - v + ws[wid];
}

// also computes dinv (fused to save a launch)
__global__ void scan_final_kernel(const int* __restrict__ cnt, const int* __restrict__ boff,
                                  int* rowptr, int* cursor, float* dinv, int n) {
    __shared__ int wsum[32];
    int idx = blockIdx.x * 1024 + threadIdx.x;
    int lane = threadIdx.x & 31, wid = threadIdx.x >> 5;
    int v = (idx < n) ? cnt[idx] : 0;
    int incl = v;
    #pragma unroll
    for (int s = 1; s < 32; s <<= 1) {
        int t = __shfl_up_sync(0xffffffffu, incl, s);
        if (lane >= s) incl += t;
    }
    if (lane == 31) wsum[wid] = incl;
    __syncthreads();
    if (wid == 0) {
        int w = wsum[lane];
        int wi = w;
        #pragma unroll
        for (int s = 1; s < 32; s <<= 1) {
            int t = __shfl_up_sync(0xffffffffu, wi, s);
            if (lane >= s) wi += t;
        }
        wsum[lane] = wi - w;
    }
    __syncthreads();
    int excl = incl - v + wsum[wid] + __ldg(&boff[blockIdx.x]);
    if (idx < n) {
        rowptr[idx] = excl;
        cursor[idx] = excl;
        dinv[idx] = rsqrtf(1.0f + (float)v);   // +1 self-loop
        if (idx == n - 1) rowptr[n] = excl + v;
    }
}

// also stores edinv[pos] = dinv[src] so gathers skip one dependent random load
__global__ void fill_kernel(const int* __restrict__ erow, const int* __restrict__ ecol,
                            const float* __restrict__ dinv,
                            int* cursor, int* esrc, float* edinv, int e) {
    int i = blockIdx.x * blockDim.x + threadIdx.x;
    if (i < e) {
        int src = erow[i];
        int pos = atomicAdd(&cursor[ecol[i]], 1);
        esrc[pos] = src;
        edinv[pos] = __ldg(&dinv[src]);
    }
}

// ---------------- gather aggregation: warp-per-node, COALESCED columns --------
template <int COLS>   // COLS = F/32 floats per lane
__global__ void gather_row_kernel(const float* __restrict__ h,
                                  const float* __restrict__ dinv,
                                  const int* __restrict__ rowptr,
                                  const int* __restrict__ esrc,
                                  const float* __restrict__ edinv,
                                  __nv_bfloat16* __restrict__ aggHi,
                                  __nv_bfloat16* __restrict__ aggLo,
                                  int n, int F) {
    int node = (blockIdx.x * blockDim.x + threadIdx.x) >> 5;
    int lane = threadIdx.x & 31;
    if (node >= n) return;
    float dn = __ldg(&dinv[node]);
    float sum[COLS];
    {
        const float* r = h + (size_t)node * F + lane;
        #pragma unroll
        for (int j = 0; j < COLS; j++) sum[j] = dn * __ldg(&r[j * 32]);
    }
    int s = __ldg(&rowptr[node]);
    int e = __ldg(&rowptr[node + 1]);
    int i = s;
    for (; i + 3 < e; i += 4) {
        int s0 = __ldg(&esrc[i]);
        int s1 = __ldg(&esrc[i + 1]);
        int s2 = __ldg(&esrc[i + 2]);
        int s3 = __ldg(&esrc[i + 3]);
        float d0 = __ldg(&edinv[i]);
        float d1 = __ldg(&edinv[i + 1]);
        float d2 = __ldg(&edinv[i + 2]);
        float d3 = __ldg(&edinv[i + 3]);
        const float* r0 = h + (size_t)s0 * F + lane;
        const float* r1 = h + (size_t)s1 * F + lane;
        const float* r2 = h + (size_t)s2 * F + lane;
        const float* r3 = h + (size_t)s3 * F + lane;
        #pragma unroll
        for (int j = 0; j < COLS; j++) sum[j] += d0 * __ldg(&r0[j * 32]);
        #pragma unroll
        for (int j = 0; j < COLS; j++) sum[j] += d1 * __ldg(&r1[j * 32]);
        #pragma unroll
        for (int j = 0; j < COLS; j++) sum[j] += d2 * __ldg(&r2[j * 32]);
        #pragma unroll
        for (int j = 0; j < COLS; j++) sum[j] += d3 * __ldg(&r3[j * 32]);
    }
    for (; i < e; i++) {
        int s0 = __ldg(&esrc[i]);
        float d0 = __ldg(&edinv[i]);
        const float* r0 = h + (size_t)s0 * F + lane;
        #pragma unroll
        for (int j = 0; j < COLS; j++) sum[j] += d0 * __ldg(&r0[j * 32]);
    }
    __nv_bfloat16* oh = aggHi + (size_t)node * F + lane;
    __nv_bfloat16* ol = aggLo + (size_t)node * F + lane;
    #pragma unroll
    for (int j = 0; j < COLS; j++) {
        float v = dn * sum[j];
        __nv_bfloat16 hb = __float2bfloat16_rn(v);
        oh[j * 32] = hb;
        ol[j * 32] = __float2bfloat16_rn(v - __bfloat162float(hb));
    }
}

// ---------------- batched weight pre-split: ALL weights in ONE launch ---------
// Each 32x32 tile block resolves its weight via a small descriptor table.
#define NW 7
struct WSplitDesc {
    const float* W;
    __nv_bfloat16* whi;
    __nv_bfloat16* wlo;
    int MK, N, Npad;
    int tileOff;       // first tile index of this weight
    int tilesX;        // ceil(MK/32)
};
struct WSplitTable { WSplitDesc d[NW]; int totalTiles; };

__global__ void wsplit_batched_kernel(WSplitTable tab) {
    __shared__ float t[32][33];
    int tile = blockIdx.x;
    // resolve weight index (NW small; linear scan)
    int wi = NW - 1;
    #pragma unroll
    for (int k = NW - 1; k > 0; k--)
        if (tile < tab.d[k].tileOff) wi = k - 1;
    const WSplitDesc& D = tab.d[wi];
    int lt = tile - D.tileOff;
    int kb = (lt % D.tilesX) * 32;
    int nb = (lt / D.tilesX) * 32;
    const int tx = threadIdx.x & 31, ty = threadIdx.x >> 5;   // 256 thr
    #pragma unroll
    for (int r = 0; r < 4; r++) {
        int k = kb + ty + 8 * r;
        int n = nb + tx;
        float v = (k < D.MK && n < D.N) ? D.W[(size_t)k * D.N + n] : 0.0f;
        t[ty + 8 * r][tx] = v;
    }
    __syncthreads();
    #pragma unroll
    for (int r = 0; r < 4; r++) {
        int n = nb + ty + 8 * r;
        int k = kb + tx;
        if (n < D.Npad && k < D.MK) {
            float v = t[tx][ty + 8 * r];
            __nv_bfloat16 h = __float2bfloat16_rn(v);
            D.whi[(size_t)n * D.MK + k] = h;
            D.wlo[(size_t)n * D.MK + k] = __float2bfloat16_rn(v - __bfloat162float(h));
        }
    }
}

// ---------------- elementwise fp32 -> bf16 hi/lo split ----------------
__global__ void split_f32_kernel(const float* __restrict__ src,
                                 __nv_bfloat16* __restrict__ hi,
                                 __nv_bfloat16* __restrict__ lo, int n) {
    int i = blockIdx.x * blockDim.x + threadIdx.x;
    if (i < n) {
        float v = src[i];
        __nv_bfloat16 h = __float2bfloat16_rn(v);
        hi[i] = h;
        lo[i] = __float2bfloat16_rn(v - __bfloat162float(h));
    }
}

// ---------------- bf16x3 tensor-core GEMM with cp.async (R7-proven shape) -----
#define RS 80

#define LDSM_X4(R, ADDR) \
    asm volatile("ldmatrix.sync.aligned.m8n8.x4.shared.b16 {%0,%1,%2,%3}, [%4];" \
        : "=r"((R)[0]), "=r"((R)[1]), "=r"((R)[2]), "=r"((R)[3]) : "r"(ADDR))

#define MMA_BF16(CC, AA, B0, B1) \
    asm volatile("mma.sync.aligned.m16n8k16.row.col.f32.bf16.bf16.f32 " \
        "{%0,%1,%2,%3}, {%4,%5,%6,%7}, {%8,%9}, {%0,%1,%2,%3};" \
        : "+f"((CC)[0]), "+f"((CC)[1]), "+f"((CC)[2]), "+f"((CC)[3]) \
        : "r"((AA)[0]), "r"((AA)[1]), "r"((AA)[2]), "r"((AA)[3]), \
          "r"(B0), "r"(B1))

#define CP16(DST, SRC, SZ) \
    asm volatile("cp.async.ca.shared.global [%0], [%1], 16, %2;" \
        :: "r"(DST), "l"(SRC), "r"(SZ) : "memory")

__global__ void __launch_bounds__(256)
gemm_mma_kernel(const __nv_bfloat16* __restrict__ aHi,
                const __nv_bfloat16* __restrict__ aLo,
                const __nv_bfloat16* __restrict__ wHi,
                const __nv_bfloat16* __restrict__ wLo,
                const float* __restrict__ bias,
                float* __restrict__ C, int Nr, int MK, int Kout, int relu,
                const float* __restrict__ mu_in, const float* __restrict__ eps_in,
                float* __restrict__ amvo_out,
                const int* __restrict__ batch, float* __restrict__ pool) {
    extern __shared__ char smem[];
    const int tid = threadIdx.x;
    const int w = tid >> 5, lid = tid & 31;
    const int wr = w >> 2, wc = w & 3;          // warp grid 2x4 over 128x128
    const int row0 = blockIdx.y * 128, col0 = blockIdx.x * 128;
    const uint32_t sbase = (uint32_t)__cvta_generic_to_shared(smem);

    const int TILE = 128 * RS;                   // 10240 B per plane
    const int STAGE = 4 * TILE;                  // AsHi | AsLo | BsHi | BsLo

    float acc[4][4][4] = {};

    const int nc = MK >> 5;               // chunks of 32

    const int lr = tid >> 1;              // 0..127
    const int lhalf = tid & 1;            // 0/1 (32B halves of the 64B row)

    auto issue_chunk = [&](int ci, int s) {
        const int k0 = ci << 5;
        const uint32_t st = sbase + s * STAGE;
        const uint32_t dstA = st + lr * RS + lhalf * 32;
        int gr = row0 + lr;
        int sz = (gr < Nr) ? 16 : 0;
        const __nv_bfloat16* sh = aHi + (size_t)(gr < Nr ? gr : 0) * MK + k0 + lhalf * 16;
        const __nv_bfloat16* sl = aLo + (size_t)(gr < Nr ? gr : 0) * MK + k0 + lhalf * 16;
        CP16(dstA,              sh,     sz);
        CP16(dstA + 16,         sh + 8, sz);
        CP16(dstA + TILE,       sl,     sz);
        CP16(dstA + TILE + 16,  sl + 8, sz);
        int n = col0 + lr;   // padded rows always valid
        const __nv_bfloat16* bh = wHi + (size_t)n * MK + k0 + lhalf * 16;
        const __nv_bfloat16* bl = wLo + (size_t)n * MK + k0 + lhalf * 16;
        const uint32_t dstB = st + 2 * TILE + lr * RS + lhalf * 32;
        CP16(dstB,              bh,     16);
        CP16(dstB + 16,         bh + 8, 16);
        CP16(dstB + TILE,       bl,     16);
        CP16(dstB + TILE + 16,  bl + 8, 16);
        asm volatile("cp.async.commit_group;" ::: "memory");
    };

    auto compute = [&](int s) {
        const uint32_t aHiB = sbase + s * STAGE;
        const uint32_t aLoB = aHiB + TILE;
        const uint32_t bHiB = aHiB + 2 * TILE;
        const uint32_t bLoB = aHiB + 3 * TILE;
        const int sub = lid & 7;
        const int g1 = (lid >> 3) & 1;
        const int g2 = (lid >> 4) & 1;
        #pragma unroll
        for (int ks = 0; ks < 2; ks++) {
            uint32_t bh[2][4], bl[2][4];
            #pragma unroll
            for (int np = 0; np < 2; np++) {
                uint32_t r = wc * 32 + np * 16 + g2 * 8 + sub;
                uint32_t off = r * RS + (ks * 2 + g1) * 16;
                LDSM_X4(bh[np], bHiB + off);
                LDSM_X4(bl[np], bLoB + off);
            }
            {
                uint32_t af[4][4];
                #pragma unroll
                for (int mt = 0; mt < 4; mt++) {
                    uint32_t r = wr * 64 + mt * 16 + g1 * 8 + sub;
                    uint32_t off = r * RS + (ks * 2 + g2) * 16;
                    LDSM_X4(af[mt], aHiB + off);
                }
                #pragma unroll
                for (int mt = 0; mt < 4; mt++)
                    #pragma unroll
                    for (int nt = 0; nt < 4; nt++) {
                        const uint32_t* BH = &bh[nt >> 1][(nt & 1) * 2];
                        const uint32_t* BL = &bl[nt >> 1][(nt & 1) * 2];
                        MMA_BF16(acc[mt][nt], af[mt], BH[0], BH[1]);
                        MMA_BF16(acc[mt][nt], af[mt], BL[0], BL[1]);
                    }
                #pragma unroll
                for (int mt = 0; mt < 4; mt++) {
                    uint32_t r = wr * 64 + mt * 16 + g1 * 8 + sub;
                    uint32_t off = r * RS + (ks * 2 + g2) * 16;
                    LDSM_X4(af[mt], aLoB + off);
                }
                #pragma unroll
                for (int mt = 0; mt < 4; mt++)
                    #pragma unroll
                    for (int nt = 0; nt < 4; nt++) {
                        const uint32_t* BH = &bh[nt >> 1][(nt & 1) * 2];
                        MMA_BF16(acc[mt][nt], af[mt], BH[0], BH[1]);
                    }
            }
        }
    };

    // ---- mainloop: 2-stage cp.async pipeline (R7) ----
    issue_chunk(0, 0);
    if (nc > 1) issue_chunk(1, 1);
    for (int ci = 0; ci < nc; ci++) {
        int s = ci & 1;
        if (ci < nc - 1) {
            asm volatile("cp.async.wait_group 1;" ::: "memory");
        } else {
            asm volatile("cp.async.wait_group 0;" ::: "memory");
        }
        __syncthreads();
        compute(s);
        __syncthreads();
        if (ci + 2 < nc) issue_chunk(ci + 2, s);
    }

    // ---- epilogue (pool path uses warp-reduced atomics; batch is sorted) ----
    const int g = lid >> 2, tg = lid & 3;
    #pragma unroll
    for (int mt = 0; mt < 4; mt++) {
        const int ra = row0 + wr * 64 + mt * 16 + g;   // row A (g in 0..7)
        const int rb = ra + 8;                          // row B
        int ba = 0, bb = 0;
        bool grp_uniform = false;
        if (pool != nullptr) {
            ba = __ldg(&batch[ra < Nr ? ra : (Nr - 1)]);
            bb = __ldg(&batch[rb < Nr ? rb : (Nr - 1)]);
            int bmin = min(ba, bb), bmax = max(ba, bb);
            #pragma unroll
            for (int msk = 4; msk <= 16; msk <<= 1) {
                bmin = min(bmin, __shfl_xor_sync(0xffffffffu, bmin, msk));
                bmax = max(bmax, __shfl_xor_sync(0xffffffffu, bmax, msk));
            }
            grp_uniform = (bmin == bmax);
        }
        #pragma unroll
        for (int nt = 0; nt < 4; nt++) {
            int col = col0 + wc * 32 + nt * 8 + 2 * tg;
            if (col >= Kout) continue;   // warp-uniform (tiles are 8-col aligned)
            float bs0 = __ldg(&bias[col]);
            float bs1 = __ldg(&bias[col + 1]);
            float a0 = acc[mt][nt][0] + bs0, a1 = acc[mt][nt][1] + bs1;
            float b0 = acc[mt][nt][2] + bs0, b1 = acc[mt][nt][3] + bs1;
            if (relu) {
                a0 = fmaxf(a0, 0.f); a1 = fmaxf(a1, 0.f);
                b0 = fmaxf(b0, 0.f); b1 = fmaxf(b1, 0.f);
            }
            if (ra < Nr) {
                *(float2*)&C[(size_t)ra * Kout + col] = make_float2(a0, a1);
                if (amvo_out != nullptr) {
                    float2 m = *(const float2*)&mu_in[(size_t)ra * Kout + col];
                    float2 e = *(const float2*)&eps_in[(size_t)ra * Kout + col];
                    float2 o;
                    o.x = fmaf(e.x, __expf(0.5f * a0), m.x);
                    o.y = fmaf(e.y, __expf(0.5f * a1), m.y);
                    *(float2*)&amvo_out[(size_t)ra * Kout + col] = o;
                }
            }
            if (rb < Nr) {
                *(float2*)&C[(size_t)rb * Kout + col] = make_float2(b0, b1);
                if (amvo_out != nullptr) {
                    float2 m = *(const float2*)&mu_in[(size_t)rb * Kout + col];
                    float2 e = *(const float2*)&eps_in[(size_t)rb * Kout + col];
                    float2 o;
                    o.x = fmaf(e.x, __expf(0.5f * b0), m.x);
                    o.y = fmaf(e.y, __expf(0.5f * b1), m.y);
                    *(float2*)&amvo_out[(size_t)rb * Kout + col] = o;
                }
            }
            if (pool != nullptr) {
                float va0 = (ra < Nr) ? a0 : 0.f, va1 = (ra < Nr) ? a1 : 0.f;
                float vb0 = (rb < Nr) ? b0 : 0.f, vb1 = (rb < Nr) ? b1 : 0.f;
                if (grp_uniform) {
                    float m0 = fmaxf(va0, vb0), m1 = fmaxf(va1, vb1);
                    #pragma unroll
                    for (int msk = 4; msk <= 16; msk <<= 1) {
                        m0 = fmaxf(m0, __shfl_xor_sync(0xffffffffu, m0, msk));
                        m1 = fmaxf(m1, __shfl_xor_sync(0xffffffffu, m1, msk));
                    }
                    if (g == 0) {
                        atomicMax((int*)&pool[(size_t)ba * Kout + col],     __float_as_int(m0));
                        atomicMax((int*)&pool[(size_t)ba * Kout + col + 1], __float_as_int(m1));
                    }
                } else {
                    if (ra < Nr) {
                        atomicMax((int*)&pool[(size_t)ba * Kout + col],     __float_as_int(a0));
                        atomicMax((int*)&pool[(size_t)ba * Kout + col + 1], __float_as_int(a1));
                    }
                    if (rb < Nr) {
                        atomicMax((int*)&pool[(size_t)bb * Kout + col],     __float_as_int(b0));
                        atomicMax((int*)&pool[(size_t)bb * Kout + col + 1], __float_as_int(b1));
                    }
                }
            }
        }
    }
}

// ---------------- launch orchestration ----------------
static inline void run_aggregate(const float* h, const float* dinv,
                                 const int* rowptr, const int* esrc, const float* edinv,
                                 __nv_bfloat16* aggHi, __nv_bfloat16* aggLo, int F) {
    int blocks = (NN * 32 + 255) / 256;
    switch (F) {
        case 64:  gather_row_kernel<2><<<blocks, 256>>>(h, dinv, rowptr, esrc, edinv, aggHi, aggLo, NN, F); break;
        case 128: gather_row_kernel<4><<<blocks, 256>>>(h, dinv, rowptr, esrc, edinv, aggHi, aggLo, NN, F); break;
        case 192: gather_row_kernel<6><<<blocks, 256>>>(h, dinv, rowptr, esrc, edinv, aggHi, aggLo, NN, F); break;
        default:  gather_row_kernel<8><<<blocks, 256>>>(h, dinv, rowptr, esrc, edinv, aggHi, aggLo, NN, F); break;
    }
}

static inline void run_gemm_mma(const __nv_bfloat16* aHi, const __nv_bfloat16* aLo,
                                const __nv_bfloat16* wHi, const __nv_bfloat16* wLo,
                                const float* bias,
                                float* C, int Nr, int MK, int Kout, int relu,
                                const float* mu_in = nullptr,
                                const float* eps_in = nullptr,
                                float* amvo_out = nullptr,
                                const int* batch = nullptr,
                                float* pool = nullptr) {
    int gx = (Kout + 127) / 128;
    const int SMEM = 2 * 4 * 128 * RS;   // 81920 (R7-proven)
    cudaFuncSetAttribute(gemm_mma_kernel,
                         cudaFuncAttributeMaxDynamicSharedMemorySize, SMEM);
    dim3 grid(gx, (Nr + 127) / 128);
    gemm_mma_kernel<<<grid, 256, SMEM>>>(aHi, aLo, wHi, wLo, bias, C, Nr, MK, Kout,
                                         relu, mu_in, eps_in, amvo_out, batch, pool);
}

extern "C" void kernel_launch(void* const* d_in, const int* in_sizes, int n_in,
                              void* d_out, int out_size) {
    const float* x     = (const float*)d_in[0];
    const int*   ei    = (const int*)d_in[1];
    const int*   batch = (const int*)d_in[2];
    const float* eps   = (const float*)d_in[3];
    const float* W1 = (const float*)d_in[4];  const float* b1 = (const float*)d_in[5];
    const float* W2 = (const float*)d_in[6];  const float* b2 = (const float*)d_in[7];
    const float* W3 = (const float*)d_in[8];  const float* b3 = (const float*)d_in[9];
    const float* Wmu = (const float*)d_in[10]; const float* bmu = (const float*)d_in[11];
    const float* Wlv = (const float*)d_in[12]; const float* blv = (const float*)d_in[13];
    const float* fc1w = (const float*)d_in[14]; const float* fc1b = (const float*)d_in[15];
    const float* fc2w = (const float*)d_in[16]; const float* fc2b = (const float*)d_in[17];

    float* out = (float*)d_out;
    float* out_amvo = out;
    float* out_mu   = out + (size_t)NN * 256;
    float* out_lv   = out + 2 * (size_t)NN * 256;
    float* out_pmvo = out + 3 * (size_t)NN * 256;

    float *dinv, *edinv, *bufB, *x2, *hidden;
    int *cnt, *rowptr, *cursor, *esrc, *bsums;
    __nv_bfloat16 *aggHi, *aggLo, *wtHi, *wtLo;
    __nv_bfloat16 *fc1hi, *fc1lo, *fc2hi, *fc2lo, *x2hi, *x2lo, *hidhi, *hidlo;
    cudaGetSymbolAddress((void**)&dinv, g_dinv);
    cudaGetSymbolAddress((void**)&edinv, g_edinv);
    cudaGetSymbolAddress((void**)&cnt, g_cnt);
    cudaGetSymbolAddress((void**)&rowptr, g_rowptr);
    cudaGetSymbolAddress((void**)&cursor, g_cursor);
    cudaGetSymbolAddress((void**)&esrc, g_esrc);
    cudaGetSymbolAddress((void**)&bsums, g_bsums);
    cudaGetSymbolAddress((void**)&aggHi, g_aggHi);
    cudaGetSymbolAddress((void**)&aggLo, g_aggLo);
    cudaGetSymbolAddress((void**)&bufB, g_bufB);
    cudaGetSymbolAddress((void**)&x2, g_x2);
    cudaGetSymbolAddress((void**)&hidden, g_hidden);
    cudaGetSymbolAddress((void**)&wtHi, g_wt_hi);
    cudaGetSymbolAddress((void**)&wtLo, g_wt_lo);
    cudaGetSymbolAddress((void**)&fc1hi, g_wtfc1_hi);
    cudaGetSymbolAddress((void**)&fc1lo, g_wtfc1_lo);
    cudaGetSymbolAddress((void**)&fc2hi, g_wtfc2_hi);
    cudaGetSymbolAddress((void**)&fc2lo, g_wtfc2_lo);
    cudaGetSymbolAddress((void**)&x2hi, g_x2hi);
    cudaGetSymbolAddress((void**)&x2lo, g_x2lo);
    cudaGetSymbolAddress((void**)&hidhi, g_hidhi);
    cudaGetSymbolAddress((void**)&hidlo, g_hidlo);

    const int* erow = ei;
    const int* ecol = ei + EE;

    const int SCAN_BLOCKS = (NN + 1023) / 1024;   // 98

    // zero scratch via memset nodes (graph-capturable)
    cudaMemsetAsync(cnt, 0, NN * sizeof(int));
    cudaMemsetAsync(x2, 0, BB * 256 * sizeof(float));

    // ALL weight pre-splits in ONE batched launch
    {
        WSplitTable tab;
        auto set = [&](int i, const float* W, __nv_bfloat16* hi, __nv_bfloat16* lo,
                       int MK, int N, int Npad, int off) {
            tab.d[i] = {W, hi, lo, MK, N, Npad, off, (MK + 31) / 32};
        };
        int off = 0;
        auto tiles = [](int MK, int Npad) { return ((MK + 31) / 32) * ((Npad + 31) / 32); };
        set(0, W1,  wtHi + WOFF_L1, wtLo + WOFF_L1, 64,  128, 128, off);  off += tiles(64, 128);
        set(1, W2,  wtHi + WOFF_L2, wtLo + WOFF_L2, 128, 192, 256, off);  off += tiles(128, 256);
        set(2, W3,  wtHi + WOFF_L3, wtLo + WOFF_L3, 192, 256, 256, off);  off += tiles(192, 256);
        set(3, Wmu, wtHi + WOFF_MU, wtLo + WOFF_MU, 256, 256, 256, off);  off += tiles(256, 256);
        set(4, Wlv, wtHi + WOFF_LV, wtLo + WOFF_LV, 256, 256, 256, off);  off += tiles(256, 256);
        set(5, fc1w, fc1hi, fc1lo, 256, 1024, 1024, off);                 off += tiles(256, 1024);
        set(6, fc2w, fc2hi, fc2lo, 1024, 128, 128, off);                  off += tiles(1024, 128);
        tab.totalTiles = off;
        wsplit_batched_kernel<<<off, 256>>>(tab);
    }

    // CSR build + normalization (dinv fused into scan_final; edinv in fill)
    count_kernel<<<(EE + 255) / 256, 256>>>(ecol, cnt, EE);
    block_reduce_kernel<<<SCAN_BLOCKS, 1024>>>(cnt, bsums, NN);
    scan_bsums_kernel<<<1, 128>>>(bsums, SCAN_BLOCKS);
    scan_final_kernel<<<SCAN_BLOCKS, 1024>>>(cnt, bsums, rowptr, cursor, dinv, NN);
    fill_kernel<<<(EE + 255) / 256, 256>>>(erow, ecol, dinv, cursor, esrc, edinv, EE);

    // layer 1: aggregate(x,64) -> gemm 64->128 +relu
    run_aggregate(x, dinv, rowptr, esrc, edinv, aggHi, aggLo, 64);
    run_gemm_mma(aggHi, aggLo, wtHi + WOFF_L1, wtLo + WOFF_L1, b1, bufB, NN, 64, 128, 1);

    // layer 2: aggregate(h1,128) -> gemm 128->192 +relu
    run_aggregate(bufB, dinv, rowptr, esrc, edinv, aggHi, aggLo, 128);
    run_gemm_mma(aggHi, aggLo, wtHi + WOFF_L2, wtLo + WOFF_L2, b2, bufB, NN, 128, 192, 1);

    // layer 3: aggregate(h2,192) -> gemm 192->256 +relu, fused segment-max pool
    run_aggregate(bufB, dinv, rowptr, esrc, edinv, aggHi, aggLo, 192);
    run_gemm_mma(aggHi, aggLo, wtHi + WOFF_L3, wtLo + WOFF_L3, b3, bufB, NN, 192, 256, 1,
                 nullptr, nullptr, nullptr, batch, x2);

    // shared aggregation for mu / logvar heads
    run_aggregate(bufB, dinv, rowptr, esrc, edinv, aggHi, aggLo, 256);
    run_gemm_mma(aggHi, aggLo, wtHi + WOFF_MU, wtLo + WOFF_MU, bmu, out_mu, NN, 256, 256, 0);
    run_gemm_mma(aggHi, aggLo, wtHi + WOFF_LV, wtLo + WOFF_LV, blv, out_lv, NN, 256, 256, 0,
                 out_mu, eps, out_amvo);

    // MLP head on pooled features (bf16x3 mma path)
    split_f32_kernel<<<(BB * 256 + 255) / 256, 256>>>(x2, x2hi, x2lo, BB * 256);
    run_gemm_mma(x2hi, x2lo, fc1hi, fc1lo, fc1b, hidden, BB, 256, 1024, 1);
    split_f32_kernel<<<(BB * 1024 + 255) / 256, 256>>>(hidden, hidhi, hidlo, BB * 1024);
    run_gemm_mma(hidhi, hidlo, fc2hi, fc2lo, fc2b, out_pmvo, BB, 1024, 128, 0);
}